// round 6
// baseline (speedup 1.0000x reference)
#include <cuda_runtime.h>
#include <cuda_bf16.h>
#include <cstdint>
#include <math.h>

// ---------------------------------------------------------------------------
// Problem constants
// ---------------------------------------------------------------------------
#define BATCH   2
#define SEQ     2048
#define HID     2048
#define NH      16
#define NKV     4
#define DH      128
#define KVW     (NKV * DH)          // 512
#define MTOT    (BATCH * SEQ)       // 4096
#define GROUPS  (NH / NKV)          // 4
#define GEMM_K  2048
#define NQKV    (HID + 2 * KVW)     // 3072

// ---------------------------------------------------------------------------
// PTX helpers — ONLY non-'a' features (mma.sync / ldmatrix / cp.async).
// ---------------------------------------------------------------------------
__device__ __forceinline__ uint32_t smem_to_u32(const void* p) {
    uint32_t a;
    asm("{ .reg .u64 t; cvta.to.shared.u64 t, %1; cvt.u32.u64 %0, t; }"
        : "=r"(a) : "l"(p));
    return a;
}
#define CP_ASYNC16(dst, src) \
    asm volatile("cp.async.cg.shared.global [%0], [%1], 16;" \
                 :: "r"(dst), "l"(src))
#define CP_ASYNC4(dst, src) \
    asm volatile("cp.async.ca.shared.global [%0], [%1], 4;" \
                 :: "r"(dst), "l"(src))
#define CP_COMMIT() asm volatile("cp.async.commit_group;")
#define CP_WAIT(n)  asm volatile("cp.async.wait_group %0;" :: "n"(n))

__device__ __forceinline__ void ldsm_x4(uint32_t* r, uint32_t addr) {
    asm volatile("ldmatrix.sync.aligned.m8n8.x4.shared.b16 {%0,%1,%2,%3}, [%4];"
                 : "=r"(r[0]), "=r"(r[1]), "=r"(r[2]), "=r"(r[3]) : "r"(addr));
}
__device__ __forceinline__ void mma_bf16(float* d, const uint32_t* a,
                                         const uint32_t* b) {
    asm volatile(
        "mma.sync.aligned.m16n8k16.row.col.f32.bf16.bf16.f32 "
        "{%0,%1,%2,%3}, {%4,%5,%6,%7}, {%8,%9}, {%0,%1,%2,%3};"
        : "+f"(d[0]), "+f"(d[1]), "+f"(d[2]), "+f"(d[3])
        : "r"(a[0]), "r"(a[1]), "r"(a[2]), "r"(a[3]), "r"(b[0]), "r"(b[1]));
}
__device__ __forceinline__ void split2(float x, float y, uint32_t& hi, uint32_t& lo) {
    __nv_bfloat16 bx = __float2bfloat16(x), by = __float2bfloat16(y);
    __nv_bfloat162 h(bx, by);
    hi = *reinterpret_cast<uint32_t*>(&h);
    __nv_bfloat162 l(__float2bfloat16(x - __bfloat162float(bx)),
                     __float2bfloat16(y - __bfloat162float(by)));
    lo = *reinterpret_cast<uint32_t*>(&l);
}

// ---------------------------------------------------------------------------
// Scratch buffers
// ---------------------------------------------------------------------------
__device__ float g_v[(size_t)MTOT * KVW];
__device__ __nv_bfloat16 g_xh[(size_t)MTOT * HID];
__device__ __nv_bfloat16 g_xl[(size_t)MTOT * HID];
__device__ __nv_bfloat16 g_qh[(size_t)MTOT * HID];
__device__ __nv_bfloat16 g_ql[(size_t)MTOT * HID];
__device__ __nv_bfloat16 g_kh[(size_t)MTOT * KVW];
__device__ __nv_bfloat16 g_kl[(size_t)MTOT * KVW];
__device__ __nv_bfloat16 g_vth[(size_t)MTOT * KVW];   // [B*KVW, SEQ]
__device__ __nv_bfloat16 g_vtl[(size_t)MTOT * KVW];
__device__ __nv_bfloat16 g_ah[(size_t)MTOT * HID];
__device__ __nv_bfloat16 g_al[(size_t)MTOT * HID];
__device__ __nv_bfloat16 g_wh[(size_t)NQKV * HID];    // [Wq;Wk;Wv] transposed
__device__ __nv_bfloat16 g_wl[(size_t)NQKV * HID];
__device__ __nv_bfloat16 g_woh[(size_t)HID * HID];
__device__ __nv_bfloat16 g_wol[(size_t)HID * HID];

// ---------------------------------------------------------------------------
// Converters
// ---------------------------------------------------------------------------
__global__ void split_kernel(const float* __restrict__ in,
                             __nv_bfloat16* __restrict__ hi,
                             __nv_bfloat16* __restrict__ lo, int n4)
{
    int i = blockIdx.x * blockDim.x + threadIdx.x;
    if (i >= n4) return;
    float4 v = ((const float4*)in)[i];
    __nv_bfloat16 h0 = __float2bfloat16(v.x);
    __nv_bfloat16 h1 = __float2bfloat16(v.y);
    __nv_bfloat16 h2 = __float2bfloat16(v.z);
    __nv_bfloat16 h3 = __float2bfloat16(v.w);
    ((__nv_bfloat162*)hi)[2*i]   = __nv_bfloat162(h0, h1);
    ((__nv_bfloat162*)hi)[2*i+1] = __nv_bfloat162(h2, h3);
    ((__nv_bfloat162*)lo)[2*i]   = __nv_bfloat162(
        __float2bfloat16(v.x - __bfloat162float(h0)),
        __float2bfloat16(v.y - __bfloat162float(h1)));
    ((__nv_bfloat162*)lo)[2*i+1] = __nv_bfloat162(
        __float2bfloat16(v.z - __bfloat162float(h2)),
        __float2bfloat16(v.w - __bfloat162float(h3)));
}

__global__ void wsplitT_kernel(const float* __restrict__ W,
                               __nv_bfloat16* __restrict__ Th,
                               __nv_bfloat16* __restrict__ Tl,
                               int K, int N)
{
    __shared__ float t[32][33];
    const int n  = blockIdx.x * 32 + threadIdx.x;
    const int kb = blockIdx.y * 32;
    #pragma unroll
    for (int j = 0; j < 32; j += 8)
        t[threadIdx.y + j][threadIdx.x] = W[(size_t)(kb + threadIdx.y + j) * N + n];
    __syncthreads();
    const int k  = kb + threadIdx.x;
    const int nb = blockIdx.x * 32;
    #pragma unroll
    for (int j = 0; j < 32; j += 8) {
        float v = t[threadIdx.x][threadIdx.y + j];
        __nv_bfloat16 h = __float2bfloat16(v);
        size_t o = (size_t)(nb + threadIdx.y + j) * K + k;
        Th[o] = h;
        Tl[o] = __float2bfloat16(v - __bfloat162float(h));
    }
}

__global__ void vsplitT_kernel(const float* __restrict__ V,
                               __nv_bfloat16* __restrict__ Th,
                               __nv_bfloat16* __restrict__ Tl)
{
    __shared__ float t[32][33];
    const int n0 = blockIdx.x * 32;
    const int s0 = blockIdx.y * 32;
    const int b  = blockIdx.z;
    #pragma unroll
    for (int j = 0; j < 32; j += 8)
        t[threadIdx.y + j][threadIdx.x] =
            V[(size_t)(b * SEQ + s0 + threadIdx.y + j) * KVW + n0 + threadIdx.x];
    __syncthreads();
    #pragma unroll
    for (int j = 0; j < 32; j += 8) {
        float v = t[threadIdx.x][threadIdx.y + j];
        __nv_bfloat16 h = __float2bfloat16(v);
        size_t o = (size_t)(b * KVW + n0 + threadIdx.y + j) * SEQ + s0 + threadIdx.x;
        Th[o] = h;
        Tl[o] = __float2bfloat16(v - __bfloat162float(h));
    }
}

// ---------------------------------------------------------------------------
// HMMA GEMM mainloop (shared via macro)
// ---------------------------------------------------------------------------
#define KC        32
#define AS_STRIDE 40
#define MAT_B     (128 * AS_STRIDE * 2)
#define STAGE_B   (4 * MAT_B)
#define NCHUNK    (GEMM_K / KC)

#define GEMM_MAINLOOP(AhP, AlP, BhP, BlP)                                       \
    float acc[4][4][4];                                                         \
    _Pragma("unroll")                                                           \
    for (int a = 0; a < 4; ++a)                                                 \
        _Pragma("unroll")                                                       \
        for (int b2 = 0; b2 < 4; ++b2)                                          \
            _Pragma("unroll")                                                   \
            for (int c = 0; c < 4; ++c) acc[a][b2][c] = 0.f;                    \
    const __nv_bfloat16* mats[4] = {AhP, AlP, BhP, BlP};                        \
    auto load_stage = [&](int s, int k0) {                                      \
        const uint32_t st = smem_base + s * STAGE_B;                            \
        _Pragma("unroll")                                                       \
        for (int mat = 0; mat < 4; ++mat) {                                     \
            const __nv_bfloat16* src = mats[mat];                               \
            const int r0 = (mat < 2) ? m0 : n0;                                 \
            const uint32_t dstb = st + mat * MAT_B;                             \
            _Pragma("unroll")                                                   \
            for (int it = 0; it < 2; ++it) {                                    \
                const int idx = it * 256 + tid;                                 \
                const int row = idx >> 2;                                       \
                const int k4  = idx & 3;                                        \
                const void* sp = src + (size_t)(r0 + row) * GEMM_K + k0 + k4*8; \
                const uint32_t dp = dstb + row * (AS_STRIDE * 2) + k4 * 16;     \
                CP_ASYNC16(dp, sp);                                             \
            }                                                                   \
        }                                                                       \
    };                                                                          \
    load_stage(0, 0);                                                           \
    CP_COMMIT();                                                                \
    for (int c = 0; c < NCHUNK; ++c) {                                          \
        if (c + 1 < NCHUNK) {                                                   \
            load_stage((c + 1) & 1, (c + 1) * KC);                              \
            CP_COMMIT();                                                        \
            CP_WAIT(1);                                                         \
        } else {                                                                \
            CP_WAIT(0);                                                         \
        }                                                                       \
        __syncthreads();                                                        \
        const uint32_t stg = smem_base + (c & 1) * STAGE_B;                     \
        const uint32_t pAh = stg;                                               \
        const uint32_t pAl = stg + MAT_B;                                       \
        const uint32_t pBh = stg + 2 * MAT_B;                                   \
        const uint32_t pBl = stg + 3 * MAT_B;                                   \
        _Pragma("unroll")                                                       \
        for (int ks = 0; ks < 2; ++ks) {                                        \
            const int kcol = ks * 16;                                           \
            uint32_t bh[8], bl[8];                                              \
            _Pragma("unroll")                                                   \
            for (int p = 0; p < 2; ++p) {                                       \
                const int nrow = wn * 32 + p * 16 + (lane & 7) + ((lane>>4)<<3);\
                const int kk   = kcol + (((lane >> 3) & 1) << 3);               \
                const uint32_t off = (nrow * AS_STRIDE + kk) * 2;               \
                ldsm_x4(&bh[p * 4], pBh + off);                                 \
                ldsm_x4(&bl[p * 4], pBl + off);                                 \
            }                                                                   \
            _Pragma("unroll")                                                   \
            for (int mt = 0; mt < 4; ++mt) {                                    \
                const int mrow = wm * 64 + mt * 16 + (lane & 15);               \
                const int kk2  = kcol + ((lane >> 4) << 3);                     \
                const uint32_t offa = (mrow * AS_STRIDE + kk2) * 2;             \
                uint32_t afr[4];                                                \
                ldsm_x4(afr, pAh + offa);                                       \
                _Pragma("unroll")                                               \
                for (int nt = 0; nt < 4; ++nt) mma_bf16(acc[mt][nt], afr, &bh[nt*2]); \
                _Pragma("unroll")                                               \
                for (int nt = 0; nt < 4; ++nt) mma_bf16(acc[mt][nt], afr, &bl[nt*2]); \
                ldsm_x4(afr, pAl + offa);                                       \
                _Pragma("unroll")                                               \
                for (int nt = 0; nt < 4; ++nt) mma_bf16(acc[mt][nt], afr, &bh[nt*2]); \
            }                                                                   \
        }                                                                       \
        __syncthreads();                                                        \
    }

// ---------------------------------------------------------------------------
// Fused QKV projection: N = 3072 (q 0:2048 pre-scaled+split, k split, v fp32)
// ---------------------------------------------------------------------------
#define ATT_SCL 0.08838834764831845f

__global__ void __launch_bounds__(256)
gemm_qkv(const __nv_bfloat16* __restrict__ Ah, const __nv_bfloat16* __restrict__ Al,
         const __nv_bfloat16* __restrict__ Bh, const __nv_bfloat16* __restrict__ Bl,
         const float* __restrict__ bq, const float* __restrict__ bk,
         const float* __restrict__ bv,
         __nv_bfloat16* __restrict__ Qh, __nv_bfloat16* __restrict__ Ql,
         __nv_bfloat16* __restrict__ Kh, __nv_bfloat16* __restrict__ Kl,
         float* __restrict__ Vo)
{
    extern __shared__ __align__(128) char smem[];
    const uint32_t smem_base = smem_to_u32(smem);
    const int tid  = threadIdx.x;
    const int warp = tid >> 5;
    const int lane = tid & 31;
    const int wm   = warp >> 2;
    const int wn   = warp & 3;
    const int m0   = blockIdx.y * 128;
    const int n0   = blockIdx.x * 128;

    GEMM_MAINLOOP(Ah, Al, Bh, Bl)

    #pragma unroll
    for (int mt = 0; mt < 4; ++mt)
        #pragma unroll
        for (int rh = 0; rh < 2; ++rh) {
            const int row = m0 + wm * 64 + mt * 16 + (lane >> 2) + rh * 8;
            #pragma unroll
            for (int nt = 0; nt < 4; ++nt) {
                const int col = n0 + wn * 32 + nt * 8 + (lane & 3) * 2;
                if (n0 < HID) {
                    // pre-scale q by 1/sqrt(d) (folded out of attention)
                    const float v0 = (acc[mt][nt][rh*2+0] + bq[col])   * ATT_SCL;
                    const float v1 = (acc[mt][nt][rh*2+1] + bq[col+1]) * ATT_SCL;
                    uint32_t hi, lo;
                    split2(v0, v1, hi, lo);
                    *(uint32_t*)&Qh[(size_t)row * HID + col] = hi;
                    *(uint32_t*)&Ql[(size_t)row * HID + col] = lo;
                } else if (n0 < HID + KVW) {
                    const int c2 = col - HID;
                    const float v0 = acc[mt][nt][rh*2+0] + bk[c2];
                    const float v1 = acc[mt][nt][rh*2+1] + bk[c2+1];
                    uint32_t hi, lo;
                    split2(v0, v1, hi, lo);
                    *(uint32_t*)&Kh[(size_t)row * KVW + c2] = hi;
                    *(uint32_t*)&Kl[(size_t)row * KVW + c2] = lo;
                } else {
                    const int c2 = col - HID - KVW;
                    float2 v;
                    v.x = acc[mt][nt][rh*2+0] + bv[c2];
                    v.y = acc[mt][nt][rh*2+1] + bv[c2+1];
                    *(float2*)&Vo[(size_t)row * KVW + c2] = v;
                }
            }
        }
}

// ---------------------------------------------------------------------------
// O-projection GEMM (fp32 out)
// ---------------------------------------------------------------------------
__global__ void __launch_bounds__(256)
gemm_o(const __nv_bfloat16* __restrict__ Ah, const __nv_bfloat16* __restrict__ Al,
       const __nv_bfloat16* __restrict__ Bh, const __nv_bfloat16* __restrict__ Bl,
       const float* __restrict__ bias, float* __restrict__ C)
{
    extern __shared__ __align__(128) char smem[];
    const uint32_t smem_base = smem_to_u32(smem);
    const int tid  = threadIdx.x;
    const int warp = tid >> 5;
    const int lane = tid & 31;
    const int wm   = warp >> 2;
    const int wn   = warp & 3;
    const int m0   = blockIdx.y * 128;
    const int n0   = blockIdx.x * 128;

    GEMM_MAINLOOP(Ah, Al, Bh, Bl)

    #pragma unroll
    for (int mt = 0; mt < 4; ++mt)
        #pragma unroll
        for (int rh = 0; rh < 2; ++rh) {
            const int row = m0 + wm * 64 + mt * 16 + (lane >> 2) + rh * 8;
            #pragma unroll
            for (int nt = 0; nt < 4; ++nt) {
                const int col = n0 + wn * 32 + nt * 8 + (lane & 3) * 2;
                float2 v;
                v.x = acc[mt][nt][rh*2+0] + bias[col];
                v.y = acc[mt][nt][rh*2+1] + bias[col+1];
                *(float2*)&C[(size_t)row * HID + col] = v;
            }
        }
}

// ---------------------------------------------------------------------------
// HMMA FlashAttention: 128 q-rows x 64 kv tiles (PROVEN R4 config),
// 8 warps (16 q-rows each), reversed-qb scheduling.
// ---------------------------------------------------------------------------
#define QSTR 136
#define VSTR 72
#define SM_QH 0
#define SM_QL 34816
#define SM_KH 69632
#define SM_KL 87040
#define SM_VH 104448
#define SM_VL 122880
#define SM_MK 141312
#define ATTN_SMEM 141568

__global__ void __launch_bounds__(256)
attn_hmma(const __nv_bfloat16* __restrict__ Qh, const __nv_bfloat16* __restrict__ Ql,
          const __nv_bfloat16* __restrict__ Kh, const __nv_bfloat16* __restrict__ Kl,
          const __nv_bfloat16* __restrict__ VTh, const __nv_bfloat16* __restrict__ VTl,
          const int* __restrict__ mask,
          __nv_bfloat16* __restrict__ OH, __nv_bfloat16* __restrict__ OL)
{
    extern __shared__ __align__(128) char sm[];
    const uint32_t base = smem_to_u32(sm);
    const int tid = threadIdx.x;
    const int w    = tid >> 5;
    const int lane = tid & 31;
    // reversed qb: heavy blocks launch first
    const int qb = (int)gridDim.x - 1 - (int)blockIdx.x;
    const int h = blockIdx.y, b = blockIdx.z;
    const int q0 = qb * 128;
    const int kvh = h >> 2;
    const int T = 2 * qb + 2;

    auto load_k = [&](int k0) {
        #pragma unroll
        for (int mat = 0; mat < 2; ++mat) {
            const __nv_bfloat16* src = mat ? Kl : Kh;
            const uint32_t dst = base + (mat ? SM_KL : SM_KH);
            #pragma unroll
            for (int i = 0; i < 4; ++i) {
                const int idx = i * 256 + tid;
                const int row = idx >> 4, c = idx & 15;
                CP_ASYNC16(dst + row * 272 + c * 16,
                           src + (size_t)(b * SEQ + k0 + row) * KVW + kvh * DH + c * 8);
            }
        }
        if (tid < 64)
            CP_ASYNC4(base + SM_MK + tid * 4, mask + b * SEQ + k0 + tid);
    };
    auto load_v = [&](int k0) {
        #pragma unroll
        for (int mat = 0; mat < 2; ++mat) {
            const __nv_bfloat16* src = mat ? VTl : VTh;
            const uint32_t dst = base + (mat ? SM_VL : SM_VH);
            #pragma unroll
            for (int i = 0; i < 4; ++i) {
                const int idx = i * 256 + tid;
                const int row = idx >> 3, c = idx & 7;
                CP_ASYNC16(dst + row * 144 + c * 16,
                           src + (size_t)(b * KVW + kvh * DH + row) * SEQ + k0 + c * 8);
            }
        }
    };

    // prologue: Q + K(0) + mask(0)
    #pragma unroll
    for (int mat = 0; mat < 2; ++mat) {
        const __nv_bfloat16* src = mat ? Ql : Qh;
        const uint32_t dst = base + (mat ? SM_QL : SM_QH);
        #pragma unroll
        for (int i = 0; i < 8; ++i) {
            const int idx = i * 256 + tid;
            const int row = idx >> 4, c = idx & 15;
            CP_ASYNC16(dst + row * 272 + c * 16,
                       src + (size_t)(b * SEQ + q0 + row) * HID + h * DH + c * 8);
        }
    }
    load_k(0);
    CP_COMMIT();
    CP_WAIT(0);
    __syncthreads();

    float s[8][4];
    float o[16][4];
    #pragma unroll
    for (int j = 0; j < 16; ++j)
        #pragma unroll
        for (int c = 0; c < 4; ++c) o[j][c] = 0.f;
    float m0 = -1e30f, m1 = -1e30f, l0 = 0.f, l1 = 0.f;

    const int r0g = q0 + w * 16 + (lane >> 2);
    const int r1g = r0g + 8;
    const int c0l = (lane & 3) * 2;
    const int* mk_s = (const int*)(sm + SM_MK);

    for (int t = 0; t < T; ++t) {
        const int k0 = t * 64;
        const bool active = (q0 + w * 16 + 15) >= k0;

        load_v(k0);
        CP_COMMIT();

        if (active) {
            #pragma unroll
            for (int j = 0; j < 8; ++j)
                #pragma unroll
                for (int c = 0; c < 4; ++c) s[j][c] = 0.f;

            // S = Qh*Kh + Qh*Kl + Ql*Kh  (Q pre-scaled by 1/sqrt(d))
            #pragma unroll
            for (int kc = 0; kc < 8; ++kc) {
                const uint32_t offa =
                    ((w * 16 + (lane & 15)) * QSTR + kc * 16 + ((lane >> 4) << 3)) * 2;
                uint32_t ah[4], al[4];
                ldsm_x4(ah, base + SM_QH + offa);
                ldsm_x4(al, base + SM_QL + offa);
                #pragma unroll
                for (int g = 0; g < 4; ++g) {
                    const uint32_t offb =
                        ((g * 16 + (lane & 7) + ((lane >> 4) << 3)) * QSTR +
                         kc * 16 + (((lane >> 3) & 1) << 3)) * 2;
                    uint32_t bh[4], bl[4];
                    ldsm_x4(bh, base + SM_KH + offb);
                    ldsm_x4(bl, base + SM_KL + offb);
                    mma_bf16(s[2*g],   ah, &bh[0]);
                    mma_bf16(s[2*g+1], ah, &bh[2]);
                    mma_bf16(s[2*g],   ah, &bl[0]);
                    mma_bf16(s[2*g+1], ah, &bl[2]);
                    mma_bf16(s[2*g],   al, &bh[0]);
                    mma_bf16(s[2*g+1], al, &bh[2]);
                }
            }

            // mask + online softmax (registers); scale already folded into Q
            float mx0 = -1e30f, mx1 = -1e30f;
            #pragma unroll
            for (int j = 0; j < 8; ++j) {
                const int cg = k0 + j * 8 + c0l;
                const int mk0 = mk_s[j * 8 + c0l];
                const int mk1 = mk_s[j * 8 + c0l + 1];
                s[j][0] = (cg     <= r0g && mk0) ? s[j][0] : -1e30f;
                s[j][1] = (cg + 1 <= r0g && mk1) ? s[j][1] : -1e30f;
                s[j][2] = (cg     <= r1g && mk0) ? s[j][2] : -1e30f;
                s[j][3] = (cg + 1 <= r1g && mk1) ? s[j][3] : -1e30f;
                mx0 = fmaxf(mx0, fmaxf(s[j][0], s[j][1]));
                mx1 = fmaxf(mx1, fmaxf(s[j][2], s[j][3]));
            }
            mx0 = fmaxf(mx0, __shfl_xor_sync(0xffffffff, mx0, 1));
            mx0 = fmaxf(mx0, __shfl_xor_sync(0xffffffff, mx0, 2));
            mx1 = fmaxf(mx1, __shfl_xor_sync(0xffffffff, mx1, 1));
            mx1 = fmaxf(mx1, __shfl_xor_sync(0xffffffff, mx1, 2));
            const float mn0 = fmaxf(m0, mx0), mn1 = fmaxf(m1, mx1);
            const float f0 = __expf(m0 - mn0), f1 = __expf(m1 - mn1);
            m0 = mn0; m1 = mn1;
            float sum0 = 0.f, sum1 = 0.f;
            #pragma unroll
            for (int j = 0; j < 8; ++j) {
                s[j][0] = __expf(s[j][0] - mn0);
                s[j][1] = __expf(s[j][1] - mn0);
                s[j][2] = __expf(s[j][2] - mn1);
                s[j][3] = __expf(s[j][3] - mn1);
                sum0 += s[j][0] + s[j][1];
                sum1 += s[j][2] + s[j][3];
            }
            sum0 += __shfl_xor_sync(0xffffffff, sum0, 1);
            sum0 += __shfl_xor_sync(0xffffffff, sum0, 2);
            sum1 += __shfl_xor_sync(0xffffffff, sum1, 1);
            sum1 += __shfl_xor_sync(0xffffffff, sum1, 2);
            l0 = l0 * f0 + sum0;
            l1 = l1 * f1 + sum1;
            #pragma unroll
            for (int j = 0; j < 16; ++j) {
                o[j][0] *= f0; o[j][1] *= f0;
                o[j][2] *= f1; o[j][3] *= f1;
            }
        }

        CP_WAIT(0);            // VT(t) ready
        __syncthreads();       // all warps done reading K(t)
        if (t + 1 < T) {
            load_k(t * 64 + 64);
            CP_COMMIT();
        }

        if (active) {
            // O += Ph*Vh + Ph*Vl + Pl*Vh
            #pragma unroll
            for (int kc = 0; kc < 4; ++kc) {
                uint32_t aph[4], apl[4];
                split2(s[2*kc][0],   s[2*kc][1],   aph[0], apl[0]);
                split2(s[2*kc][2],   s[2*kc][3],   aph[1], apl[1]);
                split2(s[2*kc+1][0], s[2*kc+1][1], aph[2], apl[2]);
                split2(s[2*kc+1][2], s[2*kc+1][3], aph[3], apl[3]);
                #pragma unroll
                for (int g = 0; g < 8; ++g) {
                    const uint32_t offb =
                        ((g * 16 + (lane & 7) + ((lane >> 4) << 3)) * VSTR +
                         kc * 16 + (((lane >> 3) & 1) << 3)) * 2;
                    uint32_t bh[4], bl[4];
                    ldsm_x4(bh, base + SM_VH + offb);
                    ldsm_x4(bl, base + SM_VL + offb);
                    mma_bf16(o[2*g],   aph, &bh[0]);
                    mma_bf16(o[2*g+1], aph, &bh[2]);
                    mma_bf16(o[2*g],   aph, &bl[0]);
                    mma_bf16(o[2*g+1], aph, &bl[2]);
                    mma_bf16(o[2*g],   apl, &bh[0]);
                    mma_bf16(o[2*g+1], apl, &bh[2]);
                }
            }
        }

        CP_WAIT(0);            // K(t+1) ready
        __syncthreads();       // all warps done reading VT(t)
    }

    // epilogue: normalize, split bf16 hi/lo, store
    const float inv0 = 1.f / l0, inv1 = 1.f / l1;
    const size_t base0 = (size_t)(b * SEQ + r0g) * HID + h * DH;
    const size_t base1 = (size_t)(b * SEQ + r1g) * HID + h * DH;
    #pragma unroll
    for (int j = 0; j < 16; ++j) {
        const int col = j * 8 + c0l;
        uint32_t hi, lo;
        split2(o[j][0] * inv0, o[j][1] * inv0, hi, lo);
        *(uint32_t*)&OH[base0 + col] = hi;
        *(uint32_t*)&OL[base0 + col] = lo;
        split2(o[j][2] * inv1, o[j][3] * inv1, hi, lo);
        *(uint32_t*)&OH[base1 + col] = hi;
        *(uint32_t*)&OL[base1 + col] = lo;
    }
}

// ---------------------------------------------------------------------------
// Launch
// ---------------------------------------------------------------------------
extern "C" void kernel_launch(void* const* d_in, const int* in_sizes, int n_in,
                              void* d_out, int out_size)
{
    const float* x    = (const float*)d_in[0];
    const int*   mask = (const int*)  d_in[1];
    const float* Wq   = (const float*)d_in[2];
    const float* bq   = (const float*)d_in[3];
    const float* Wk   = (const float*)d_in[4];
    const float* bk   = (const float*)d_in[5];
    const float* Wv   = (const float*)d_in[6];
    const float* bv   = (const float*)d_in[7];
    const float* Wo   = (const float*)d_in[8];
    const float* bo   = (const float*)d_in[9];
    float* out = (float*)d_out;

    void *pv, *pxh, *pxl, *pqh, *pql, *pkh, *pkl, *pvth, *pvtl, *pah, *pal;
    void *pwh, *pwl, *pwoh, *pwol;
    cudaGetSymbolAddress(&pv,  g_v);
    cudaGetSymbolAddress(&pxh, g_xh);  cudaGetSymbolAddress(&pxl, g_xl);
    cudaGetSymbolAddress(&pqh, g_qh);  cudaGetSymbolAddress(&pql, g_ql);
    cudaGetSymbolAddress(&pkh, g_kh);  cudaGetSymbolAddress(&pkl, g_kl);
    cudaGetSymbolAddress(&pvth, g_vth); cudaGetSymbolAddress(&pvtl, g_vtl);
    cudaGetSymbolAddress(&pah, g_ah);  cudaGetSymbolAddress(&pal, g_al);
    cudaGetSymbolAddress(&pwh, g_wh);  cudaGetSymbolAddress(&pwl, g_wl);
    cudaGetSymbolAddress(&pwoh, g_woh); cudaGetSymbolAddress(&pwol, g_wol);

    __nv_bfloat16* wh = (__nv_bfloat16*)pwh;
    __nv_bfloat16* wl = (__nv_bfloat16*)pwl;

    // --- converters ---
    const int n4 = MTOT * HID / 4;
    split_kernel<<<n4 / 256, 256>>>(x, (__nv_bfloat16*)pxh, (__nv_bfloat16*)pxl, n4);
    dim3 tb(32, 8);
    wsplitT_kernel<<<dim3(HID / 32, HID / 32), tb>>>(Wq, wh, wl, HID, HID);
    wsplitT_kernel<<<dim3(KVW / 32, HID / 32), tb>>>(
        Wk, wh + (size_t)HID * HID, wl + (size_t)HID * HID, HID, KVW);
    wsplitT_kernel<<<dim3(KVW / 32, HID / 32), tb>>>(
        Wv, wh + (size_t)(HID + KVW) * HID, wl + (size_t)(HID + KVW) * HID, HID, KVW);
    wsplitT_kernel<<<dim3(HID / 32, HID / 32), tb>>>(Wo, (__nv_bfloat16*)pwoh,
                                                     (__nv_bfloat16*)pwol, HID, HID);

    // --- fused QKV projection ---
    const int gemm_smem = 2 * STAGE_B;
    cudaFuncSetAttribute(gemm_qkv, cudaFuncAttributeMaxDynamicSharedMemorySize,
                         gemm_smem);
    cudaFuncSetAttribute(gemm_o, cudaFuncAttributeMaxDynamicSharedMemorySize,
                         gemm_smem);
    gemm_qkv<<<dim3(NQKV / 128, MTOT / 128), 256, gemm_smem>>>(
        (const __nv_bfloat16*)pxh, (const __nv_bfloat16*)pxl, wh, wl,
        bq, bk, bv,
        (__nv_bfloat16*)pqh, (__nv_bfloat16*)pql,
        (__nv_bfloat16*)pkh, (__nv_bfloat16*)pkl, (float*)pv);

    // --- V transpose + split ---
    vsplitT_kernel<<<dim3(KVW / 32, SEQ / 32, BATCH), tb>>>(
        (const float*)pv, (__nv_bfloat16*)pvth, (__nv_bfloat16*)pvtl);

    // --- HMMA flash attention (64-wide kv tiles, reversed schedule) ---
    cudaFuncSetAttribute(attn_hmma, cudaFuncAttributeMaxDynamicSharedMemorySize,
                         ATTN_SMEM);
    attn_hmma<<<dim3(SEQ / 128, NH, BATCH), 256, ATTN_SMEM>>>(
        (const __nv_bfloat16*)pqh, (const __nv_bfloat16*)pql,
        (const __nv_bfloat16*)pkh, (const __nv_bfloat16*)pkl,
        (const __nv_bfloat16*)pvth, (const __nv_bfloat16*)pvtl,
        mask, (__nv_bfloat16*)pah, (__nv_bfloat16*)pal);

    // --- output projection ---
    gemm_o<<<dim3(HID / 128, MTOT / 128), 256, gemm_smem>>>(
        (const __nv_bfloat16*)pah, (const __nv_bfloat16*)pal,
        (const __nv_bfloat16*)pwoh, (const __nv_bfloat16*)pwol, bo, out);
}

// round 7
// speedup vs baseline: 1.0726x; 1.0726x over previous
#include <cuda_runtime.h>
#include <cuda_bf16.h>
#include <cstdint>
#include <math.h>

// ---------------------------------------------------------------------------
// Problem constants
// ---------------------------------------------------------------------------
#define BATCH   2
#define SEQ     2048
#define HID     2048
#define NH      16
#define NKV     4
#define DH      128
#define KVW     (NKV * DH)          // 512
#define MTOT    (BATCH * SEQ)       // 4096
#define GROUPS  (NH / NKV)          // 4
#define GEMM_K  2048
#define NQKV    (HID + 2 * KVW)     // 3072

// ---------------------------------------------------------------------------
// PTX helpers — ONLY non-'a' features (mma.sync / ldmatrix / cp.async).
// ---------------------------------------------------------------------------
__device__ __forceinline__ uint32_t smem_to_u32(const void* p) {
    uint32_t a;
    asm("{ .reg .u64 t; cvta.to.shared.u64 t, %1; cvt.u32.u64 %0, t; }"
        : "=r"(a) : "l"(p));
    return a;
}
#define CP_ASYNC16(dst, src) \
    asm volatile("cp.async.cg.shared.global [%0], [%1], 16;" \
                 :: "r"(dst), "l"(src))
#define CP_ASYNC4(dst, src) \
    asm volatile("cp.async.ca.shared.global [%0], [%1], 4;" \
                 :: "r"(dst), "l"(src))
#define CP_COMMIT() asm volatile("cp.async.commit_group;")
#define CP_WAIT(n)  asm volatile("cp.async.wait_group %0;" :: "n"(n))

__device__ __forceinline__ void ldsm_x4(uint32_t* r, uint32_t addr) {
    asm volatile("ldmatrix.sync.aligned.m8n8.x4.shared.b16 {%0,%1,%2,%3}, [%4];"
                 : "=r"(r[0]), "=r"(r[1]), "=r"(r[2]), "=r"(r[3]) : "r"(addr));
}
__device__ __forceinline__ void mma_bf16(float* d, const uint32_t* a,
                                         const uint32_t* b) {
    asm volatile(
        "mma.sync.aligned.m16n8k16.row.col.f32.bf16.bf16.f32 "
        "{%0,%1,%2,%3}, {%4,%5,%6,%7}, {%8,%9}, {%0,%1,%2,%3};"
        : "+f"(d[0]), "+f"(d[1]), "+f"(d[2]), "+f"(d[3])
        : "r"(a[0]), "r"(a[1]), "r"(a[2]), "r"(a[3]), "r"(b[0]), "r"(b[1]));
}
__device__ __forceinline__ void split2(float x, float y, uint32_t& hi, uint32_t& lo) {
    __nv_bfloat16 bx = __float2bfloat16(x), by = __float2bfloat16(y);
    __nv_bfloat162 h(bx, by);
    hi = *reinterpret_cast<uint32_t*>(&h);
    __nv_bfloat162 l(__float2bfloat16(x - __bfloat162float(bx)),
                     __float2bfloat16(y - __bfloat162float(by)));
    lo = *reinterpret_cast<uint32_t*>(&l);
}

// ---------------------------------------------------------------------------
// Scratch buffers
// ---------------------------------------------------------------------------
__device__ float g_v[(size_t)MTOT * KVW];
__device__ __nv_bfloat16 g_xh[(size_t)MTOT * HID];
__device__ __nv_bfloat16 g_xl[(size_t)MTOT * HID];
__device__ __nv_bfloat16 g_qh[(size_t)MTOT * HID];
__device__ __nv_bfloat16 g_ql[(size_t)MTOT * HID];
__device__ __nv_bfloat16 g_kh[(size_t)MTOT * KVW];
__device__ __nv_bfloat16 g_kl[(size_t)MTOT * KVW];
__device__ __nv_bfloat16 g_vth[(size_t)MTOT * KVW];   // [B*KVW, SEQ]
__device__ __nv_bfloat16 g_vtl[(size_t)MTOT * KVW];
__device__ __nv_bfloat16 g_ah[(size_t)MTOT * HID];
__device__ __nv_bfloat16 g_al[(size_t)MTOT * HID];
__device__ __nv_bfloat16 g_wh[(size_t)NQKV * HID];    // [Wq;Wk;Wv] transposed
__device__ __nv_bfloat16 g_wl[(size_t)NQKV * HID];
__device__ __nv_bfloat16 g_woh[(size_t)HID * HID];
__device__ __nv_bfloat16 g_wol[(size_t)HID * HID];

// ---------------------------------------------------------------------------
// Converters
// ---------------------------------------------------------------------------
__global__ void split_kernel(const float* __restrict__ in,
                             __nv_bfloat16* __restrict__ hi,
                             __nv_bfloat16* __restrict__ lo, int n4)
{
    int i = blockIdx.x * blockDim.x + threadIdx.x;
    if (i >= n4) return;
    float4 v = ((const float4*)in)[i];
    __nv_bfloat16 h0 = __float2bfloat16(v.x);
    __nv_bfloat16 h1 = __float2bfloat16(v.y);
    __nv_bfloat16 h2 = __float2bfloat16(v.z);
    __nv_bfloat16 h3 = __float2bfloat16(v.w);
    ((__nv_bfloat162*)hi)[2*i]   = __nv_bfloat162(h0, h1);
    ((__nv_bfloat162*)hi)[2*i+1] = __nv_bfloat162(h2, h3);
    ((__nv_bfloat162*)lo)[2*i]   = __nv_bfloat162(
        __float2bfloat16(v.x - __bfloat162float(h0)),
        __float2bfloat16(v.y - __bfloat162float(h1)));
    ((__nv_bfloat162*)lo)[2*i+1] = __nv_bfloat162(
        __float2bfloat16(v.z - __bfloat162float(h2)),
        __float2bfloat16(v.w - __bfloat162float(h3)));
}

// All four weight matrices transposed+split in ONE launch.
// blockIdx.x in [0,160): [0,64)=Wq, [64,80)=Wk, [80,96)=Wv, [96,160)=Wo.
__global__ void wconvT_kernel(const float* __restrict__ Wq,
                              const float* __restrict__ Wk,
                              const float* __restrict__ Wv,
                              const float* __restrict__ Wo,
                              __nv_bfloat16* __restrict__ wh,
                              __nv_bfloat16* __restrict__ wl,
                              __nv_bfloat16* __restrict__ woh,
                              __nv_bfloat16* __restrict__ wol)
{
    const int bx = blockIdx.x;
    const float* W;
    __nv_bfloat16 *Th, *Tl;
    int N, nblk;
    if (bx < 64)      { W = Wq; Th = wh;  Tl = wl;  N = HID; nblk = bx; }
    else if (bx < 80) { W = Wk; Th = wh + (size_t)HID * GEMM_K;
                        Tl = wl + (size_t)HID * GEMM_K; N = KVW; nblk = bx - 64; }
    else if (bx < 96) { W = Wv; Th = wh + (size_t)(HID + KVW) * GEMM_K;
                        Tl = wl + (size_t)(HID + KVW) * GEMM_K; N = KVW; nblk = bx - 80; }
    else              { W = Wo; Th = woh; Tl = wol; N = HID; nblk = bx - 96; }

    __shared__ float t[32][33];
    const int n  = nblk * 32 + threadIdx.x;
    const int kb = blockIdx.y * 32;
    #pragma unroll
    for (int j = 0; j < 32; j += 8)
        t[threadIdx.y + j][threadIdx.x] = W[(size_t)(kb + threadIdx.y + j) * N + n];
    __syncthreads();
    const int k  = kb + threadIdx.x;
    const int nb = nblk * 32;
    #pragma unroll
    for (int j = 0; j < 32; j += 8) {
        float v = t[threadIdx.x][threadIdx.y + j];
        __nv_bfloat16 h = __float2bfloat16(v);
        size_t o = (size_t)(nb + threadIdx.y + j) * GEMM_K + k;
        Th[o] = h;
        Tl[o] = __float2bfloat16(v - __bfloat162float(h));
    }
}

__global__ void vsplitT_kernel(const float* __restrict__ V,
                               __nv_bfloat16* __restrict__ Th,
                               __nv_bfloat16* __restrict__ Tl)
{
    __shared__ float t[32][33];
    const int n0 = blockIdx.x * 32;
    const int s0 = blockIdx.y * 32;
    const int b  = blockIdx.z;
    #pragma unroll
    for (int j = 0; j < 32; j += 8)
        t[threadIdx.y + j][threadIdx.x] =
            V[(size_t)(b * SEQ + s0 + threadIdx.y + j) * KVW + n0 + threadIdx.x];
    __syncthreads();
    #pragma unroll
    for (int j = 0; j < 32; j += 8) {
        float v = t[threadIdx.x][threadIdx.y + j];
        __nv_bfloat16 h = __float2bfloat16(v);
        size_t o = (size_t)(b * KVW + n0 + threadIdx.y + j) * SEQ + s0 + threadIdx.x;
        Th[o] = h;
        Tl[o] = __float2bfloat16(v - __bfloat162float(h));
    }
}

// ---------------------------------------------------------------------------
// HMMA GEMM mainloop (shared via macro)
// ---------------------------------------------------------------------------
#define KC        32
#define AS_STRIDE 40
#define MAT_B     (128 * AS_STRIDE * 2)
#define STAGE_B   (4 * MAT_B)
#define NCHUNK    (GEMM_K / KC)

#define GEMM_MAINLOOP(AhP, AlP, BhP, BlP)                                       \
    float acc[4][4][4];                                                         \
    _Pragma("unroll")                                                           \
    for (int a = 0; a < 4; ++a)                                                 \
        _Pragma("unroll")                                                       \
        for (int b2 = 0; b2 < 4; ++b2)                                          \
            _Pragma("unroll")                                                   \
            for (int c = 0; c < 4; ++c) acc[a][b2][c] = 0.f;                    \
    const __nv_bfloat16* mats[4] = {AhP, AlP, BhP, BlP};                        \
    auto load_stage = [&](int s, int k0) {                                      \
        const uint32_t st = smem_base + s * STAGE_B;                            \
        _Pragma("unroll")                                                       \
        for (int mat = 0; mat < 4; ++mat) {                                     \
            const __nv_bfloat16* src = mats[mat];                               \
            const int r0 = (mat < 2) ? m0 : n0;                                 \
            const uint32_t dstb = st + mat * MAT_B;                             \
            _Pragma("unroll")                                                   \
            for (int it = 0; it < 2; ++it) {                                    \
                const int idx = it * 256 + tid;                                 \
                const int row = idx >> 2;                                       \
                const int k4  = idx & 3;                                        \
                const void* sp = src + (size_t)(r0 + row) * GEMM_K + k0 + k4*8; \
                const uint32_t dp = dstb + row * (AS_STRIDE * 2) + k4 * 16;     \
                CP_ASYNC16(dp, sp);                                             \
            }                                                                   \
        }                                                                       \
    };                                                                          \
    load_stage(0, 0);                                                           \
    CP_COMMIT();                                                                \
    for (int c = 0; c < NCHUNK; ++c) {                                          \
        if (c + 1 < NCHUNK) {                                                   \
            load_stage((c + 1) & 1, (c + 1) * KC);                              \
            CP_COMMIT();                                                        \
            CP_WAIT(1);                                                         \
        } else {                                                                \
            CP_WAIT(0);                                                         \
        }                                                                       \
        __syncthreads();                                                        \
        const uint32_t stg = smem_base + (c & 1) * STAGE_B;                     \
        const uint32_t pAh = stg;                                               \
        const uint32_t pAl = stg + MAT_B;                                       \
        const uint32_t pBh = stg + 2 * MAT_B;                                   \
        const uint32_t pBl = stg + 3 * MAT_B;                                   \
        _Pragma("unroll")                                                       \
        for (int ks = 0; ks < 2; ++ks) {                                        \
            const int kcol = ks * 16;                                           \
            uint32_t bh[8], bl[8];                                              \
            _Pragma("unroll")                                                   \
            for (int p = 0; p < 2; ++p) {                                       \
                const int nrow = wn * 32 + p * 16 + (lane & 7) + ((lane>>4)<<3);\
                const int kk   = kcol + (((lane >> 3) & 1) << 3);               \
                const uint32_t off = (nrow * AS_STRIDE + kk) * 2;               \
                ldsm_x4(&bh[p * 4], pBh + off);                                 \
                ldsm_x4(&bl[p * 4], pBl + off);                                 \
            }                                                                   \
            _Pragma("unroll")                                                   \
            for (int mt = 0; mt < 4; ++mt) {                                    \
                const int mrow = wm * 64 + mt * 16 + (lane & 15);               \
                const int kk2  = kcol + ((lane >> 4) << 3);                     \
                const uint32_t offa = (mrow * AS_STRIDE + kk2) * 2;             \
                uint32_t afr[4];                                                \
                ldsm_x4(afr, pAh + offa);                                       \
                _Pragma("unroll")                                               \
                for (int nt = 0; nt < 4; ++nt) mma_bf16(acc[mt][nt], afr, &bh[nt*2]); \
                _Pragma("unroll")                                               \
                for (int nt = 0; nt < 4; ++nt) mma_bf16(acc[mt][nt], afr, &bl[nt*2]); \
                ldsm_x4(afr, pAl + offa);                                       \
                _Pragma("unroll")                                               \
                for (int nt = 0; nt < 4; ++nt) mma_bf16(acc[mt][nt], afr, &bh[nt*2]); \
            }                                                                   \
        }                                                                       \
        __syncthreads();                                                        \
    }

// ---------------------------------------------------------------------------
// Fused QKV projection: N = 3072 (q 0:2048 pre-scaled+split, k split, v fp32)
// ---------------------------------------------------------------------------
#define ATT_SCL 0.08838834764831845f

__global__ void __launch_bounds__(256)
gemm_qkv(const __nv_bfloat16* __restrict__ Ah, const __nv_bfloat16* __restrict__ Al,
         const __nv_bfloat16* __restrict__ Bh, const __nv_bfloat16* __restrict__ Bl,
         const float* __restrict__ bq, const float* __restrict__ bk,
         const float* __restrict__ bv,
         __nv_bfloat16* __restrict__ Qh, __nv_bfloat16* __restrict__ Ql,
         __nv_bfloat16* __restrict__ Kh, __nv_bfloat16* __restrict__ Kl,
         float* __restrict__ Vo)
{
    extern __shared__ __align__(128) char smem[];
    const uint32_t smem_base = smem_to_u32(smem);
    const int tid  = threadIdx.x;
    const int warp = tid >> 5;
    const int lane = tid & 31;
    const int wm   = warp >> 2;
    const int wn   = warp & 3;
    const int m0   = blockIdx.y * 128;
    const int n0   = blockIdx.x * 128;

    GEMM_MAINLOOP(Ah, Al, Bh, Bl)

    #pragma unroll
    for (int mt = 0; mt < 4; ++mt)
        #pragma unroll
        for (int rh = 0; rh < 2; ++rh) {
            const int row = m0 + wm * 64 + mt * 16 + (lane >> 2) + rh * 8;
            #pragma unroll
            for (int nt = 0; nt < 4; ++nt) {
                const int col = n0 + wn * 32 + nt * 8 + (lane & 3) * 2;
                if (n0 < HID) {
                    const float v0 = (acc[mt][nt][rh*2+0] + bq[col])   * ATT_SCL;
                    const float v1 = (acc[mt][nt][rh*2+1] + bq[col+1]) * ATT_SCL;
                    uint32_t hi, lo;
                    split2(v0, v1, hi, lo);
                    *(uint32_t*)&Qh[(size_t)row * HID + col] = hi;
                    *(uint32_t*)&Ql[(size_t)row * HID + col] = lo;
                } else if (n0 < HID + KVW) {
                    const int c2 = col - HID;
                    const float v0 = acc[mt][nt][rh*2+0] + bk[c2];
                    const float v1 = acc[mt][nt][rh*2+1] + bk[c2+1];
                    uint32_t hi, lo;
                    split2(v0, v1, hi, lo);
                    *(uint32_t*)&Kh[(size_t)row * KVW + c2] = hi;
                    *(uint32_t*)&Kl[(size_t)row * KVW + c2] = lo;
                } else {
                    const int c2 = col - HID - KVW;
                    float2 v;
                    v.x = acc[mt][nt][rh*2+0] + bv[c2];
                    v.y = acc[mt][nt][rh*2+1] + bv[c2+1];
                    *(float2*)&Vo[(size_t)row * KVW + c2] = v;
                }
            }
        }
}

// ---------------------------------------------------------------------------
// O-projection GEMM (fp32 out)
// ---------------------------------------------------------------------------
__global__ void __launch_bounds__(256)
gemm_o(const __nv_bfloat16* __restrict__ Ah, const __nv_bfloat16* __restrict__ Al,
       const __nv_bfloat16* __restrict__ Bh, const __nv_bfloat16* __restrict__ Bl,
       const float* __restrict__ bias, float* __restrict__ C)
{
    extern __shared__ __align__(128) char smem[];
    const uint32_t smem_base = smem_to_u32(smem);
    const int tid  = threadIdx.x;
    const int warp = tid >> 5;
    const int lane = tid & 31;
    const int wm   = warp >> 2;
    const int wn   = warp & 3;
    const int m0   = blockIdx.y * 128;
    const int n0   = blockIdx.x * 128;

    GEMM_MAINLOOP(Ah, Al, Bh, Bl)

    #pragma unroll
    for (int mt = 0; mt < 4; ++mt)
        #pragma unroll
        for (int rh = 0; rh < 2; ++rh) {
            const int row = m0 + wm * 64 + mt * 16 + (lane >> 2) + rh * 8;
            #pragma unroll
            for (int nt = 0; nt < 4; ++nt) {
                const int col = n0 + wn * 32 + nt * 8 + (lane & 3) * 2;
                float2 v;
                v.x = acc[mt][nt][rh*2+0] + bias[col];
                v.y = acc[mt][nt][rh*2+1] + bias[col+1];
                *(float2*)&C[(size_t)row * HID + col] = v;
            }
        }
}

// ---------------------------------------------------------------------------
// HMMA FlashAttention: 128 q-rows x 64 kv tiles, 8 warps (16 q-rows each).
// Grid (NH, SEQ/128, BATCH): h fast (4-head groups share K/V in L2),
// qb reversed on the SLOW axis => true LPT scheduling.
// ---------------------------------------------------------------------------
#define QSTR 136
#define VSTR 72
#define SM_QH 0
#define SM_QL 34816
#define SM_KH 69632
#define SM_KL 87040
#define SM_VH 104448
#define SM_VL 122880
#define SM_MK 141312
#define ATTN_SMEM 141568

__global__ void __launch_bounds__(256)
attn_hmma(const __nv_bfloat16* __restrict__ Qh, const __nv_bfloat16* __restrict__ Ql,
          const __nv_bfloat16* __restrict__ Kh, const __nv_bfloat16* __restrict__ Kl,
          const __nv_bfloat16* __restrict__ VTh, const __nv_bfloat16* __restrict__ VTl,
          const int* __restrict__ mask,
          __nv_bfloat16* __restrict__ OH, __nv_bfloat16* __restrict__ OL)
{
    extern __shared__ __align__(128) char sm[];
    const uint32_t base = smem_to_u32(sm);
    const int tid = threadIdx.x;
    const int w    = tid >> 5;
    const int lane = tid & 31;
    const int h  = blockIdx.x;
    const int qb = (int)gridDim.y - 1 - (int)blockIdx.y;   // heavy-first (LPT)
    const int b  = blockIdx.z;
    const int q0 = qb * 128;
    const int kvh = h >> 2;
    const int T = 2 * qb + 2;

    auto load_k = [&](int k0) {
        #pragma unroll
        for (int mat = 0; mat < 2; ++mat) {
            const __nv_bfloat16* src = mat ? Kl : Kh;
            const uint32_t dst = base + (mat ? SM_KL : SM_KH);
            #pragma unroll
            for (int i = 0; i < 4; ++i) {
                const int idx = i * 256 + tid;
                const int row = idx >> 4, c = idx & 15;
                CP_ASYNC16(dst + row * 272 + c * 16,
                           src + (size_t)(b * SEQ + k0 + row) * KVW + kvh * DH + c * 8);
            }
        }
        if (tid < 64)
            CP_ASYNC4(base + SM_MK + tid * 4, mask + b * SEQ + k0 + tid);
    };
    auto load_v = [&](int k0) {
        #pragma unroll
        for (int mat = 0; mat < 2; ++mat) {
            const __nv_bfloat16* src = mat ? VTl : VTh;
            const uint32_t dst = base + (mat ? SM_VL : SM_VH);
            #pragma unroll
            for (int i = 0; i < 4; ++i) {
                const int idx = i * 256 + tid;
                const int row = idx >> 3, c = idx & 7;
                CP_ASYNC16(dst + row * 144 + c * 16,
                           src + (size_t)(b * KVW + kvh * DH + row) * SEQ + k0 + c * 8);
            }
        }
    };

    // prologue: Q + K(0) + mask(0)
    #pragma unroll
    for (int mat = 0; mat < 2; ++mat) {
        const __nv_bfloat16* src = mat ? Ql : Qh;
        const uint32_t dst = base + (mat ? SM_QL : SM_QH);
        #pragma unroll
        for (int i = 0; i < 8; ++i) {
            const int idx = i * 256 + tid;
            const int row = idx >> 4, c = idx & 15;
            CP_ASYNC16(dst + row * 272 + c * 16,
                       src + (size_t)(b * SEQ + q0 + row) * HID + h * DH + c * 8);
        }
    }
    load_k(0);
    CP_COMMIT();
    CP_WAIT(0);
    __syncthreads();

    float s[8][4];
    float o[16][4];
    #pragma unroll
    for (int j = 0; j < 16; ++j)
        #pragma unroll
        for (int c = 0; c < 4; ++c) o[j][c] = 0.f;
    float m0 = -1e30f, m1 = -1e30f, l0 = 0.f, l1 = 0.f;

    const int r0g = q0 + w * 16 + (lane >> 2);
    const int r1g = r0g + 8;
    const int c0l = (lane & 3) * 2;
    const int* mk_s = (const int*)(sm + SM_MK);

    for (int t = 0; t < T; ++t) {
        const int k0 = t * 64;
        const bool active = (q0 + w * 16 + 15) >= k0;

        load_v(k0);
        CP_COMMIT();

        if (active) {
            #pragma unroll
            for (int j = 0; j < 8; ++j)
                #pragma unroll
                for (int c = 0; c < 4; ++c) s[j][c] = 0.f;

            // S = Qh*Kh + Qh*Kl + Ql*Kh  (Q pre-scaled by 1/sqrt(d))
            #pragma unroll
            for (int kc = 0; kc < 8; ++kc) {
                const uint32_t offa =
                    ((w * 16 + (lane & 15)) * QSTR + kc * 16 + ((lane >> 4) << 3)) * 2;
                uint32_t ah[4], al[4];
                ldsm_x4(ah, base + SM_QH + offa);
                ldsm_x4(al, base + SM_QL + offa);
                #pragma unroll
                for (int g = 0; g < 4; ++g) {
                    const uint32_t offb =
                        ((g * 16 + (lane & 7) + ((lane >> 4) << 3)) * QSTR +
                         kc * 16 + (((lane >> 3) & 1) << 3)) * 2;
                    uint32_t bh[4], bl[4];
                    ldsm_x4(bh, base + SM_KH + offb);
                    ldsm_x4(bl, base + SM_KL + offb);
                    mma_bf16(s[2*g],   ah, &bh[0]);
                    mma_bf16(s[2*g+1], ah, &bh[2]);
                    mma_bf16(s[2*g],   ah, &bl[0]);
                    mma_bf16(s[2*g+1], ah, &bl[2]);
                    mma_bf16(s[2*g],   al, &bh[0]);
                    mma_bf16(s[2*g+1], al, &bh[2]);
                }
            }

            // mask + online softmax (registers)
            float mx0 = -1e30f, mx1 = -1e30f;
            #pragma unroll
            for (int j = 0; j < 8; ++j) {
                const int cg = k0 + j * 8 + c0l;
                const int mk0 = mk_s[j * 8 + c0l];
                const int mk1 = mk_s[j * 8 + c0l + 1];
                s[j][0] = (cg     <= r0g && mk0) ? s[j][0] : -1e30f;
                s[j][1] = (cg + 1 <= r0g && mk1) ? s[j][1] : -1e30f;
                s[j][2] = (cg     <= r1g && mk0) ? s[j][2] : -1e30f;
                s[j][3] = (cg + 1 <= r1g && mk1) ? s[j][3] : -1e30f;
                mx0 = fmaxf(mx0, fmaxf(s[j][0], s[j][1]));
                mx1 = fmaxf(mx1, fmaxf(s[j][2], s[j][3]));
            }
            mx0 = fmaxf(mx0, __shfl_xor_sync(0xffffffff, mx0, 1));
            mx0 = fmaxf(mx0, __shfl_xor_sync(0xffffffff, mx0, 2));
            mx1 = fmaxf(mx1, __shfl_xor_sync(0xffffffff, mx1, 1));
            mx1 = fmaxf(mx1, __shfl_xor_sync(0xffffffff, mx1, 2));
            const float mn0 = fmaxf(m0, mx0), mn1 = fmaxf(m1, mx1);
            const float f0 = __expf(m0 - mn0), f1 = __expf(m1 - mn1);
            m0 = mn0; m1 = mn1;
            float sum0 = 0.f, sum1 = 0.f;
            #pragma unroll
            for (int j = 0; j < 8; ++j) {
                s[j][0] = __expf(s[j][0] - mn0);
                s[j][1] = __expf(s[j][1] - mn0);
                s[j][2] = __expf(s[j][2] - mn1);
                s[j][3] = __expf(s[j][3] - mn1);
                sum0 += s[j][0] + s[j][1];
                sum1 += s[j][2] + s[j][3];
            }
            sum0 += __shfl_xor_sync(0xffffffff, sum0, 1);
            sum0 += __shfl_xor_sync(0xffffffff, sum0, 2);
            sum1 += __shfl_xor_sync(0xffffffff, sum1, 1);
            sum1 += __shfl_xor_sync(0xffffffff, sum1, 2);
            l0 = l0 * f0 + sum0;
            l1 = l1 * f1 + sum1;
            #pragma unroll
            for (int j = 0; j < 16; ++j) {
                o[j][0] *= f0; o[j][1] *= f0;
                o[j][2] *= f1; o[j][3] *= f1;
            }
        }

        CP_WAIT(0);            // VT(t) ready
        __syncthreads();       // all warps done reading K(t)
        if (t + 1 < T) {
            load_k(t * 64 + 64);
            CP_COMMIT();
        }

        if (active) {
            // O += Ph*Vh + Ph*Vl + Pl*Vh
            #pragma unroll
            for (int kc = 0; kc < 4; ++kc) {
                uint32_t aph[4], apl[4];
                split2(s[2*kc][0],   s[2*kc][1],   aph[0], apl[0]);
                split2(s[2*kc][2],   s[2*kc][3],   aph[1], apl[1]);
                split2(s[2*kc+1][0], s[2*kc+1][1], aph[2], apl[2]);
                split2(s[2*kc+1][2], s[2*kc+1][3], aph[3], apl[3]);
                #pragma unroll
                for (int g = 0; g < 8; ++g) {
                    const uint32_t offb =
                        ((g * 16 + (lane & 7) + ((lane >> 4) << 3)) * VSTR +
                         kc * 16 + (((lane >> 3) & 1) << 3)) * 2;
                    uint32_t bh[4], bl[4];
                    ldsm_x4(bh, base + SM_VH + offb);
                    ldsm_x4(bl, base + SM_VL + offb);
                    mma_bf16(o[2*g],   aph, &bh[0]);
                    mma_bf16(o[2*g+1], aph, &bh[2]);
                    mma_bf16(o[2*g],   aph, &bl[0]);
                    mma_bf16(o[2*g+1], aph, &bl[2]);
                    mma_bf16(o[2*g],   apl, &bh[0]);
                    mma_bf16(o[2*g+1], apl, &bh[2]);
                }
            }
        }

        CP_WAIT(0);            // K(t+1) ready
        __syncthreads();       // all warps done reading VT(t)
    }

    // epilogue: normalize, split bf16 hi/lo, store
    const float inv0 = 1.f / l0, inv1 = 1.f / l1;
    const size_t base0 = (size_t)(b * SEQ + r0g) * HID + h * DH;
    const size_t base1 = (size_t)(b * SEQ + r1g) * HID + h * DH;
    #pragma unroll
    for (int j = 0; j < 16; ++j) {
        const int col = j * 8 + c0l;
        uint32_t hi, lo;
        split2(o[j][0] * inv0, o[j][1] * inv0, hi, lo);
        *(uint32_t*)&OH[base0 + col] = hi;
        *(uint32_t*)&OL[base0 + col] = lo;
        split2(o[j][2] * inv1, o[j][3] * inv1, hi, lo);
        *(uint32_t*)&OH[base1 + col] = hi;
        *(uint32_t*)&OL[base1 + col] = lo;
    }
}

// ---------------------------------------------------------------------------
// Launch
// ---------------------------------------------------------------------------
extern "C" void kernel_launch(void* const* d_in, const int* in_sizes, int n_in,
                              void* d_out, int out_size)
{
    const float* x    = (const float*)d_in[0];
    const int*   mask = (const int*)  d_in[1];
    const float* Wq   = (const float*)d_in[2];
    const float* bq   = (const float*)d_in[3];
    const float* Wk   = (const float*)d_in[4];
    const float* bk   = (const float*)d_in[5];
    const float* Wv   = (const float*)d_in[6];
    const float* bv   = (const float*)d_in[7];
    const float* Wo   = (const float*)d_in[8];
    const float* bo   = (const float*)d_in[9];
    float* out = (float*)d_out;

    void *pv, *pxh, *pxl, *pqh, *pql, *pkh, *pkl, *pvth, *pvtl, *pah, *pal;
    void *pwh, *pwl, *pwoh, *pwol;
    cudaGetSymbolAddress(&pv,  g_v);
    cudaGetSymbolAddress(&pxh, g_xh);  cudaGetSymbolAddress(&pxl, g_xl);
    cudaGetSymbolAddress(&pqh, g_qh);  cudaGetSymbolAddress(&pql, g_ql);
    cudaGetSymbolAddress(&pkh, g_kh);  cudaGetSymbolAddress(&pkl, g_kl);
    cudaGetSymbolAddress(&pvth, g_vth); cudaGetSymbolAddress(&pvtl, g_vtl);
    cudaGetSymbolAddress(&pah, g_ah);  cudaGetSymbolAddress(&pal, g_al);
    cudaGetSymbolAddress(&pwh, g_wh);  cudaGetSymbolAddress(&pwl, g_wl);
    cudaGetSymbolAddress(&pwoh, g_woh); cudaGetSymbolAddress(&pwol, g_wol);

    __nv_bfloat16* wh = (__nv_bfloat16*)pwh;
    __nv_bfloat16* wl = (__nv_bfloat16*)pwl;

    // --- converters (2 launches) ---
    const int n4 = MTOT * HID / 4;
    split_kernel<<<n4 / 256, 256>>>(x, (__nv_bfloat16*)pxh, (__nv_bfloat16*)pxl, n4);
    dim3 tb(32, 8);
    wconvT_kernel<<<dim3(160, GEMM_K / 32), tb>>>(
        Wq, Wk, Wv, Wo, wh, wl, (__nv_bfloat16*)pwoh, (__nv_bfloat16*)pwol);

    // --- fused QKV projection ---
    const int gemm_smem = 2 * STAGE_B;
    cudaFuncSetAttribute(gemm_qkv, cudaFuncAttributeMaxDynamicSharedMemorySize,
                         gemm_smem);
    cudaFuncSetAttribute(gemm_o, cudaFuncAttributeMaxDynamicSharedMemorySize,
                         gemm_smem);
    gemm_qkv<<<dim3(NQKV / 128, MTOT / 128), 256, gemm_smem>>>(
        (const __nv_bfloat16*)pxh, (const __nv_bfloat16*)pxl, wh, wl,
        bq, bk, bv,
        (__nv_bfloat16*)pqh, (__nv_bfloat16*)pql,
        (__nv_bfloat16*)pkh, (__nv_bfloat16*)pkl, (float*)pv);

    // --- V transpose + split ---
    vsplitT_kernel<<<dim3(KVW / 32, SEQ / 32, BATCH), tb>>>(
        (const float*)pv, (__nv_bfloat16*)pvth, (__nv_bfloat16*)pvtl);

    // --- HMMA flash attention (h fast, qb slow reversed = LPT) ---
    cudaFuncSetAttribute(attn_hmma, cudaFuncAttributeMaxDynamicSharedMemorySize,
                         ATTN_SMEM);
    attn_hmma<<<dim3(NH, SEQ / 128, BATCH), 256, ATTN_SMEM>>>(
        (const __nv_bfloat16*)pqh, (const __nv_bfloat16*)pql,
        (const __nv_bfloat16*)pkh, (const __nv_bfloat16*)pkl,
        (const __nv_bfloat16*)pvth, (const __nv_bfloat16*)pvtl,
        mask, (__nv_bfloat16*)pah, (__nv_bfloat16*)pal);

    // --- output projection ---
    gemm_o<<<dim3(HID / 128, MTOT / 128), 256, gemm_smem>>>(
        (const __nv_bfloat16*)pah, (const __nv_bfloat16*)pal,
        (const __nv_bfloat16*)pwoh, (const __nv_bfloat16*)pwol, bo, out);
}

// round 8
// speedup vs baseline: 1.4909x; 1.3900x over previous
#include <cuda_runtime.h>
#include <cuda_bf16.h>
#include <cuda_fp16.h>
#include <cstdint>
#include <math.h>

// ---------------------------------------------------------------------------
// Problem constants
// ---------------------------------------------------------------------------
#define BATCH   2
#define SEQ     2048
#define HID     2048
#define NH      16
#define NKV     4
#define DH      128
#define KVW     (NKV * DH)          // 512
#define MTOT    (BATCH * SEQ)       // 4096
#define GROUPS  (NH / NKV)          // 4
#define GEMM_K  2048
#define NQKV    (HID + 2 * KVW)     // 3072

// ---------------------------------------------------------------------------
// PTX helpers — ONLY non-'a' features (mma.sync / ldmatrix / cp.async).
// ---------------------------------------------------------------------------
__device__ __forceinline__ uint32_t smem_to_u32(const void* p) {
    uint32_t a;
    asm("{ .reg .u64 t; cvta.to.shared.u64 t, %1; cvt.u32.u64 %0, t; }"
        : "=r"(a) : "l"(p));
    return a;
}
#define CP_ASYNC16(dst, src) \
    asm volatile("cp.async.cg.shared.global [%0], [%1], 16;" \
                 :: "r"(dst), "l"(src))
#define CP_ASYNC4(dst, src) \
    asm volatile("cp.async.ca.shared.global [%0], [%1], 4;" \
                 :: "r"(dst), "l"(src))
#define CP_COMMIT() asm volatile("cp.async.commit_group;")
#define CP_WAIT(n)  asm volatile("cp.async.wait_group %0;" :: "n"(n))

__device__ __forceinline__ void ldsm_x4(uint32_t* r, uint32_t addr) {
    asm volatile("ldmatrix.sync.aligned.m8n8.x4.shared.b16 {%0,%1,%2,%3}, [%4];"
                 : "=r"(r[0]), "=r"(r[1]), "=r"(r[2]), "=r"(r[3]) : "r"(addr));
}
__device__ __forceinline__ void mma_bf16(float* d, const uint32_t* a,
                                         const uint32_t* b) {
    asm volatile(
        "mma.sync.aligned.m16n8k16.row.col.f32.bf16.bf16.f32 "
        "{%0,%1,%2,%3}, {%4,%5,%6,%7}, {%8,%9}, {%0,%1,%2,%3};"
        : "+f"(d[0]), "+f"(d[1]), "+f"(d[2]), "+f"(d[3])
        : "r"(a[0]), "r"(a[1]), "r"(a[2]), "r"(a[3]), "r"(b[0]), "r"(b[1]));
}
__device__ __forceinline__ void mma_f16(float* d, const uint32_t* a,
                                        const uint32_t* b) {
    asm volatile(
        "mma.sync.aligned.m16n8k16.row.col.f32.f16.f16.f32 "
        "{%0,%1,%2,%3}, {%4,%5,%6,%7}, {%8,%9}, {%0,%1,%2,%3};"
        : "+f"(d[0]), "+f"(d[1]), "+f"(d[2]), "+f"(d[3])
        : "r"(a[0]), "r"(a[1]), "r"(a[2]), "r"(a[3]), "r"(b[0]), "r"(b[1]));
}
// bf16 hi/lo split (attention P/Q/K path)
__device__ __forceinline__ void split2(float x, float y, uint32_t& hi, uint32_t& lo) {
    __nv_bfloat16 bx = __float2bfloat16(x), by = __float2bfloat16(y);
    __nv_bfloat162 h(bx, by);
    hi = *reinterpret_cast<uint32_t*>(&h);
    __nv_bfloat162 l(__float2bfloat16(x - __bfloat162float(bx)),
                     __float2bfloat16(y - __bfloat162float(by)));
    lo = *reinterpret_cast<uint32_t*>(&l);
}
__device__ __forceinline__ float ex2(float x) {
    float r;
    asm("ex2.approx.f32 %0, %1;" : "=f"(r) : "f"(x));
    return r;
}

// ---------------------------------------------------------------------------
// Scratch buffers
// ---------------------------------------------------------------------------
__device__ float g_v[(size_t)MTOT * KVW];
__device__ __half g_xh[(size_t)MTOT * HID];           // x as single fp16
__device__ __nv_bfloat16 g_qh[(size_t)MTOT * HID];
__device__ __nv_bfloat16 g_ql[(size_t)MTOT * HID];
__device__ __nv_bfloat16 g_kh[(size_t)MTOT * KVW];
__device__ __nv_bfloat16 g_kl[(size_t)MTOT * KVW];
__device__ __nv_bfloat16 g_vth[(size_t)MTOT * KVW];   // [B*KVW, SEQ]
__device__ __nv_bfloat16 g_vtl[(size_t)MTOT * KVW];
__device__ __half g_ah[(size_t)MTOT * HID];           // attn out as single fp16
__device__ __half g_wh[(size_t)NQKV * HID];           // [Wq;Wk;Wv] T, fp16 hi
__device__ __half g_wl[(size_t)NQKV * HID];           //                fp16 lo
__device__ __half g_woh[(size_t)HID * HID];
__device__ __half g_wol[(size_t)HID * HID];

// ---------------------------------------------------------------------------
// Converters
// ---------------------------------------------------------------------------
// x fp32 -> fp16 (single)
__global__ void xcvt_kernel(const float* __restrict__ in,
                            __half* __restrict__ hi, int n4)
{
    int i = blockIdx.x * blockDim.x + threadIdx.x;
    if (i >= n4) return;
    float4 v = ((const float4*)in)[i];
    __half2 a(__float2half(v.x), __float2half(v.y));
    __half2 b(__float2half(v.z), __float2half(v.w));
    ((__half2*)hi)[2*i]   = a;
    ((__half2*)hi)[2*i+1] = b;
}

// All four weight matrices transposed + fp16 hi/lo split in ONE launch.
// blockIdx.x in [0,160): [0,64)=Wq, [64,80)=Wk, [80,96)=Wv, [96,160)=Wo.
__global__ void wconvT_kernel(const float* __restrict__ Wq,
                              const float* __restrict__ Wk,
                              const float* __restrict__ Wv,
                              const float* __restrict__ Wo,
                              __half* __restrict__ wh,
                              __half* __restrict__ wl,
                              __half* __restrict__ woh,
                              __half* __restrict__ wol)
{
    const int bx = blockIdx.x;
    const float* W;
    __half *Th, *Tl;
    int N, nblk;
    if (bx < 64)      { W = Wq; Th = wh;  Tl = wl;  N = HID; nblk = bx; }
    else if (bx < 80) { W = Wk; Th = wh + (size_t)HID * GEMM_K;
                        Tl = wl + (size_t)HID * GEMM_K; N = KVW; nblk = bx - 64; }
    else if (bx < 96) { W = Wv; Th = wh + (size_t)(HID + KVW) * GEMM_K;
                        Tl = wl + (size_t)(HID + KVW) * GEMM_K; N = KVW; nblk = bx - 80; }
    else              { W = Wo; Th = woh; Tl = wol; N = HID; nblk = bx - 96; }

    __shared__ float t[32][33];
    const int n  = nblk * 32 + threadIdx.x;
    const int kb = blockIdx.y * 32;
    #pragma unroll
    for (int j = 0; j < 32; j += 8)
        t[threadIdx.y + j][threadIdx.x] = W[(size_t)(kb + threadIdx.y + j) * N + n];
    __syncthreads();
    const int k  = kb + threadIdx.x;
    const int nb = nblk * 32;
    #pragma unroll
    for (int j = 0; j < 32; j += 8) {
        float v = t[threadIdx.x][threadIdx.y + j];
        __half h = __float2half(v);
        size_t o = (size_t)(nb + threadIdx.y + j) * GEMM_K + k;
        Th[o] = h;
        Tl[o] = __float2half(v - __half2float(h));
    }
}

__global__ void vsplitT_kernel(const float* __restrict__ V,
                               __nv_bfloat16* __restrict__ Th,
                               __nv_bfloat16* __restrict__ Tl)
{
    __shared__ float t[32][33];
    const int n0 = blockIdx.x * 32;
    const int s0 = blockIdx.y * 32;
    const int b  = blockIdx.z;
    #pragma unroll
    for (int j = 0; j < 32; j += 8)
        t[threadIdx.y + j][threadIdx.x] =
            V[(size_t)(b * SEQ + s0 + threadIdx.y + j) * KVW + n0 + threadIdx.x];
    __syncthreads();
    #pragma unroll
    for (int j = 0; j < 32; j += 8) {
        float v = t[threadIdx.x][threadIdx.y + j];
        __nv_bfloat16 h = __float2bfloat16(v);
        size_t o = (size_t)(b * KVW + n0 + threadIdx.y + j) * SEQ + s0 + threadIdx.x;
        Th[o] = h;
        Tl[o] = __float2bfloat16(v - __bfloat162float(h));
    }
}

// ---------------------------------------------------------------------------
// fp16 HMMA GEMM mainloop: C = Ah[M,K] @ (Bh+Bl)^T[N,K]
// 3 smem mats per stage (Ah, Bh, Bl). 2 MMA passes per A-fragment.
// ---------------------------------------------------------------------------
#define KC        32
#define AS_STRIDE 40
#define MAT_B     (128 * AS_STRIDE * 2)
#define STAGE_B   (3 * MAT_B)          // 30720 bytes
#define NCHUNK    (GEMM_K / KC)

#define GEMM_MAINLOOP_F16(AhP, BhP, BlP)                                        \
    float acc[4][4][4];                                                         \
    _Pragma("unroll")                                                           \
    for (int a = 0; a < 4; ++a)                                                 \
        _Pragma("unroll")                                                       \
        for (int b2 = 0; b2 < 4; ++b2)                                          \
            _Pragma("unroll")                                                   \
            for (int c = 0; c < 4; ++c) acc[a][b2][c] = 0.f;                    \
    const __half* mats[3] = {AhP, BhP, BlP};                                    \
    auto load_stage = [&](int s, int k0) {                                      \
        const uint32_t st = smem_base + s * STAGE_B;                            \
        _Pragma("unroll")                                                       \
        for (int mat = 0; mat < 3; ++mat) {                                     \
            const __half* src = mats[mat];                                      \
            const int r0 = (mat < 1) ? m0 : n0;                                 \
            const uint32_t dstb = st + mat * MAT_B;                             \
            _Pragma("unroll")                                                   \
            for (int it = 0; it < 2; ++it) {                                    \
                const int idx = it * 256 + tid;                                 \
                const int row = idx >> 2;                                       \
                const int k4  = idx & 3;                                        \
                const void* sp = src + (size_t)(r0 + row) * GEMM_K + k0 + k4*8; \
                const uint32_t dp = dstb + row * (AS_STRIDE * 2) + k4 * 16;     \
                CP_ASYNC16(dp, sp);                                             \
            }                                                                   \
        }                                                                       \
    };                                                                          \
    load_stage(0, 0);                                                           \
    CP_COMMIT();                                                                \
    for (int c = 0; c < NCHUNK; ++c) {                                          \
        if (c + 1 < NCHUNK) {                                                   \
            load_stage((c + 1) & 1, (c + 1) * KC);                              \
            CP_COMMIT();                                                        \
            CP_WAIT(1);                                                         \
        } else {                                                                \
            CP_WAIT(0);                                                         \
        }                                                                       \
        __syncthreads();                                                        \
        const uint32_t stg = smem_base + (c & 1) * STAGE_B;                     \
        const uint32_t pA  = stg;                                               \
        const uint32_t pBh = stg + MAT_B;                                       \
        const uint32_t pBl = stg + 2 * MAT_B;                                   \
        _Pragma("unroll")                                                       \
        for (int ks = 0; ks < 2; ++ks) {                                        \
            const int kcol = ks * 16;                                           \
            uint32_t bh[8], bl[8];                                              \
            _Pragma("unroll")                                                   \
            for (int p = 0; p < 2; ++p) {                                       \
                const int nrow = wn * 32 + p * 16 + (lane & 7) + ((lane>>4)<<3);\
                const int kk   = kcol + (((lane >> 3) & 1) << 3);               \
                const uint32_t off = (nrow * AS_STRIDE + kk) * 2;               \
                ldsm_x4(&bh[p * 4], pBh + off);                                 \
                ldsm_x4(&bl[p * 4], pBl + off);                                 \
            }                                                                   \
            _Pragma("unroll")                                                   \
            for (int mt = 0; mt < 4; ++mt) {                                    \
                const int mrow = wm * 64 + mt * 16 + (lane & 15);               \
                const int kk2  = kcol + ((lane >> 4) << 3);                     \
                const uint32_t offa = (mrow * AS_STRIDE + kk2) * 2;             \
                uint32_t afr[4];                                                \
                ldsm_x4(afr, pA + offa);                                        \
                _Pragma("unroll")                                               \
                for (int nt = 0; nt < 4; ++nt) mma_f16(acc[mt][nt], afr, &bh[nt*2]); \
                _Pragma("unroll")                                               \
                for (int nt = 0; nt < 4; ++nt) mma_f16(acc[mt][nt], afr, &bl[nt*2]); \
            }                                                                   \
        }                                                                       \
        __syncthreads();                                                        \
    }

// ---------------------------------------------------------------------------
// Fused QKV projection: N = 3072 (q 0:2048 pre-scaled+bf16-split, k bf16-split,
// v fp32). Q pre-scale includes log2(e) so attention softmax can use raw ex2.
// ---------------------------------------------------------------------------
#define ATT_SCL (0.08838834764831845f * 1.4426950408889634f)

__global__ void __launch_bounds__(256)
gemm_qkv(const __half* __restrict__ Ah,
         const __half* __restrict__ Bh, const __half* __restrict__ Bl,
         const float* __restrict__ bq, const float* __restrict__ bk,
         const float* __restrict__ bv,
         __nv_bfloat16* __restrict__ Qh, __nv_bfloat16* __restrict__ Ql,
         __nv_bfloat16* __restrict__ Kh, __nv_bfloat16* __restrict__ Kl,
         float* __restrict__ Vo)
{
    extern __shared__ __align__(128) char smem[];
    const uint32_t smem_base = smem_to_u32(smem);
    const int tid  = threadIdx.x;
    const int warp = tid >> 5;
    const int lane = tid & 31;
    const int wm   = warp >> 2;
    const int wn   = warp & 3;
    const int m0   = blockIdx.y * 128;
    const int n0   = blockIdx.x * 128;

    GEMM_MAINLOOP_F16(Ah, Bh, Bl)

    #pragma unroll
    for (int mt = 0; mt < 4; ++mt)
        #pragma unroll
        for (int rh = 0; rh < 2; ++rh) {
            const int row = m0 + wm * 64 + mt * 16 + (lane >> 2) + rh * 8;
            #pragma unroll
            for (int nt = 0; nt < 4; ++nt) {
                const int col = n0 + wn * 32 + nt * 8 + (lane & 3) * 2;
                if (n0 < HID) {
                    const float v0 = (acc[mt][nt][rh*2+0] + bq[col])   * ATT_SCL;
                    const float v1 = (acc[mt][nt][rh*2+1] + bq[col+1]) * ATT_SCL;
                    uint32_t hi, lo;
                    split2(v0, v1, hi, lo);
                    *(uint32_t*)&Qh[(size_t)row * HID + col] = hi;
                    *(uint32_t*)&Ql[(size_t)row * HID + col] = lo;
                } else if (n0 < HID + KVW) {
                    const int c2 = col - HID;
                    const float v0 = acc[mt][nt][rh*2+0] + bk[c2];
                    const float v1 = acc[mt][nt][rh*2+1] + bk[c2+1];
                    uint32_t hi, lo;
                    split2(v0, v1, hi, lo);
                    *(uint32_t*)&Kh[(size_t)row * KVW + c2] = hi;
                    *(uint32_t*)&Kl[(size_t)row * KVW + c2] = lo;
                } else {
                    const int c2 = col - HID - KVW;
                    float2 v;
                    v.x = acc[mt][nt][rh*2+0] + bv[c2];
                    v.y = acc[mt][nt][rh*2+1] + bv[c2+1];
                    *(float2*)&Vo[(size_t)row * KVW + c2] = v;
                }
            }
        }
}

// ---------------------------------------------------------------------------
// O-projection GEMM (fp16 A single, fp16 W hi/lo, fp32 out)
// ---------------------------------------------------------------------------
__global__ void __launch_bounds__(256)
gemm_o(const __half* __restrict__ Ah,
       const __half* __restrict__ Bh, const __half* __restrict__ Bl,
       const float* __restrict__ bias, float* __restrict__ C)
{
    extern __shared__ __align__(128) char smem[];
    const uint32_t smem_base = smem_to_u32(smem);
    const int tid  = threadIdx.x;
    const int warp = tid >> 5;
    const int lane = tid & 31;
    const int wm   = warp >> 2;
    const int wn   = warp & 3;
    const int m0   = blockIdx.y * 128;
    const int n0   = blockIdx.x * 128;

    GEMM_MAINLOOP_F16(Ah, Bh, Bl)

    #pragma unroll
    for (int mt = 0; mt < 4; ++mt)
        #pragma unroll
        for (int rh = 0; rh < 2; ++rh) {
            const int row = m0 + wm * 64 + mt * 16 + (lane >> 2) + rh * 8;
            #pragma unroll
            for (int nt = 0; nt < 4; ++nt) {
                const int col = n0 + wn * 32 + nt * 8 + (lane & 3) * 2;
                float2 v;
                v.x = acc[mt][nt][rh*2+0] + bias[col];
                v.y = acc[mt][nt][rh*2+1] + bias[col+1];
                *(float2*)&C[(size_t)row * HID + col] = v;
            }
        }
}

// ---------------------------------------------------------------------------
// HMMA FlashAttention: 128 q-rows x 64 kv tiles, 8 warps (16 q-rows each).
// Grid (NH, SEQ/128, BATCH), qb reversed on slow axis => LPT scheduling.
// Softmax in base-2 domain (Q pre-scaled by scl*log2e) -> raw ex2.
// ---------------------------------------------------------------------------
#define QSTR 136
#define VSTR 72
#define SM_QH 0
#define SM_QL 34816
#define SM_KH 69632
#define SM_KL 87040
#define SM_VH 104448
#define SM_VL 122880
#define SM_MK 141312
#define ATTN_SMEM 141568

__global__ void __launch_bounds__(256)
attn_hmma(const __nv_bfloat16* __restrict__ Qh, const __nv_bfloat16* __restrict__ Ql,
          const __nv_bfloat16* __restrict__ Kh, const __nv_bfloat16* __restrict__ Kl,
          const __nv_bfloat16* __restrict__ VTh, const __nv_bfloat16* __restrict__ VTl,
          const int* __restrict__ mask,
          __half* __restrict__ OH)
{
    extern __shared__ __align__(128) char sm[];
    const uint32_t base = smem_to_u32(sm);
    const int tid = threadIdx.x;
    const int w    = tid >> 5;
    const int lane = tid & 31;
    const int h  = blockIdx.x;
    const int qb = (int)gridDim.y - 1 - (int)blockIdx.y;   // heavy-first (LPT)
    const int b  = blockIdx.z;
    const int q0 = qb * 128;
    const int kvh = h >> 2;
    const int T = 2 * qb + 2;

    auto load_k = [&](int k0) {
        #pragma unroll
        for (int mat = 0; mat < 2; ++mat) {
            const __nv_bfloat16* src = mat ? Kl : Kh;
            const uint32_t dst = base + (mat ? SM_KL : SM_KH);
            #pragma unroll
            for (int i = 0; i < 4; ++i) {
                const int idx = i * 256 + tid;
                const int row = idx >> 4, c = idx & 15;
                CP_ASYNC16(dst + row * 272 + c * 16,
                           src + (size_t)(b * SEQ + k0 + row) * KVW + kvh * DH + c * 8);
            }
        }
        if (tid < 64)
            CP_ASYNC4(base + SM_MK + tid * 4, mask + b * SEQ + k0 + tid);
    };
    auto load_v = [&](int k0) {
        #pragma unroll
        for (int mat = 0; mat < 2; ++mat) {
            const __nv_bfloat16* src = mat ? VTl : VTh;
            const uint32_t dst = base + (mat ? SM_VL : SM_VH);
            #pragma unroll
            for (int i = 0; i < 4; ++i) {
                const int idx = i * 256 + tid;
                const int row = idx >> 3, c = idx & 7;
                CP_ASYNC16(dst + row * 144 + c * 16,
                           src + (size_t)(b * KVW + kvh * DH + row) * SEQ + k0 + c * 8);
            }
        }
    };

    // prologue: Q + K(0) + mask(0)
    #pragma unroll
    for (int mat = 0; mat < 2; ++mat) {
        const __nv_bfloat16* src = mat ? Ql : Qh;
        const uint32_t dst = base + (mat ? SM_QL : SM_QH);
        #pragma unroll
        for (int i = 0; i < 8; ++i) {
            const int idx = i * 256 + tid;
            const int row = idx >> 4, c = idx & 15;
            CP_ASYNC16(dst + row * 272 + c * 16,
                       src + (size_t)(b * SEQ + q0 + row) * HID + h * DH + c * 8);
        }
    }
    load_k(0);
    CP_COMMIT();
    CP_WAIT(0);
    __syncthreads();

    float s[8][4];
    float o[16][4];
    #pragma unroll
    for (int j = 0; j < 16; ++j)
        #pragma unroll
        for (int c = 0; c < 4; ++c) o[j][c] = 0.f;
    float m0 = -1e30f, m1 = -1e30f, l0 = 0.f, l1 = 0.f;

    const int r0g = q0 + w * 16 + (lane >> 2);
    const int r1g = r0g + 8;
    const int c0l = (lane & 3) * 2;
    const int* mk_s = (const int*)(sm + SM_MK);

    for (int t = 0; t < T; ++t) {
        const int k0 = t * 64;
        const bool active = (q0 + w * 16 + 15) >= k0;

        load_v(k0);
        CP_COMMIT();

        if (active) {
            #pragma unroll
            for (int j = 0; j < 8; ++j)
                #pragma unroll
                for (int c = 0; c < 4; ++c) s[j][c] = 0.f;

            // S = Qh*Kh + Qh*Kl + Ql*Kh  (Q pre-scaled by scl*log2e)
            #pragma unroll
            for (int kc = 0; kc < 8; ++kc) {
                const uint32_t offa =
                    ((w * 16 + (lane & 15)) * QSTR + kc * 16 + ((lane >> 4) << 3)) * 2;
                uint32_t ah[4], al[4];
                ldsm_x4(ah, base + SM_QH + offa);
                ldsm_x4(al, base + SM_QL + offa);
                #pragma unroll
                for (int g = 0; g < 4; ++g) {
                    const uint32_t offb =
                        ((g * 16 + (lane & 7) + ((lane >> 4) << 3)) * QSTR +
                         kc * 16 + (((lane >> 3) & 1) << 3)) * 2;
                    uint32_t bh[4], bl[4];
                    ldsm_x4(bh, base + SM_KH + offb);
                    ldsm_x4(bl, base + SM_KL + offb);
                    mma_bf16(s[2*g],   ah, &bh[0]);
                    mma_bf16(s[2*g+1], ah, &bh[2]);
                    mma_bf16(s[2*g],   ah, &bl[0]);
                    mma_bf16(s[2*g+1], ah, &bl[2]);
                    mma_bf16(s[2*g],   al, &bh[0]);
                    mma_bf16(s[2*g+1], al, &bh[2]);
                }
            }

            // mask + online softmax (registers, base-2 domain)
            float mx0 = -1e30f, mx1 = -1e30f;
            #pragma unroll
            for (int j = 0; j < 8; ++j) {
                const int cg = k0 + j * 8 + c0l;
                const int mk0 = mk_s[j * 8 + c0l];
                const int mk1 = mk_s[j * 8 + c0l + 1];
                s[j][0] = (cg     <= r0g && mk0) ? s[j][0] : -1e30f;
                s[j][1] = (cg + 1 <= r0g && mk1) ? s[j][1] : -1e30f;
                s[j][2] = (cg     <= r1g && mk0) ? s[j][2] : -1e30f;
                s[j][3] = (cg + 1 <= r1g && mk1) ? s[j][3] : -1e30f;
                mx0 = fmaxf(mx0, fmaxf(s[j][0], s[j][1]));
                mx1 = fmaxf(mx1, fmaxf(s[j][2], s[j][3]));
            }
            mx0 = fmaxf(mx0, __shfl_xor_sync(0xffffffff, mx0, 1));
            mx0 = fmaxf(mx0, __shfl_xor_sync(0xffffffff, mx0, 2));
            mx1 = fmaxf(mx1, __shfl_xor_sync(0xffffffff, mx1, 1));
            mx1 = fmaxf(mx1, __shfl_xor_sync(0xffffffff, mx1, 2));
            const float mn0 = fmaxf(m0, mx0), mn1 = fmaxf(m1, mx1);
            const float f0 = ex2(m0 - mn0), f1 = ex2(m1 - mn1);
            m0 = mn0; m1 = mn1;
            float sum0 = 0.f, sum1 = 0.f;
            #pragma unroll
            for (int j = 0; j < 8; ++j) {
                s[j][0] = ex2(s[j][0] - mn0);
                s[j][1] = ex2(s[j][1] - mn0);
                s[j][2] = ex2(s[j][2] - mn1);
                s[j][3] = ex2(s[j][3] - mn1);
                sum0 += s[j][0] + s[j][1];
                sum1 += s[j][2] + s[j][3];
            }
            sum0 += __shfl_xor_sync(0xffffffff, sum0, 1);
            sum0 += __shfl_xor_sync(0xffffffff, sum0, 2);
            sum1 += __shfl_xor_sync(0xffffffff, sum1, 1);
            sum1 += __shfl_xor_sync(0xffffffff, sum1, 2);
            l0 = l0 * f0 + sum0;
            l1 = l1 * f1 + sum1;
            #pragma unroll
            for (int j = 0; j < 16; ++j) {
                o[j][0] *= f0; o[j][1] *= f0;
                o[j][2] *= f1; o[j][3] *= f1;
            }
        }

        CP_WAIT(0);            // VT(t) ready
        __syncthreads();       // all warps done reading K(t)
        if (t + 1 < T) {
            load_k(t * 64 + 64);
            CP_COMMIT();
        }

        if (active) {
            // O += Ph*Vh + Ph*Vl + Pl*Vh
            #pragma unroll
            for (int kc = 0; kc < 4; ++kc) {
                uint32_t aph[4], apl[4];
                split2(s[2*kc][0],   s[2*kc][1],   aph[0], apl[0]);
                split2(s[2*kc][2],   s[2*kc][3],   aph[1], apl[1]);
                split2(s[2*kc+1][0], s[2*kc+1][1], aph[2], apl[2]);
                split2(s[2*kc+1][2], s[2*kc+1][3], aph[3], apl[3]);
                #pragma unroll
                for (int g = 0; g < 8; ++g) {
                    const uint32_t offb =
                        ((g * 16 + (lane & 7) + ((lane >> 4) << 3)) * VSTR +
                         kc * 16 + (((lane >> 3) & 1) << 3)) * 2;
                    uint32_t bh[4], bl[4];
                    ldsm_x4(bh, base + SM_VH + offb);
                    ldsm_x4(bl, base + SM_VL + offb);
                    mma_bf16(o[2*g],   aph, &bh[0]);
                    mma_bf16(o[2*g+1], aph, &bh[2]);
                    mma_bf16(o[2*g],   aph, &bl[0]);
                    mma_bf16(o[2*g+1], aph, &bl[2]);
                    mma_bf16(o[2*g],   apl, &bh[0]);
                    mma_bf16(o[2*g+1], apl, &bh[2]);
                }
            }
        }

        CP_WAIT(0);            // K(t+1) ready
        __syncthreads();       // all warps done reading VT(t)
    }

    // epilogue: normalize, store single fp16
    const float inv0 = 1.f / l0, inv1 = 1.f / l1;
    const size_t base0 = (size_t)(b * SEQ + r0g) * HID + h * DH;
    const size_t base1 = (size_t)(b * SEQ + r1g) * HID + h * DH;
    #pragma unroll
    for (int j = 0; j < 16; ++j) {
        const int col = j * 8 + c0l;
        __half2 h0(__float2half(o[j][0] * inv0), __float2half(o[j][1] * inv0));
        __half2 h1(__float2half(o[j][2] * inv1), __float2half(o[j][3] * inv1));
        *(__half2*)&OH[base0 + col] = h0;
        *(__half2*)&OH[base1 + col] = h1;
    }
}

// ---------------------------------------------------------------------------
// Launch
// ---------------------------------------------------------------------------
extern "C" void kernel_launch(void* const* d_in, const int* in_sizes, int n_in,
                              void* d_out, int out_size)
{
    const float* x    = (const float*)d_in[0];
    const int*   mask = (const int*)  d_in[1];
    const float* Wq   = (const float*)d_in[2];
    const float* bq   = (const float*)d_in[3];
    const float* Wk   = (const float*)d_in[4];
    const float* bk   = (const float*)d_in[5];
    const float* Wv   = (const float*)d_in[6];
    const float* bv   = (const float*)d_in[7];
    const float* Wo   = (const float*)d_in[8];
    const float* bo   = (const float*)d_in[9];
    float* out = (float*)d_out;

    void *pv, *pxh, *pqh, *pql, *pkh, *pkl, *pvth, *pvtl, *pah;
    void *pwh, *pwl, *pwoh, *pwol;
    cudaGetSymbolAddress(&pv,  g_v);
    cudaGetSymbolAddress(&pxh, g_xh);
    cudaGetSymbolAddress(&pqh, g_qh);  cudaGetSymbolAddress(&pql, g_ql);
    cudaGetSymbolAddress(&pkh, g_kh);  cudaGetSymbolAddress(&pkl, g_kl);
    cudaGetSymbolAddress(&pvth, g_vth); cudaGetSymbolAddress(&pvtl, g_vtl);
    cudaGetSymbolAddress(&pah, g_ah);
    cudaGetSymbolAddress(&pwh, g_wh);  cudaGetSymbolAddress(&pwl, g_wl);
    cudaGetSymbolAddress(&pwoh, g_woh); cudaGetSymbolAddress(&pwol, g_wol);

    __half* wh = (__half*)pwh;
    __half* wl = (__half*)pwl;

    // --- converters (2 launches) ---
    const int n4 = MTOT * HID / 4;
    xcvt_kernel<<<n4 / 256, 256>>>(x, (__half*)pxh, n4);
    dim3 tb(32, 8);
    wconvT_kernel<<<dim3(160, GEMM_K / 32), tb>>>(
        Wq, Wk, Wv, Wo, wh, wl, (__half*)pwoh, (__half*)pwol);

    // --- fused QKV projection (fp16 2-pass) ---
    const int gemm_smem = 2 * STAGE_B;   // 61440
    cudaFuncSetAttribute(gemm_qkv, cudaFuncAttributeMaxDynamicSharedMemorySize,
                         gemm_smem);
    cudaFuncSetAttribute(gemm_o, cudaFuncAttributeMaxDynamicSharedMemorySize,
                         gemm_smem);
    gemm_qkv<<<dim3(NQKV / 128, MTOT / 128), 256, gemm_smem>>>(
        (const __half*)pxh, wh, wl, bq, bk, bv,
        (__nv_bfloat16*)pqh, (__nv_bfloat16*)pql,
        (__nv_bfloat16*)pkh, (__nv_bfloat16*)pkl, (float*)pv);

    // --- V transpose + split (bf16) ---
    vsplitT_kernel<<<dim3(KVW / 32, SEQ / 32, BATCH), tb>>>(
        (const float*)pv, (__nv_bfloat16*)pvth, (__nv_bfloat16*)pvtl);

    // --- HMMA flash attention (bf16 3-term, LPT schedule, base-2 softmax) ---
    cudaFuncSetAttribute(attn_hmma, cudaFuncAttributeMaxDynamicSharedMemorySize,
                         ATTN_SMEM);
    attn_hmma<<<dim3(NH, SEQ / 128, BATCH), 256, ATTN_SMEM>>>(
        (const __nv_bfloat16*)pqh, (const __nv_bfloat16*)pql,
        (const __nv_bfloat16*)pkh, (const __nv_bfloat16*)pkl,
        (const __nv_bfloat16*)pvth, (const __nv_bfloat16*)pvtl,
        mask, (__half*)pah);

    // --- output projection (fp16 2-pass) ---
    gemm_o<<<dim3(HID / 128, MTOT / 128), 256, gemm_smem>>>(
        (const __half*)pah, (__half*)pwoh, (__half*)pwol, bo, out);
}

// round 9
// speedup vs baseline: 1.6292x; 1.0928x over previous
#include <cuda_runtime.h>
#include <cuda_bf16.h>
#include <cuda_fp16.h>
#include <cstdint>
#include <math.h>

// ---------------------------------------------------------------------------
// Problem constants
// ---------------------------------------------------------------------------
#define BATCH   2
#define SEQ     2048
#define HID     2048
#define NH      16
#define NKV     4
#define DH      128
#define KVW     (NKV * DH)          // 512
#define MTOT    (BATCH * SEQ)       // 4096
#define GROUPS  (NH / NKV)          // 4
#define GEMM_K  2048
#define NQKV    (HID + 2 * KVW)     // 3072

// ---------------------------------------------------------------------------
// PTX helpers — ONLY non-'a' features (mma.sync / ldmatrix / cp.async).
// ---------------------------------------------------------------------------
__device__ __forceinline__ uint32_t smem_to_u32(const void* p) {
    uint32_t a;
    asm("{ .reg .u64 t; cvta.to.shared.u64 t, %1; cvt.u32.u64 %0, t; }"
        : "=r"(a) : "l"(p));
    return a;
}
#define CP_ASYNC16(dst, src) \
    asm volatile("cp.async.cg.shared.global [%0], [%1], 16;" \
                 :: "r"(dst), "l"(src))
#define CP_ASYNC4(dst, src) \
    asm volatile("cp.async.ca.shared.global [%0], [%1], 4;" \
                 :: "r"(dst), "l"(src))
#define CP_COMMIT() asm volatile("cp.async.commit_group;")
#define CP_WAIT(n)  asm volatile("cp.async.wait_group %0;" :: "n"(n))

__device__ __forceinline__ void ldsm_x4(uint32_t* r, uint32_t addr) {
    asm volatile("ldmatrix.sync.aligned.m8n8.x4.shared.b16 {%0,%1,%2,%3}, [%4];"
                 : "=r"(r[0]), "=r"(r[1]), "=r"(r[2]), "=r"(r[3]) : "r"(addr));
}
__device__ __forceinline__ void mma_f16(float* d, const uint32_t* a,
                                        const uint32_t* b) {
    asm volatile(
        "mma.sync.aligned.m16n8k16.row.col.f32.f16.f16.f32 "
        "{%0,%1,%2,%3}, {%4,%5,%6,%7}, {%8,%9}, {%0,%1,%2,%3};"
        : "+f"(d[0]), "+f"(d[1]), "+f"(d[2]), "+f"(d[3])
        : "r"(a[0]), "r"(a[1]), "r"(a[2]), "r"(a[3]), "r"(b[0]), "r"(b[1]));
}
// fp16 hi/lo split pack
__device__ __forceinline__ void split2h(float x, float y, uint32_t& hi, uint32_t& lo) {
    __half hx = __float2half(x), hy = __float2half(y);
    __half2 h(hx, hy);
    hi = *reinterpret_cast<uint32_t*>(&h);
    __half2 l(__float2half(x - __half2float(hx)),
              __float2half(y - __half2float(hy)));
    lo = *reinterpret_cast<uint32_t*>(&l);
}
__device__ __forceinline__ uint32_t packh2(float x, float y) {
    __half2 h(__float2half(x), __float2half(y));
    return *reinterpret_cast<uint32_t*>(&h);
}
__device__ __forceinline__ float ex2(float x) {
    float r;
    asm("ex2.approx.f32 %0, %1;" : "=f"(r) : "f"(x));
    return r;
}

// ---------------------------------------------------------------------------
// Scratch buffers
// ---------------------------------------------------------------------------
__device__ float g_v[(size_t)MTOT * KVW];
__device__ __half g_xh[(size_t)MTOT * HID];           // x as single fp16
__device__ __half g_qs[(size_t)MTOT * HID];           // q single fp16 (pre-scaled)
__device__ __half g_kh[(size_t)MTOT * KVW];           // k fp16 hi
__device__ __half g_kl[(size_t)MTOT * KVW];           // k fp16 lo
__device__ __half g_vth[(size_t)MTOT * KVW];          // VT fp16 hi [B*KVW, SEQ]
__device__ __half g_vtl[(size_t)MTOT * KVW];
__device__ __half g_ah[(size_t)MTOT * HID];           // attn out fp16
__device__ __half g_wh[(size_t)NQKV * HID];           // [Wq;Wk;Wv] T, fp16 hi
__device__ __half g_wl[(size_t)NQKV * HID];
__device__ __half g_woh[(size_t)HID * HID];
__device__ __half g_wol[(size_t)HID * HID];

// ---------------------------------------------------------------------------
// Converters
// ---------------------------------------------------------------------------
__global__ void xcvt_kernel(const float* __restrict__ in,
                            __half* __restrict__ hi, int n4)
{
    int i = blockIdx.x * blockDim.x + threadIdx.x;
    if (i >= n4) return;
    float4 v = ((const float4*)in)[i];
    __half2 a(__float2half(v.x), __float2half(v.y));
    __half2 b(__float2half(v.z), __float2half(v.w));
    ((__half2*)hi)[2*i]   = a;
    ((__half2*)hi)[2*i+1] = b;
}

// All four weight matrices transposed + fp16 hi/lo split in ONE launch.
__global__ void wconvT_kernel(const float* __restrict__ Wq,
                              const float* __restrict__ Wk,
                              const float* __restrict__ Wv,
                              const float* __restrict__ Wo,
                              __half* __restrict__ wh,
                              __half* __restrict__ wl,
                              __half* __restrict__ woh,
                              __half* __restrict__ wol)
{
    const int bx = blockIdx.x;
    const float* W;
    __half *Th, *Tl;
    int N, nblk;
    if (bx < 64)      { W = Wq; Th = wh;  Tl = wl;  N = HID; nblk = bx; }
    else if (bx < 80) { W = Wk; Th = wh + (size_t)HID * GEMM_K;
                        Tl = wl + (size_t)HID * GEMM_K; N = KVW; nblk = bx - 64; }
    else if (bx < 96) { W = Wv; Th = wh + (size_t)(HID + KVW) * GEMM_K;
                        Tl = wl + (size_t)(HID + KVW) * GEMM_K; N = KVW; nblk = bx - 80; }
    else              { W = Wo; Th = woh; Tl = wol; N = HID; nblk = bx - 96; }

    __shared__ float t[32][33];
    const int n  = nblk * 32 + threadIdx.x;
    const int kb = blockIdx.y * 32;
    #pragma unroll
    for (int j = 0; j < 32; j += 8)
        t[threadIdx.y + j][threadIdx.x] = W[(size_t)(kb + threadIdx.y + j) * N + n];
    __syncthreads();
    const int k  = kb + threadIdx.x;
    const int nb = nblk * 32;
    #pragma unroll
    for (int j = 0; j < 32; j += 8) {
        float v = t[threadIdx.x][threadIdx.y + j];
        __half h = __float2half(v);
        size_t o = (size_t)(nb + threadIdx.y + j) * GEMM_K + k;
        Th[o] = h;
        Tl[o] = __float2half(v - __half2float(h));
    }
}

// V [B*SEQ, KVW] fp32 -> VT [B*KVW, SEQ] fp16 hi/lo
__global__ void vsplitT_kernel(const float* __restrict__ V,
                               __half* __restrict__ Th,
                               __half* __restrict__ Tl)
{
    __shared__ float t[32][33];
    const int n0 = blockIdx.x * 32;
    const int s0 = blockIdx.y * 32;
    const int b  = blockIdx.z;
    #pragma unroll
    for (int j = 0; j < 32; j += 8)
        t[threadIdx.y + j][threadIdx.x] =
            V[(size_t)(b * SEQ + s0 + threadIdx.y + j) * KVW + n0 + threadIdx.x];
    __syncthreads();
    #pragma unroll
    for (int j = 0; j < 32; j += 8) {
        float v = t[threadIdx.x][threadIdx.y + j];
        __half h = __float2half(v);
        size_t o = (size_t)(b * KVW + n0 + threadIdx.y + j) * SEQ + s0 + threadIdx.x;
        Th[o] = h;
        Tl[o] = __float2half(v - __half2float(h));
    }
}

// ---------------------------------------------------------------------------
// fp16 HMMA GEMM mainloop: C = Ah[M,K] @ (Bh+Bl)^T[N,K]
// ---------------------------------------------------------------------------
#define KC        32
#define AS_STRIDE 40
#define MAT_B     (128 * AS_STRIDE * 2)
#define STAGE_B   (3 * MAT_B)          // 30720 bytes
#define NCHUNK    (GEMM_K / KC)

#define GEMM_MAINLOOP_F16(AhP, BhP, BlP)                                        \
    float acc[4][4][4];                                                         \
    _Pragma("unroll")                                                           \
    for (int a = 0; a < 4; ++a)                                                 \
        _Pragma("unroll")                                                       \
        for (int b2 = 0; b2 < 4; ++b2)                                          \
            _Pragma("unroll")                                                   \
            for (int c = 0; c < 4; ++c) acc[a][b2][c] = 0.f;                    \
    const __half* mats[3] = {AhP, BhP, BlP};                                    \
    auto load_stage = [&](int s, int k0) {                                      \
        const uint32_t st = smem_base + s * STAGE_B;                            \
        _Pragma("unroll")                                                       \
        for (int mat = 0; mat < 3; ++mat) {                                     \
            const __half* src = mats[mat];                                      \
            const int r0 = (mat < 1) ? m0 : n0;                                 \
            const uint32_t dstb = st + mat * MAT_B;                             \
            _Pragma("unroll")                                                   \
            for (int it = 0; it < 2; ++it) {                                    \
                const int idx = it * 256 + tid;                                 \
                const int row = idx >> 2;                                       \
                const int k4  = idx & 3;                                        \
                const void* sp = src + (size_t)(r0 + row) * GEMM_K + k0 + k4*8; \
                const uint32_t dp = dstb + row * (AS_STRIDE * 2) + k4 * 16;     \
                CP_ASYNC16(dp, sp);                                             \
            }                                                                   \
        }                                                                       \
    };                                                                          \
    load_stage(0, 0);                                                           \
    CP_COMMIT();                                                                \
    for (int c = 0; c < NCHUNK; ++c) {                                          \
        if (c + 1 < NCHUNK) {                                                   \
            load_stage((c + 1) & 1, (c + 1) * KC);                              \
            CP_COMMIT();                                                        \
            CP_WAIT(1);                                                         \
        } else {                                                                \
            CP_WAIT(0);                                                         \
        }                                                                       \
        __syncthreads();                                                        \
        const uint32_t stg = smem_base + (c & 1) * STAGE_B;                     \
        const uint32_t pA  = stg;                                               \
        const uint32_t pBh = stg + MAT_B;                                       \
        const uint32_t pBl = stg + 2 * MAT_B;                                   \
        _Pragma("unroll")                                                       \
        for (int ks = 0; ks < 2; ++ks) {                                        \
            const int kcol = ks * 16;                                           \
            uint32_t bh[8], bl[8];                                              \
            _Pragma("unroll")                                                   \
            for (int p = 0; p < 2; ++p) {                                       \
                const int nrow = wn * 32 + p * 16 + (lane & 7) + ((lane>>4)<<3);\
                const int kk   = kcol + (((lane >> 3) & 1) << 3);               \
                const uint32_t off = (nrow * AS_STRIDE + kk) * 2;               \
                ldsm_x4(&bh[p * 4], pBh + off);                                 \
                ldsm_x4(&bl[p * 4], pBl + off);                                 \
            }                                                                   \
            _Pragma("unroll")                                                   \
            for (int mt = 0; mt < 4; ++mt) {                                    \
                const int mrow = wm * 64 + mt * 16 + (lane & 15);               \
                const int kk2  = kcol + ((lane >> 4) << 3);                     \
                const uint32_t offa = (mrow * AS_STRIDE + kk2) * 2;             \
                uint32_t afr[4];                                                \
                ldsm_x4(afr, pA + offa);                                        \
                _Pragma("unroll")                                               \
                for (int nt = 0; nt < 4; ++nt) mma_f16(acc[mt][nt], afr, &bh[nt*2]); \
                _Pragma("unroll")                                               \
                for (int nt = 0; nt < 4; ++nt) mma_f16(acc[mt][nt], afr, &bl[nt*2]); \
            }                                                                   \
        }                                                                       \
        __syncthreads();                                                        \
    }

// ---------------------------------------------------------------------------
// Fused QKV projection: q -> single fp16 (pre-scaled by scl*log2e),
// k -> fp16 hi/lo, v -> fp32.
// ---------------------------------------------------------------------------
#define ATT_SCL (0.08838834764831845f * 1.4426950408889634f)

__global__ void __launch_bounds__(256)
gemm_qkv(const __half* __restrict__ Ah,
         const __half* __restrict__ Bh, const __half* __restrict__ Bl,
         const float* __restrict__ bq, const float* __restrict__ bk,
         const float* __restrict__ bv,
         __half* __restrict__ Qs,
         __half* __restrict__ Kh, __half* __restrict__ Kl,
         float* __restrict__ Vo)
{
    extern __shared__ __align__(128) char smem[];
    const uint32_t smem_base = smem_to_u32(smem);
    const int tid  = threadIdx.x;
    const int warp = tid >> 5;
    const int lane = tid & 31;
    const int wm   = warp >> 2;
    const int wn   = warp & 3;
    const int m0   = blockIdx.y * 128;
    const int n0   = blockIdx.x * 128;

    GEMM_MAINLOOP_F16(Ah, Bh, Bl)

    #pragma unroll
    for (int mt = 0; mt < 4; ++mt)
        #pragma unroll
        for (int rh = 0; rh < 2; ++rh) {
            const int row = m0 + wm * 64 + mt * 16 + (lane >> 2) + rh * 8;
            #pragma unroll
            for (int nt = 0; nt < 4; ++nt) {
                const int col = n0 + wn * 32 + nt * 8 + (lane & 3) * 2;
                if (n0 < HID) {
                    const float v0 = (acc[mt][nt][rh*2+0] + bq[col])   * ATT_SCL;
                    const float v1 = (acc[mt][nt][rh*2+1] + bq[col+1]) * ATT_SCL;
                    *(uint32_t*)&Qs[(size_t)row * HID + col] = packh2(v0, v1);
                } else if (n0 < HID + KVW) {
                    const int c2 = col - HID;
                    const float v0 = acc[mt][nt][rh*2+0] + bk[c2];
                    const float v1 = acc[mt][nt][rh*2+1] + bk[c2+1];
                    uint32_t hi, lo;
                    split2h(v0, v1, hi, lo);
                    *(uint32_t*)&Kh[(size_t)row * KVW + c2] = hi;
                    *(uint32_t*)&Kl[(size_t)row * KVW + c2] = lo;
                } else {
                    const int c2 = col - HID - KVW;
                    float2 v;
                    v.x = acc[mt][nt][rh*2+0] + bv[c2];
                    v.y = acc[mt][nt][rh*2+1] + bv[c2+1];
                    *(float2*)&Vo[(size_t)row * KVW + c2] = v;
                }
            }
        }
}

// ---------------------------------------------------------------------------
// O-projection GEMM (fp16 A single, fp16 W hi/lo, fp32 out)
// ---------------------------------------------------------------------------
__global__ void __launch_bounds__(256)
gemm_o(const __half* __restrict__ Ah,
       const __half* __restrict__ Bh, const __half* __restrict__ Bl,
       const float* __restrict__ bias, float* __restrict__ C)
{
    extern __shared__ __align__(128) char smem[];
    const uint32_t smem_base = smem_to_u32(smem);
    const int tid  = threadIdx.x;
    const int warp = tid >> 5;
    const int lane = tid & 31;
    const int wm   = warp >> 2;
    const int wn   = warp & 3;
    const int m0   = blockIdx.y * 128;
    const int n0   = blockIdx.x * 128;

    GEMM_MAINLOOP_F16(Ah, Bh, Bl)

    #pragma unroll
    for (int mt = 0; mt < 4; ++mt)
        #pragma unroll
        for (int rh = 0; rh < 2; ++rh) {
            const int row = m0 + wm * 64 + mt * 16 + (lane >> 2) + rh * 8;
            #pragma unroll
            for (int nt = 0; nt < 4; ++nt) {
                const int col = n0 + wn * 32 + nt * 8 + (lane & 3) * 2;
                float2 v;
                v.x = acc[mt][nt][rh*2+0] + bias[col];
                v.y = acc[mt][nt][rh*2+1] + bias[col+1];
                *(float2*)&C[(size_t)row * HID + col] = v;
            }
        }
}

// ---------------------------------------------------------------------------
// fp16 HMMA FlashAttention: 128 q-rows x 64 kv tiles, 8 warps.
// QK = Q(single) x (Kh+Kl): 2 passes.  PV = P(single) x (Vh+Vl): 2 passes.
// Grid (NH, SEQ/128, BATCH), qb reversed on slow axis => LPT.
// ---------------------------------------------------------------------------
#define QSTR 136
#define VSTR 72
#define SM_Q  0
#define SM_KH 34816
#define SM_KL 52224
#define SM_VH 69632
#define SM_VL 88064
#define SM_MK 106496
#define ATTN_SMEM 106752

__global__ void __launch_bounds__(256)
attn_hmma(const __half* __restrict__ Qs,
          const __half* __restrict__ Kh, const __half* __restrict__ Kl,
          const __half* __restrict__ VTh, const __half* __restrict__ VTl,
          const int* __restrict__ mask,
          __half* __restrict__ OH)
{
    extern __shared__ __align__(128) char sm[];
    const uint32_t base = smem_to_u32(sm);
    const int tid = threadIdx.x;
    const int w    = tid >> 5;
    const int lane = tid & 31;
    const int h  = blockIdx.x;
    const int qb = (int)gridDim.y - 1 - (int)blockIdx.y;   // heavy-first (LPT)
    const int b  = blockIdx.z;
    const int q0 = qb * 128;
    const int kvh = h >> 2;
    const int T = 2 * qb + 2;

    auto load_k = [&](int k0) {
        #pragma unroll
        for (int mat = 0; mat < 2; ++mat) {
            const __half* src = mat ? Kl : Kh;
            const uint32_t dst = base + (mat ? SM_KL : SM_KH);
            #pragma unroll
            for (int i = 0; i < 4; ++i) {
                const int idx = i * 256 + tid;
                const int row = idx >> 4, c = idx & 15;
                CP_ASYNC16(dst + row * 272 + c * 16,
                           src + (size_t)(b * SEQ + k0 + row) * KVW + kvh * DH + c * 8);
            }
        }
        if (tid < 64)
            CP_ASYNC4(base + SM_MK + tid * 4, mask + b * SEQ + k0 + tid);
    };
    auto load_v = [&](int k0) {
        #pragma unroll
        for (int mat = 0; mat < 2; ++mat) {
            const __half* src = mat ? VTl : VTh;
            const uint32_t dst = base + (mat ? SM_VL : SM_VH);
            #pragma unroll
            for (int i = 0; i < 4; ++i) {
                const int idx = i * 256 + tid;
                const int row = idx >> 3, c = idx & 7;
                CP_ASYNC16(dst + row * 144 + c * 16,
                           src + (size_t)(b * KVW + kvh * DH + row) * SEQ + k0 + c * 8);
            }
        }
    };

    // prologue: Q + K(0) + mask(0)
    #pragma unroll
    for (int i = 0; i < 8; ++i) {
        const int idx = i * 256 + tid;
        const int row = idx >> 4, c = idx & 15;
        CP_ASYNC16(base + SM_Q + row * 272 + c * 16,
                   Qs + (size_t)(b * SEQ + q0 + row) * HID + h * DH + c * 8);
    }
    load_k(0);
    CP_COMMIT();
    CP_WAIT(0);
    __syncthreads();

    float s[8][4];
    float o[16][4];
    #pragma unroll
    for (int j = 0; j < 16; ++j)
        #pragma unroll
        for (int c = 0; c < 4; ++c) o[j][c] = 0.f;
    float m0 = -1e30f, m1 = -1e30f, l0 = 0.f, l1 = 0.f;

    const int r0g = q0 + w * 16 + (lane >> 2);
    const int r1g = r0g + 8;
    const int c0l = (lane & 3) * 2;
    const int* mk_s = (const int*)(sm + SM_MK);

    for (int t = 0; t < T; ++t) {
        const int k0 = t * 64;
        const bool active = (q0 + w * 16 + 15) >= k0;

        load_v(k0);
        CP_COMMIT();

        if (active) {
            #pragma unroll
            for (int j = 0; j < 8; ++j)
                #pragma unroll
                for (int c = 0; c < 4; ++c) s[j][c] = 0.f;

            // S = Q*(Kh + Kl)  (Q pre-scaled by scl*log2e)
            #pragma unroll
            for (int kc = 0; kc < 8; ++kc) {
                const uint32_t offa =
                    ((w * 16 + (lane & 15)) * QSTR + kc * 16 + ((lane >> 4) << 3)) * 2;
                uint32_t aq[4];
                ldsm_x4(aq, base + SM_Q + offa);
                #pragma unroll
                for (int g = 0; g < 4; ++g) {
                    const uint32_t offb =
                        ((g * 16 + (lane & 7) + ((lane >> 4) << 3)) * QSTR +
                         kc * 16 + (((lane >> 3) & 1) << 3)) * 2;
                    uint32_t bh[4], bl[4];
                    ldsm_x4(bh, base + SM_KH + offb);
                    ldsm_x4(bl, base + SM_KL + offb);
                    mma_f16(s[2*g],   aq, &bh[0]);
                    mma_f16(s[2*g+1], aq, &bh[2]);
                    mma_f16(s[2*g],   aq, &bl[0]);
                    mma_f16(s[2*g+1], aq, &bl[2]);
                }
            }

            // mask + online softmax (registers, base-2 domain)
            float mx0 = -1e30f, mx1 = -1e30f;
            #pragma unroll
            for (int j = 0; j < 8; ++j) {
                const int cg = k0 + j * 8 + c0l;
                const int mk0 = mk_s[j * 8 + c0l];
                const int mk1 = mk_s[j * 8 + c0l + 1];
                s[j][0] = (cg     <= r0g && mk0) ? s[j][0] : -1e30f;
                s[j][1] = (cg + 1 <= r0g && mk1) ? s[j][1] : -1e30f;
                s[j][2] = (cg     <= r1g && mk0) ? s[j][2] : -1e30f;
                s[j][3] = (cg + 1 <= r1g && mk1) ? s[j][3] : -1e30f;
                mx0 = fmaxf(mx0, fmaxf(s[j][0], s[j][1]));
                mx1 = fmaxf(mx1, fmaxf(s[j][2], s[j][3]));
            }
            mx0 = fmaxf(mx0, __shfl_xor_sync(0xffffffff, mx0, 1));
            mx0 = fmaxf(mx0, __shfl_xor_sync(0xffffffff, mx0, 2));
            mx1 = fmaxf(mx1, __shfl_xor_sync(0xffffffff, mx1, 1));
            mx1 = fmaxf(mx1, __shfl_xor_sync(0xffffffff, mx1, 2));
            const float mn0 = fmaxf(m0, mx0), mn1 = fmaxf(m1, mx1);
            const float f0 = ex2(m0 - mn0), f1 = ex2(m1 - mn1);
            m0 = mn0; m1 = mn1;
            float sum0 = 0.f, sum1 = 0.f;
            #pragma unroll
            for (int j = 0; j < 8; ++j) {
                s[j][0] = ex2(s[j][0] - mn0);
                s[j][1] = ex2(s[j][1] - mn0);
                s[j][2] = ex2(s[j][2] - mn1);
                s[j][3] = ex2(s[j][3] - mn1);
                sum0 += s[j][0] + s[j][1];
                sum1 += s[j][2] + s[j][3];
            }
            sum0 += __shfl_xor_sync(0xffffffff, sum0, 1);
            sum0 += __shfl_xor_sync(0xffffffff, sum0, 2);
            sum1 += __shfl_xor_sync(0xffffffff, sum1, 1);
            sum1 += __shfl_xor_sync(0xffffffff, sum1, 2);
            l0 = l0 * f0 + sum0;
            l1 = l1 * f1 + sum1;
            #pragma unroll
            for (int j = 0; j < 16; ++j) {
                o[j][0] *= f0; o[j][1] *= f0;
                o[j][2] *= f1; o[j][3] *= f1;
            }
        }

        CP_WAIT(0);            // VT(t) ready
        __syncthreads();       // all warps done reading K(t)
        if (t + 1 < T) {
            load_k(t * 64 + 64);
            CP_COMMIT();
        }

        if (active) {
            // O += P*(Vh + Vl)   (P single fp16)
            #pragma unroll
            for (int kc = 0; kc < 4; ++kc) {
                uint32_t ap[4];
                ap[0] = packh2(s[2*kc][0],   s[2*kc][1]);
                ap[1] = packh2(s[2*kc][2],   s[2*kc][3]);
                ap[2] = packh2(s[2*kc+1][0], s[2*kc+1][1]);
                ap[3] = packh2(s[2*kc+1][2], s[2*kc+1][3]);
                #pragma unroll
                for (int g = 0; g < 8; ++g) {
                    const uint32_t offb =
                        ((g * 16 + (lane & 7) + ((lane >> 4) << 3)) * VSTR +
                         kc * 16 + (((lane >> 3) & 1) << 3)) * 2;
                    uint32_t bh[4], bl[4];
                    ldsm_x4(bh, base + SM_VH + offb);
                    ldsm_x4(bl, base + SM_VL + offb);
                    mma_f16(o[2*g],   ap, &bh[0]);
                    mma_f16(o[2*g+1], ap, &bh[2]);
                    mma_f16(o[2*g],   ap, &bl[0]);
                    mma_f16(o[2*g+1], ap, &bl[2]);
                }
            }
        }

        CP_WAIT(0);            // K(t+1) ready
        __syncthreads();       // all warps done reading VT(t)
    }

    // epilogue: normalize, store single fp16
    const float inv0 = 1.f / l0, inv1 = 1.f / l1;
    const size_t base0 = (size_t)(b * SEQ + r0g) * HID + h * DH;
    const size_t base1 = (size_t)(b * SEQ + r1g) * HID + h * DH;
    #pragma unroll
    for (int j = 0; j < 16; ++j) {
        const int col = j * 8 + c0l;
        *(uint32_t*)&OH[base0 + col] = packh2(o[j][0] * inv0, o[j][1] * inv0);
        *(uint32_t*)&OH[base1 + col] = packh2(o[j][2] * inv1, o[j][3] * inv1);
    }
}

// ---------------------------------------------------------------------------
// Launch
// ---------------------------------------------------------------------------
extern "C" void kernel_launch(void* const* d_in, const int* in_sizes, int n_in,
                              void* d_out, int out_size)
{
    const float* x    = (const float*)d_in[0];
    const int*   mask = (const int*)  d_in[1];
    const float* Wq   = (const float*)d_in[2];
    const float* bq   = (const float*)d_in[3];
    const float* Wk   = (const float*)d_in[4];
    const float* bk   = (const float*)d_in[5];
    const float* Wv   = (const float*)d_in[6];
    const float* bv   = (const float*)d_in[7];
    const float* Wo   = (const float*)d_in[8];
    const float* bo   = (const float*)d_in[9];
    float* out = (float*)d_out;

    void *pv, *pxh, *pqs, *pkh, *pkl, *pvth, *pvtl, *pah;
    void *pwh, *pwl, *pwoh, *pwol;
    cudaGetSymbolAddress(&pv,  g_v);
    cudaGetSymbolAddress(&pxh, g_xh);
    cudaGetSymbolAddress(&pqs, g_qs);
    cudaGetSymbolAddress(&pkh, g_kh);  cudaGetSymbolAddress(&pkl, g_kl);
    cudaGetSymbolAddress(&pvth, g_vth); cudaGetSymbolAddress(&pvtl, g_vtl);
    cudaGetSymbolAddress(&pah, g_ah);
    cudaGetSymbolAddress(&pwh, g_wh);  cudaGetSymbolAddress(&pwl, g_wl);
    cudaGetSymbolAddress(&pwoh, g_woh); cudaGetSymbolAddress(&pwol, g_wol);

    __half* wh = (__half*)pwh;
    __half* wl = (__half*)pwl;

    // --- converters ---
    const int n4 = MTOT * HID / 4;
    xcvt_kernel<<<n4 / 256, 256>>>(x, (__half*)pxh, n4);
    dim3 tb(32, 8);
    wconvT_kernel<<<dim3(160, GEMM_K / 32), tb>>>(
        Wq, Wk, Wv, Wo, wh, wl, (__half*)pwoh, (__half*)pwol);

    // --- fused QKV projection (fp16 2-pass) ---
    const int gemm_smem = 2 * STAGE_B;   // 61440
    cudaFuncSetAttribute(gemm_qkv, cudaFuncAttributeMaxDynamicSharedMemorySize,
                         gemm_smem);
    cudaFuncSetAttribute(gemm_o, cudaFuncAttributeMaxDynamicSharedMemorySize,
                         gemm_smem);
    gemm_qkv<<<dim3(NQKV / 128, MTOT / 128), 256, gemm_smem>>>(
        (const __half*)pxh, wh, wl, bq, bk, bv,
        (__half*)pqs, (__half*)pkh, (__half*)pkl, (float*)pv);

    // --- V transpose + fp16 split ---
    vsplitT_kernel<<<dim3(KVW / 32, SEQ / 32, BATCH), tb>>>(
        (const float*)pv, (__half*)pvth, (__half*)pvtl);

    // --- fp16 flash attention (2-pass QK, 2-pass PV, LPT schedule) ---
    cudaFuncSetAttribute(attn_hmma, cudaFuncAttributeMaxDynamicSharedMemorySize,
                         ATTN_SMEM);
    attn_hmma<<<dim3(NH, SEQ / 128, BATCH), 256, ATTN_SMEM>>>(
        (const __half*)pqs, (const __half*)pkh, (const __half*)pkl,
        (const __half*)pvth, (const __half*)pvtl,
        mask, (__half*)pah);

    // --- output projection (fp16 2-pass) ---
    gemm_o<<<dim3(HID / 128, MTOT / 128), 256, gemm_smem>>>(
        (const __half*)pah, (__half*)pwoh, (__half*)pwol, bo, out);
}

// round 10
// speedup vs baseline: 1.6382x; 1.0055x over previous
#include <cuda_runtime.h>
#include <cuda_bf16.h>
#include <cuda_fp16.h>
#include <cstdint>
#include <math.h>

// ---------------------------------------------------------------------------
// Problem constants
// ---------------------------------------------------------------------------
#define BATCH   2
#define SEQ     2048
#define HID     2048
#define NH      16
#define NKV     4
#define DH      128
#define KVW     (NKV * DH)          // 512
#define MTOT    (BATCH * SEQ)       // 4096
#define GROUPS  (NH / NKV)          // 4
#define GEMM_K  2048
#define NQKV    (HID + 2 * KVW)     // 3072

// ---------------------------------------------------------------------------
// PTX helpers — ONLY non-'a' features (mma.sync / ldmatrix / cp.async).
// ---------------------------------------------------------------------------
__device__ __forceinline__ uint32_t smem_to_u32(const void* p) {
    uint32_t a;
    asm("{ .reg .u64 t; cvta.to.shared.u64 t, %1; cvt.u32.u64 %0, t; }"
        : "=r"(a) : "l"(p));
    return a;
}
#define CP_ASYNC16(dst, src) \
    asm volatile("cp.async.cg.shared.global [%0], [%1], 16;" \
                 :: "r"(dst), "l"(src))
#define CP_ASYNC4(dst, src) \
    asm volatile("cp.async.ca.shared.global [%0], [%1], 4;" \
                 :: "r"(dst), "l"(src))
#define CP_COMMIT() asm volatile("cp.async.commit_group;")
#define CP_WAIT(n)  asm volatile("cp.async.wait_group %0;" :: "n"(n))

__device__ __forceinline__ void ldsm_x4(uint32_t* r, uint32_t addr) {
    asm volatile("ldmatrix.sync.aligned.m8n8.x4.shared.b16 {%0,%1,%2,%3}, [%4];"
                 : "=r"(r[0]), "=r"(r[1]), "=r"(r[2]), "=r"(r[3]) : "r"(addr));
}
__device__ __forceinline__ void mma_f16(float* d, const uint32_t* a,
                                        const uint32_t* b) {
    asm volatile(
        "mma.sync.aligned.m16n8k16.row.col.f32.f16.f16.f32 "
        "{%0,%1,%2,%3}, {%4,%5,%6,%7}, {%8,%9}, {%0,%1,%2,%3};"
        : "+f"(d[0]), "+f"(d[1]), "+f"(d[2]), "+f"(d[3])
        : "r"(a[0]), "r"(a[1]), "r"(a[2]), "r"(a[3]), "r"(b[0]), "r"(b[1]));
}
__device__ __forceinline__ void split2h(float x, float y, uint32_t& hi, uint32_t& lo) {
    __half hx = __float2half(x), hy = __float2half(y);
    __half2 h(hx, hy);
    hi = *reinterpret_cast<uint32_t*>(&h);
    __half2 l(__float2half(x - __half2float(hx)),
              __float2half(y - __half2float(hy)));
    lo = *reinterpret_cast<uint32_t*>(&l);
}
__device__ __forceinline__ uint32_t packh2(float x, float y) {
    __half2 h(__float2half(x), __float2half(y));
    return *reinterpret_cast<uint32_t*>(&h);
}
__device__ __forceinline__ float ex2(float x) {
    float r;
    asm("ex2.approx.f32 %0, %1;" : "=f"(r) : "f"(x));
    return r;
}

// ---------------------------------------------------------------------------
// Scratch buffers
// ---------------------------------------------------------------------------
__device__ float g_v[(size_t)MTOT * KVW];
__device__ __half g_xh[(size_t)MTOT * HID];           // x single fp16
__device__ __half g_qs[(size_t)MTOT * HID];           // q single fp16 (pre-scaled)
__device__ __half g_kh[(size_t)MTOT * KVW];           // k single fp16
__device__ __half g_vth[(size_t)MTOT * KVW];          // VT single fp16 [B*KVW, SEQ]
__device__ __half g_ah[(size_t)MTOT * HID];           // attn out fp16
__device__ __half g_wh[(size_t)NQKV * HID];           // [Wq;Wk;Wv] T, fp16 hi
__device__ __half g_wl[(size_t)NQKV * HID];
__device__ __half g_woh[(size_t)HID * HID];
__device__ __half g_wol[(size_t)HID * HID];

// ---------------------------------------------------------------------------
// Converters
// ---------------------------------------------------------------------------
__global__ void xcvt_kernel(const float* __restrict__ in,
                            __half* __restrict__ hi, int n4)
{
    int i = blockIdx.x * blockDim.x + threadIdx.x;
    if (i >= n4) return;
    float4 v = ((const float4*)in)[i];
    __half2 a(__float2half(v.x), __float2half(v.y));
    __half2 b(__float2half(v.z), __float2half(v.w));
    ((__half2*)hi)[2*i]   = a;
    ((__half2*)hi)[2*i+1] = b;
}

// All four weight matrices transposed + fp16 hi/lo split in ONE launch.
__global__ void wconvT_kernel(const float* __restrict__ Wq,
                              const float* __restrict__ Wk,
                              const float* __restrict__ Wv,
                              const float* __restrict__ Wo,
                              __half* __restrict__ wh,
                              __half* __restrict__ wl,
                              __half* __restrict__ woh,
                              __half* __restrict__ wol)
{
    const int bx = blockIdx.x;
    const float* W;
    __half *Th, *Tl;
    int N, nblk;
    if (bx < 64)      { W = Wq; Th = wh;  Tl = wl;  N = HID; nblk = bx; }
    else if (bx < 80) { W = Wk; Th = wh + (size_t)HID * GEMM_K;
                        Tl = wl + (size_t)HID * GEMM_K; N = KVW; nblk = bx - 64; }
    else if (bx < 96) { W = Wv; Th = wh + (size_t)(HID + KVW) * GEMM_K;
                        Tl = wl + (size_t)(HID + KVW) * GEMM_K; N = KVW; nblk = bx - 80; }
    else              { W = Wo; Th = woh; Tl = wol; N = HID; nblk = bx - 96; }

    __shared__ float t[32][33];
    const int n  = nblk * 32 + threadIdx.x;
    const int kb = blockIdx.y * 32;
    #pragma unroll
    for (int j = 0; j < 32; j += 8)
        t[threadIdx.y + j][threadIdx.x] = W[(size_t)(kb + threadIdx.y + j) * N + n];
    __syncthreads();
    const int k  = kb + threadIdx.x;
    const int nb = nblk * 32;
    #pragma unroll
    for (int j = 0; j < 32; j += 8) {
        float v = t[threadIdx.x][threadIdx.y + j];
        __half h = __float2half(v);
        size_t o = (size_t)(nb + threadIdx.y + j) * GEMM_K + k;
        Th[o] = h;
        Tl[o] = __float2half(v - __half2float(h));
    }
}

// V [B*SEQ, KVW] fp32 -> VT [B*KVW, SEQ] single fp16
__global__ void vsplitT_kernel(const float* __restrict__ V,
                               __half* __restrict__ Th)
{
    __shared__ float t[32][33];
    const int n0 = blockIdx.x * 32;
    const int s0 = blockIdx.y * 32;
    const int b  = blockIdx.z;
    #pragma unroll
    for (int j = 0; j < 32; j += 8)
        t[threadIdx.y + j][threadIdx.x] =
            V[(size_t)(b * SEQ + s0 + threadIdx.y + j) * KVW + n0 + threadIdx.x];
    __syncthreads();
    #pragma unroll
    for (int j = 0; j < 32; j += 8) {
        float v = t[threadIdx.x][threadIdx.y + j];
        size_t o = (size_t)(b * KVW + n0 + threadIdx.y + j) * SEQ + s0 + threadIdx.x;
        Th[o] = __float2half(v);
    }
}

// ---------------------------------------------------------------------------
// fp16 HMMA GEMM mainloop: C = Ah[M,K] @ (Bh+Bl)^T[N,K]
// 3-stage pipeline, ONE sync per chunk (wait -> sync -> issue -> compute).
// ---------------------------------------------------------------------------
#define KC        32
#define AS_STRIDE 40
#define MAT_B     (128 * AS_STRIDE * 2)
#define STAGE_B   (3 * MAT_B)          // 30720 bytes
#define NCHUNK    (GEMM_K / KC)

#define GEMM_MAINLOOP_F16(AhP, BhP, BlP)                                        \
    float acc[4][4][4];                                                         \
    _Pragma("unroll")                                                           \
    for (int a = 0; a < 4; ++a)                                                 \
        _Pragma("unroll")                                                       \
        for (int b2 = 0; b2 < 4; ++b2)                                          \
            _Pragma("unroll")                                                   \
            for (int c = 0; c < 4; ++c) acc[a][b2][c] = 0.f;                    \
    const __half* mats[3] = {AhP, BhP, BlP};                                    \
    auto load_stage = [&](int s, int k0) {                                      \
        const uint32_t st = smem_base + s * STAGE_B;                            \
        _Pragma("unroll")                                                       \
        for (int mat = 0; mat < 3; ++mat) {                                     \
            const __half* src = mats[mat];                                      \
            const int r0 = (mat < 1) ? m0 : n0;                                 \
            const uint32_t dstb = st + mat * MAT_B;                             \
            _Pragma("unroll")                                                   \
            for (int it = 0; it < 2; ++it) {                                    \
                const int idx = it * 256 + tid;                                 \
                const int row = idx >> 2;                                       \
                const int k4  = idx & 3;                                        \
                const void* sp = src + (size_t)(r0 + row) * GEMM_K + k0 + k4*8; \
                const uint32_t dp = dstb + row * (AS_STRIDE * 2) + k4 * 16;     \
                CP_ASYNC16(dp, sp);                                             \
            }                                                                   \
        }                                                                       \
    };                                                                          \
    load_stage(0, 0);                                                           \
    CP_COMMIT();                                                                \
    load_stage(1, KC);                                                          \
    CP_COMMIT();                                                                \
    for (int c = 0; c < NCHUNK; ++c) {                                          \
        if (c + 1 < NCHUNK) { CP_WAIT(1); } else { CP_WAIT(0); }                \
        __syncthreads();                                                        \
        if (c + 2 < NCHUNK) {                                                   \
            load_stage((c + 2) % 3, (c + 2) * KC);                              \
            CP_COMMIT();                                                        \
        }                                                                       \
        const uint32_t stg = smem_base + (c % 3) * STAGE_B;                     \
        const uint32_t pA  = stg;                                               \
        const uint32_t pBh = stg + MAT_B;                                       \
        const uint32_t pBl = stg + 2 * MAT_B;                                   \
        _Pragma("unroll")                                                       \
        for (int ks = 0; ks < 2; ++ks) {                                        \
            const int kcol = ks * 16;                                           \
            uint32_t bh[8], bl[8];                                              \
            _Pragma("unroll")                                                   \
            for (int p = 0; p < 2; ++p) {                                       \
                const int nrow = wn * 32 + p * 16 + (lane & 7) + ((lane>>4)<<3);\
                const int kk   = kcol + (((lane >> 3) & 1) << 3);               \
                const uint32_t off = (nrow * AS_STRIDE + kk) * 2;               \
                ldsm_x4(&bh[p * 4], pBh + off);                                 \
                ldsm_x4(&bl[p * 4], pBl + off);                                 \
            }                                                                   \
            _Pragma("unroll")                                                   \
            for (int mt = 0; mt < 4; ++mt) {                                    \
                const int mrow = wm * 64 + mt * 16 + (lane & 15);               \
                const int kk2  = kcol + ((lane >> 4) << 3);                     \
                const uint32_t offa = (mrow * AS_STRIDE + kk2) * 2;             \
                uint32_t afr[4];                                                \
                ldsm_x4(afr, pA + offa);                                        \
                _Pragma("unroll")                                               \
                for (int nt = 0; nt < 4; ++nt) mma_f16(acc[mt][nt], afr, &bh[nt*2]); \
                _Pragma("unroll")                                               \
                for (int nt = 0; nt < 4; ++nt) mma_f16(acc[mt][nt], afr, &bl[nt*2]); \
            }                                                                   \
        }                                                                       \
    }

// ---------------------------------------------------------------------------
// Fused QKV projection: q -> single fp16 (pre-scaled by scl*log2e),
// k -> single fp16, v -> fp32.
// ---------------------------------------------------------------------------
#define ATT_SCL (0.08838834764831845f * 1.4426950408889634f)

__global__ void __launch_bounds__(256)
gemm_qkv(const __half* __restrict__ Ah,
         const __half* __restrict__ Bh, const __half* __restrict__ Bl,
         const float* __restrict__ bq, const float* __restrict__ bk,
         const float* __restrict__ bv,
         __half* __restrict__ Qs, __half* __restrict__ Kh,
         float* __restrict__ Vo)
{
    extern __shared__ __align__(128) char smem[];
    const uint32_t smem_base = smem_to_u32(smem);
    const int tid  = threadIdx.x;
    const int warp = tid >> 5;
    const int lane = tid & 31;
    const int wm   = warp >> 2;
    const int wn   = warp & 3;
    const int m0   = blockIdx.y * 128;
    const int n0   = blockIdx.x * 128;

    GEMM_MAINLOOP_F16(Ah, Bh, Bl)

    #pragma unroll
    for (int mt = 0; mt < 4; ++mt)
        #pragma unroll
        for (int rh = 0; rh < 2; ++rh) {
            const int row = m0 + wm * 64 + mt * 16 + (lane >> 2) + rh * 8;
            #pragma unroll
            for (int nt = 0; nt < 4; ++nt) {
                const int col = n0 + wn * 32 + nt * 8 + (lane & 3) * 2;
                if (n0 < HID) {
                    const float v0 = (acc[mt][nt][rh*2+0] + bq[col])   * ATT_SCL;
                    const float v1 = (acc[mt][nt][rh*2+1] + bq[col+1]) * ATT_SCL;
                    *(uint32_t*)&Qs[(size_t)row * HID + col] = packh2(v0, v1);
                } else if (n0 < HID + KVW) {
                    const int c2 = col - HID;
                    const float v0 = acc[mt][nt][rh*2+0] + bk[c2];
                    const float v1 = acc[mt][nt][rh*2+1] + bk[c2+1];
                    *(uint32_t*)&Kh[(size_t)row * KVW + c2] = packh2(v0, v1);
                } else {
                    const int c2 = col - HID - KVW;
                    float2 v;
                    v.x = acc[mt][nt][rh*2+0] + bv[c2];
                    v.y = acc[mt][nt][rh*2+1] + bv[c2+1];
                    *(float2*)&Vo[(size_t)row * KVW + c2] = v;
                }
            }
        }
}

// ---------------------------------------------------------------------------
// O-projection GEMM (fp16 A single, fp16 W hi/lo, fp32 out)
// ---------------------------------------------------------------------------
__global__ void __launch_bounds__(256)
gemm_o(const __half* __restrict__ Ah,
       const __half* __restrict__ Bh, const __half* __restrict__ Bl,
       const float* __restrict__ bias, float* __restrict__ C)
{
    extern __shared__ __align__(128) char smem[];
    const uint32_t smem_base = smem_to_u32(smem);
    const int tid  = threadIdx.x;
    const int warp = tid >> 5;
    const int lane = tid & 31;
    const int wm   = warp >> 2;
    const int wn   = warp & 3;
    const int m0   = blockIdx.y * 128;
    const int n0   = blockIdx.x * 128;

    GEMM_MAINLOOP_F16(Ah, Bh, Bl)

    #pragma unroll
    for (int mt = 0; mt < 4; ++mt)
        #pragma unroll
        for (int rh = 0; rh < 2; ++rh) {
            const int row = m0 + wm * 64 + mt * 16 + (lane >> 2) + rh * 8;
            #pragma unroll
            for (int nt = 0; nt < 4; ++nt) {
                const int col = n0 + wn * 32 + nt * 8 + (lane & 3) * 2;
                float2 v;
                v.x = acc[mt][nt][rh*2+0] + bias[col];
                v.y = acc[mt][nt][rh*2+1] + bias[col+1];
                *(float2*)&C[(size_t)row * HID + col] = v;
            }
        }
}

// ---------------------------------------------------------------------------
// fp16 FlashAttention: 128 q-rows x 64 kv tiles, 8 warps.
// Single-pass QK (Q,K fp16), single-pass PV (P,V fp16).
// K+V+mask double-buffered as one cp.async group; ONE sync per tile.
// Grid (NH, SEQ/128, BATCH), qb reversed on slow axis => LPT.
// ---------------------------------------------------------------------------
#define QSTR 136
#define VSTR 72
#define SM_Q   0
#define SM_ST  34816                 // stage base (K tile then V tile)
#define STG_B  35840                 // 17408 (K) + 18432 (V)
#define SM_MK  (SM_ST + 2 * STG_B)   // 106496
#define ATTN_SMEM (SM_MK + 512)      // 107008

__global__ void __launch_bounds__(256)
attn_hmma(const __half* __restrict__ Qs, const __half* __restrict__ Kh,
          const __half* __restrict__ VTh, const int* __restrict__ mask,
          __half* __restrict__ OH)
{
    extern __shared__ __align__(128) char sm[];
    const uint32_t base = smem_to_u32(sm);
    const int tid = threadIdx.x;
    const int w    = tid >> 5;
    const int lane = tid & 31;
    const int h  = blockIdx.x;
    const int qb = (int)gridDim.y - 1 - (int)blockIdx.y;   // heavy-first (LPT)
    const int b  = blockIdx.z;
    const int q0 = qb * 128;
    const int kvh = h >> 2;
    const int T = 2 * qb + 2;

    // K(t) + V(t) + mask(t) as ONE group into stage t&1
    auto load_kv = [&](int t) {
        const int k0 = t * 64;
        const int s  = t & 1;
        const uint32_t kdst = base + SM_ST + s * STG_B;
        #pragma unroll
        for (int i = 0; i < 4; ++i) {
            const int idx = i * 256 + tid;
            const int row = idx >> 4, c = idx & 15;
            CP_ASYNC16(kdst + row * 272 + c * 16,
                       Kh + (size_t)(b * SEQ + k0 + row) * KVW + kvh * DH + c * 8);
        }
        const uint32_t vdst = kdst + 17408;
        #pragma unroll
        for (int i = 0; i < 4; ++i) {
            const int idx = i * 256 + tid;
            const int row = idx >> 3, c = idx & 7;
            CP_ASYNC16(vdst + row * 144 + c * 16,
                       VTh + (size_t)(b * KVW + kvh * DH + row) * SEQ + k0 + c * 8);
        }
        if (tid < 64)
            CP_ASYNC4(base + SM_MK + s * 256 + tid * 4, mask + b * SEQ + k0 + tid);
    };

    // prologue: Q + KV(0) in group 0
    #pragma unroll
    for (int i = 0; i < 8; ++i) {
        const int idx = i * 256 + tid;
        const int row = idx >> 4, c = idx & 15;
        CP_ASYNC16(base + SM_Q + row * 272 + c * 16,
                   Qs + (size_t)(b * SEQ + q0 + row) * HID + h * DH + c * 8);
    }
    load_kv(0);
    CP_COMMIT();

    float s[8][4];
    float o[16][4];
    #pragma unroll
    for (int j = 0; j < 16; ++j)
        #pragma unroll
        for (int c = 0; c < 4; ++c) o[j][c] = 0.f;
    float m0 = -1e30f, m1 = -1e30f, l0 = 0.f, l1 = 0.f;

    const int r0g = q0 + w * 16 + (lane >> 2);
    const int r1g = r0g + 8;
    const int c0l = (lane & 3) * 2;

    for (int t = 0; t < T; ++t) {
        const int k0 = t * 64;
        const int st = t & 1;
        const bool active = (q0 + w * 16 + 15) >= k0;

        CP_WAIT(0);            // group t (K,V,mask of tile t) complete
        __syncthreads();       // publish + all warps done with stage (t+1)&1
        if (t + 1 < T) {
            load_kv(t + 1);
            CP_COMMIT();
        }

        if (active) {
            const uint32_t pK = base + SM_ST + st * STG_B;
            const uint32_t pV = pK + 17408;
            const int* mk_s = (const int*)(sm + SM_MK + st * 256);

            #pragma unroll
            for (int j = 0; j < 8; ++j)
                #pragma unroll
                for (int c = 0; c < 4; ++c) s[j][c] = 0.f;

            // S = Q*K (both single fp16; Q pre-scaled by scl*log2e)
            #pragma unroll
            for (int kc = 0; kc < 8; ++kc) {
                const uint32_t offa =
                    ((w * 16 + (lane & 15)) * QSTR + kc * 16 + ((lane >> 4) << 3)) * 2;
                uint32_t aq[4];
                ldsm_x4(aq, base + SM_Q + offa);
                #pragma unroll
                for (int g = 0; g < 4; ++g) {
                    const uint32_t offb =
                        ((g * 16 + (lane & 7) + ((lane >> 4) << 3)) * QSTR +
                         kc * 16 + (((lane >> 3) & 1) << 3)) * 2;
                    uint32_t bh[4];
                    ldsm_x4(bh, pK + offb);
                    mma_f16(s[2*g],   aq, &bh[0]);
                    mma_f16(s[2*g+1], aq, &bh[2]);
                }
            }

            // mask + online softmax (registers, base-2 domain)
            float mx0 = -1e30f, mx1 = -1e30f;
            #pragma unroll
            for (int j = 0; j < 8; ++j) {
                const int cg = k0 + j * 8 + c0l;
                const int mk0 = mk_s[j * 8 + c0l];
                const int mk1 = mk_s[j * 8 + c0l + 1];
                s[j][0] = (cg     <= r0g && mk0) ? s[j][0] : -1e30f;
                s[j][1] = (cg + 1 <= r0g && mk1) ? s[j][1] : -1e30f;
                s[j][2] = (cg     <= r1g && mk0) ? s[j][2] : -1e30f;
                s[j][3] = (cg + 1 <= r1g && mk1) ? s[j][3] : -1e30f;
                mx0 = fmaxf(mx0, fmaxf(s[j][0], s[j][1]));
                mx1 = fmaxf(mx1, fmaxf(s[j][2], s[j][3]));
            }
            mx0 = fmaxf(mx0, __shfl_xor_sync(0xffffffff, mx0, 1));
            mx0 = fmaxf(mx0, __shfl_xor_sync(0xffffffff, mx0, 2));
            mx1 = fmaxf(mx1, __shfl_xor_sync(0xffffffff, mx1, 1));
            mx1 = fmaxf(mx1, __shfl_xor_sync(0xffffffff, mx1, 2));
            const float mn0 = fmaxf(m0, mx0), mn1 = fmaxf(m1, mx1);
            const float f0 = ex2(m0 - mn0), f1 = ex2(m1 - mn1);
            m0 = mn0; m1 = mn1;
            float sum0 = 0.f, sum1 = 0.f;
            #pragma unroll
            for (int j = 0; j < 8; ++j) {
                s[j][0] = ex2(s[j][0] - mn0);
                s[j][1] = ex2(s[j][1] - mn0);
                s[j][2] = ex2(s[j][2] - mn1);
                s[j][3] = ex2(s[j][3] - mn1);
                sum0 += s[j][0] + s[j][1];
                sum1 += s[j][2] + s[j][3];
            }
            sum0 += __shfl_xor_sync(0xffffffff, sum0, 1);
            sum0 += __shfl_xor_sync(0xffffffff, sum0, 2);
            sum1 += __shfl_xor_sync(0xffffffff, sum1, 1);
            sum1 += __shfl_xor_sync(0xffffffff, sum1, 2);
            l0 = l0 * f0 + sum0;
            l1 = l1 * f1 + sum1;
            #pragma unroll
            for (int j = 0; j < 16; ++j) {
                o[j][0] *= f0; o[j][1] *= f0;
                o[j][2] *= f1; o[j][3] *= f1;
            }

            // O += P*V (both single fp16)
            #pragma unroll
            for (int kc = 0; kc < 4; ++kc) {
                uint32_t ap[4];
                ap[0] = packh2(s[2*kc][0],   s[2*kc][1]);
                ap[1] = packh2(s[2*kc][2],   s[2*kc][3]);
                ap[2] = packh2(s[2*kc+1][0], s[2*kc+1][1]);
                ap[3] = packh2(s[2*kc+1][2], s[2*kc+1][3]);
                #pragma unroll
                for (int g = 0; g < 8; ++g) {
                    const uint32_t offb =
                        ((g * 16 + (lane & 7) + ((lane >> 4) << 3)) * VSTR +
                         kc * 16 + (((lane >> 3) & 1) << 3)) * 2;
                    uint32_t bh[4];
                    ldsm_x4(bh, pV + offb);
                    mma_f16(o[2*g],   ap, &bh[0]);
                    mma_f16(o[2*g+1], ap, &bh[2]);
                }
            }
        }
    }

    // epilogue: normalize, store single fp16
    const float inv0 = 1.f / l0, inv1 = 1.f / l1;
    const size_t base0 = (size_t)(b * SEQ + r0g) * HID + h * DH;
    const size_t base1 = (size_t)(b * SEQ + r1g) * HID + h * DH;
    #pragma unroll
    for (int j = 0; j < 16; ++j) {
        const int col = j * 8 + c0l;
        *(uint32_t*)&OH[base0 + col] = packh2(o[j][0] * inv0, o[j][1] * inv0);
        *(uint32_t*)&OH[base1 + col] = packh2(o[j][2] * inv1, o[j][3] * inv1);
    }
}

// ---------------------------------------------------------------------------
// Launch
// ---------------------------------------------------------------------------
extern "C" void kernel_launch(void* const* d_in, const int* in_sizes, int n_in,
                              void* d_out, int out_size)
{
    const float* x    = (const float*)d_in[0];
    const int*   mask = (const int*)  d_in[1];
    const float* Wq   = (const float*)d_in[2];
    const float* bq   = (const float*)d_in[3];
    const float* Wk   = (const float*)d_in[4];
    const float* bk   = (const float*)d_in[5];
    const float* Wv   = (const float*)d_in[6];
    const float* bv   = (const float*)d_in[7];
    const float* Wo   = (const float*)d_in[8];
    const float* bo   = (const float*)d_in[9];
    float* out = (float*)d_out;

    void *pv, *pxh, *pqs, *pkh, *pvth, *pah;
    void *pwh, *pwl, *pwoh, *pwol;
    cudaGetSymbolAddress(&pv,  g_v);
    cudaGetSymbolAddress(&pxh, g_xh);
    cudaGetSymbolAddress(&pqs, g_qs);
    cudaGetSymbolAddress(&pkh, g_kh);
    cudaGetSymbolAddress(&pvth, g_vth);
    cudaGetSymbolAddress(&pah, g_ah);
    cudaGetSymbolAddress(&pwh, g_wh);  cudaGetSymbolAddress(&pwl, g_wl);
    cudaGetSymbolAddress(&pwoh, g_woh); cudaGetSymbolAddress(&pwol, g_wol);

    __half* wh = (__half*)pwh;
    __half* wl = (__half*)pwl;

    // --- converters ---
    const int n4 = MTOT * HID / 4;
    xcvt_kernel<<<n4 / 256, 256>>>(x, (__half*)pxh, n4);
    dim3 tb(32, 8);
    wconvT_kernel<<<dim3(160, GEMM_K / 32), tb>>>(
        Wq, Wk, Wv, Wo, wh, wl, (__half*)pwoh, (__half*)pwol);

    // --- fused QKV projection (fp16 2-pass, 3-stage pipeline) ---
    const int gemm_smem = 3 * STAGE_B;   // 92160
    cudaFuncSetAttribute(gemm_qkv, cudaFuncAttributeMaxDynamicSharedMemorySize,
                         gemm_smem);
    cudaFuncSetAttribute(gemm_o, cudaFuncAttributeMaxDynamicSharedMemorySize,
                         gemm_smem);
    gemm_qkv<<<dim3(NQKV / 128, MTOT / 128), 256, gemm_smem>>>(
        (const __half*)pxh, wh, wl, bq, bk, bv,
        (__half*)pqs, (__half*)pkh, (float*)pv);

    // --- V transpose (single fp16) ---
    vsplitT_kernel<<<dim3(KVW / 32, SEQ / 32, BATCH), tb>>>(
        (const float*)pv, (__half*)pvth);

    // --- fp16 flash attention (1-pass QK, 1-pass PV, K+V double buffer) ---
    cudaFuncSetAttribute(attn_hmma, cudaFuncAttributeMaxDynamicSharedMemorySize,
                         ATTN_SMEM);
    attn_hmma<<<dim3(NH, SEQ / 128, BATCH), 256, ATTN_SMEM>>>(
        (const __half*)pqs, (const __half*)pkh, (const __half*)pvth,
        mask, (__half*)pah);

    // --- output projection (fp16 2-pass, 3-stage pipeline) ---
    gemm_o<<<dim3(HID / 128, MTOT / 128), 256, gemm_smem>>>(
        (const __half*)pah, (__half*)pwoh, (__half*)pwol, bo, out);
}

// round 11
// speedup vs baseline: 2.4843x; 1.5165x over previous
#include <cuda_runtime.h>
#include <cuda_bf16.h>
#include <cuda_fp16.h>
#include <cstdint>
#include <math.h>

// ---------------------------------------------------------------------------
// Problem constants
// ---------------------------------------------------------------------------
#define BATCH   2
#define SEQ     2048
#define HID     2048
#define NH      16
#define NKV     4
#define DH      128
#define KVW     (NKV * DH)          // 512
#define MTOT    (BATCH * SEQ)       // 4096
#define GROUPS  (NH / NKV)          // 4
#define GEMM_K  2048
#define NQKV    (HID + 2 * KVW)     // 3072

// ---------------------------------------------------------------------------
// PTX helpers — ONLY non-'a' features (mma.sync / ldmatrix / cp.async).
// ---------------------------------------------------------------------------
__device__ __forceinline__ uint32_t smem_to_u32(const void* p) {
    uint32_t a;
    asm("{ .reg .u64 t; cvta.to.shared.u64 t, %1; cvt.u32.u64 %0, t; }"
        : "=r"(a) : "l"(p));
    return a;
}
#define CP_ASYNC16(dst, src) \
    asm volatile("cp.async.cg.shared.global [%0], [%1], 16;" \
                 :: "r"(dst), "l"(src))
#define CP_ASYNC4(dst, src) \
    asm volatile("cp.async.ca.shared.global [%0], [%1], 4;" \
                 :: "r"(dst), "l"(src))
#define CP_COMMIT() asm volatile("cp.async.commit_group;")
#define CP_WAIT(n)  asm volatile("cp.async.wait_group %0;" :: "n"(n))

__device__ __forceinline__ void ldsm_x4(uint32_t* r, uint32_t addr) {
    asm volatile("ldmatrix.sync.aligned.m8n8.x4.shared.b16 {%0,%1,%2,%3}, [%4];"
                 : "=r"(r[0]), "=r"(r[1]), "=r"(r[2]), "=r"(r[3]) : "r"(addr));
}
__device__ __forceinline__ void mma_f16(float* d, const uint32_t* a,
                                        const uint32_t* b) {
    asm volatile(
        "mma.sync.aligned.m16n8k16.row.col.f32.f16.f16.f32 "
        "{%0,%1,%2,%3}, {%4,%5,%6,%7}, {%8,%9}, {%0,%1,%2,%3};"
        : "+f"(d[0]), "+f"(d[1]), "+f"(d[2]), "+f"(d[3])
        : "r"(a[0]), "r"(a[1]), "r"(a[2]), "r"(a[3]), "r"(b[0]), "r"(b[1]));
}
__device__ __forceinline__ uint32_t packh2(float x, float y) {
    __half2 h(__float2half(x), __float2half(y));
    return *reinterpret_cast<uint32_t*>(&h);
}
__device__ __forceinline__ float ex2(float x) {
    float r;
    asm("ex2.approx.f32 %0, %1;" : "=f"(r) : "f"(x));
    return r;
}

// ---------------------------------------------------------------------------
// Scratch buffers
// ---------------------------------------------------------------------------
__device__ float g_v[(size_t)MTOT * KVW];
__device__ __half g_xh[(size_t)MTOT * HID];           // x single fp16
__device__ __half g_qs[(size_t)MTOT * HID];           // q single fp16 (pre-scaled)
__device__ __half g_kh[(size_t)MTOT * KVW];           // k single fp16
__device__ __half g_vth[(size_t)MTOT * KVW];          // VT single fp16 [B*KVW, SEQ]
__device__ __half g_ah[(size_t)MTOT * HID];           // attn out fp16
__device__ __half g_wh[(size_t)NQKV * HID];           // [Wq;Wk;Wv] T, single fp16
__device__ __half g_woh[(size_t)HID * HID];           // Wo T, single fp16

// ---------------------------------------------------------------------------
// Converters
// ---------------------------------------------------------------------------
__global__ void xcvt_kernel(const float* __restrict__ in,
                            __half* __restrict__ hi, int n4)
{
    int i = blockIdx.x * blockDim.x + threadIdx.x;
    if (i >= n4) return;
    float4 v = ((const float4*)in)[i];
    __half2 a(__float2half(v.x), __float2half(v.y));
    __half2 b(__float2half(v.z), __float2half(v.w));
    ((__half2*)hi)[2*i]   = a;
    ((__half2*)hi)[2*i+1] = b;
}

// All four weight matrices transposed to single fp16 in ONE launch.
__global__ void wconvT_kernel(const float* __restrict__ Wq,
                              const float* __restrict__ Wk,
                              const float* __restrict__ Wv,
                              const float* __restrict__ Wo,
                              __half* __restrict__ wh,
                              __half* __restrict__ woh)
{
    const int bx = blockIdx.x;
    const float* W;
    __half* Th;
    int N, nblk;
    if (bx < 64)      { W = Wq; Th = wh;  N = HID; nblk = bx; }
    else if (bx < 80) { W = Wk; Th = wh + (size_t)HID * GEMM_K;  N = KVW; nblk = bx - 64; }
    else if (bx < 96) { W = Wv; Th = wh + (size_t)(HID + KVW) * GEMM_K; N = KVW; nblk = bx - 80; }
    else              { W = Wo; Th = woh; N = HID; nblk = bx - 96; }

    __shared__ float t[32][33];
    const int n  = nblk * 32 + threadIdx.x;
    const int kb = blockIdx.y * 32;
    #pragma unroll
    for (int j = 0; j < 32; j += 8)
        t[threadIdx.y + j][threadIdx.x] = W[(size_t)(kb + threadIdx.y + j) * N + n];
    __syncthreads();
    const int k  = kb + threadIdx.x;
    const int nb = nblk * 32;
    #pragma unroll
    for (int j = 0; j < 32; j += 8) {
        float v = t[threadIdx.x][threadIdx.y + j];
        Th[(size_t)(nb + threadIdx.y + j) * GEMM_K + k] = __float2half(v);
    }
}

// V [B*SEQ, KVW] fp32 -> VT [B*KVW, SEQ] single fp16
__global__ void vsplitT_kernel(const float* __restrict__ V,
                               __half* __restrict__ Th)
{
    __shared__ float t[32][33];
    const int n0 = blockIdx.x * 32;
    const int s0 = blockIdx.y * 32;
    const int b  = blockIdx.z;
    #pragma unroll
    for (int j = 0; j < 32; j += 8)
        t[threadIdx.y + j][threadIdx.x] =
            V[(size_t)(b * SEQ + s0 + threadIdx.y + j) * KVW + n0 + threadIdx.x];
    __syncthreads();
    #pragma unroll
    for (int j = 0; j < 32; j += 8) {
        float v = t[threadIdx.x][threadIdx.y + j];
        size_t o = (size_t)(b * KVW + n0 + threadIdx.y + j) * SEQ + s0 + threadIdx.x;
        Th[o] = __float2half(v);
    }
}

// ---------------------------------------------------------------------------
// fp16 HMMA GEMM mainloop: C = A[M,K] @ B^T[N,K]  (single-pass, 2 smem mats)
// 3-stage pipeline, ONE sync per chunk.
// ---------------------------------------------------------------------------
#define KC        32
#define AS_STRIDE 40
#define MAT_B     (128 * AS_STRIDE * 2)   // 10240 bytes
#define STAGE_B   (2 * MAT_B)             // 20480 bytes
#define NCHUNK    (GEMM_K / KC)

#define GEMM_MAINLOOP_F16(AhP, BhP)                                             \
    float acc[4][4][4];                                                         \
    _Pragma("unroll")                                                           \
    for (int a = 0; a < 4; ++a)                                                 \
        _Pragma("unroll")                                                       \
        for (int b2 = 0; b2 < 4; ++b2)                                          \
            _Pragma("unroll")                                                   \
            for (int c = 0; c < 4; ++c) acc[a][b2][c] = 0.f;                    \
    const __half* mats[2] = {AhP, BhP};                                         \
    auto load_stage = [&](int s, int k0) {                                      \
        const uint32_t st = smem_base + s * STAGE_B;                            \
        _Pragma("unroll")                                                       \
        for (int mat = 0; mat < 2; ++mat) {                                     \
            const __half* src = mats[mat];                                      \
            const int r0 = (mat < 1) ? m0 : n0;                                 \
            const uint32_t dstb = st + mat * MAT_B;                             \
            _Pragma("unroll")                                                   \
            for (int it = 0; it < 2; ++it) {                                    \
                const int idx = it * 256 + tid;                                 \
                const int row = idx >> 2;                                       \
                const int k4  = idx & 3;                                        \
                const void* sp = src + (size_t)(r0 + row) * GEMM_K + k0 + k4*8; \
                const uint32_t dp = dstb + row * (AS_STRIDE * 2) + k4 * 16;     \
                CP_ASYNC16(dp, sp);                                             \
            }                                                                   \
        }                                                                       \
    };                                                                          \
    load_stage(0, 0);                                                           \
    CP_COMMIT();                                                                \
    load_stage(1, KC);                                                          \
    CP_COMMIT();                                                                \
    for (int c = 0; c < NCHUNK; ++c) {                                          \
        if (c + 1 < NCHUNK) { CP_WAIT(1); } else { CP_WAIT(0); }                \
        __syncthreads();                                                        \
        if (c + 2 < NCHUNK) {                                                   \
            load_stage((c + 2) % 3, (c + 2) * KC);                              \
            CP_COMMIT();                                                        \
        }                                                                       \
        const uint32_t stg = smem_base + (c % 3) * STAGE_B;                     \
        const uint32_t pA  = stg;                                               \
        const uint32_t pB  = stg + MAT_B;                                       \
        _Pragma("unroll")                                                       \
        for (int ks = 0; ks < 2; ++ks) {                                        \
            const int kcol = ks * 16;                                           \
            uint32_t bh[8];                                                     \
            _Pragma("unroll")                                                   \
            for (int p = 0; p < 2; ++p) {                                       \
                const int nrow = wn * 32 + p * 16 + (lane & 7) + ((lane>>4)<<3);\
                const int kk   = kcol + (((lane >> 3) & 1) << 3);               \
                const uint32_t off = (nrow * AS_STRIDE + kk) * 2;               \
                ldsm_x4(&bh[p * 4], pB + off);                                  \
            }                                                                   \
            _Pragma("unroll")                                                   \
            for (int mt = 0; mt < 4; ++mt) {                                    \
                const int mrow = wm * 64 + mt * 16 + (lane & 15);               \
                const int kk2  = kcol + ((lane >> 4) << 3);                     \
                const uint32_t offa = (mrow * AS_STRIDE + kk2) * 2;             \
                uint32_t afr[4];                                                \
                ldsm_x4(afr, pA + offa);                                        \
                _Pragma("unroll")                                               \
                for (int nt = 0; nt < 4; ++nt) mma_f16(acc[mt][nt], afr, &bh[nt*2]); \
            }                                                                   \
        }                                                                       \
    }

// ---------------------------------------------------------------------------
// Fused QKV projection: q -> single fp16 (pre-scaled by scl*log2e),
// k -> single fp16, v -> fp32.
// ---------------------------------------------------------------------------
#define ATT_SCL (0.08838834764831845f * 1.4426950408889634f)

__global__ void __launch_bounds__(256)
gemm_qkv(const __half* __restrict__ Ah, const __half* __restrict__ Bh,
         const float* __restrict__ bq, const float* __restrict__ bk,
         const float* __restrict__ bv,
         __half* __restrict__ Qs, __half* __restrict__ Kh,
         float* __restrict__ Vo)
{
    extern __shared__ __align__(128) char smem[];
    const uint32_t smem_base = smem_to_u32(smem);
    const int tid  = threadIdx.x;
    const int warp = tid >> 5;
    const int lane = tid & 31;
    const int wm   = warp >> 2;
    const int wn   = warp & 3;
    const int m0   = blockIdx.y * 128;
    const int n0   = blockIdx.x * 128;

    GEMM_MAINLOOP_F16(Ah, Bh)

    #pragma unroll
    for (int mt = 0; mt < 4; ++mt)
        #pragma unroll
        for (int rh = 0; rh < 2; ++rh) {
            const int row = m0 + wm * 64 + mt * 16 + (lane >> 2) + rh * 8;
            #pragma unroll
            for (int nt = 0; nt < 4; ++nt) {
                const int col = n0 + wn * 32 + nt * 8 + (lane & 3) * 2;
                if (n0 < HID) {
                    const float v0 = (acc[mt][nt][rh*2+0] + bq[col])   * ATT_SCL;
                    const float v1 = (acc[mt][nt][rh*2+1] + bq[col+1]) * ATT_SCL;
                    *(uint32_t*)&Qs[(size_t)row * HID + col] = packh2(v0, v1);
                } else if (n0 < HID + KVW) {
                    const int c2 = col - HID;
                    const float v0 = acc[mt][nt][rh*2+0] + bk[c2];
                    const float v1 = acc[mt][nt][rh*2+1] + bk[c2+1];
                    *(uint32_t*)&Kh[(size_t)row * KVW + c2] = packh2(v0, v1);
                } else {
                    const int c2 = col - HID - KVW;
                    float2 v;
                    v.x = acc[mt][nt][rh*2+0] + bv[c2];
                    v.y = acc[mt][nt][rh*2+1] + bv[c2+1];
                    *(float2*)&Vo[(size_t)row * KVW + c2] = v;
                }
            }
        }
}

// ---------------------------------------------------------------------------
// O-projection GEMM (fp16 single-pass, fp32 out)
// ---------------------------------------------------------------------------
__global__ void __launch_bounds__(256)
gemm_o(const __half* __restrict__ Ah, const __half* __restrict__ Bh,
       const float* __restrict__ bias, float* __restrict__ C)
{
    extern __shared__ __align__(128) char smem[];
    const uint32_t smem_base = smem_to_u32(smem);
    const int tid  = threadIdx.x;
    const int warp = tid >> 5;
    const int lane = tid & 31;
    const int wm   = warp >> 2;
    const int wn   = warp & 3;
    const int m0   = blockIdx.y * 128;
    const int n0   = blockIdx.x * 128;

    GEMM_MAINLOOP_F16(Ah, Bh)

    #pragma unroll
    for (int mt = 0; mt < 4; ++mt)
        #pragma unroll
        for (int rh = 0; rh < 2; ++rh) {
            const int row = m0 + wm * 64 + mt * 16 + (lane >> 2) + rh * 8;
            #pragma unroll
            for (int nt = 0; nt < 4; ++nt) {
                const int col = n0 + wn * 32 + nt * 8 + (lane & 3) * 2;
                float2 v;
                v.x = acc[mt][nt][rh*2+0] + bias[col];
                v.y = acc[mt][nt][rh*2+1] + bias[col+1];
                *(float2*)&C[(size_t)row * HID + col] = v;
            }
        }
}

// ---------------------------------------------------------------------------
// fp16 FlashAttention: 128 q-rows x 64 kv tiles, 8 warps.
// Single-pass QK, single-pass PV. K+V+mask double-buffered; ONE sync per tile.
// Grid (NH, SEQ/128, BATCH), qb reversed on slow axis => LPT.
// ---------------------------------------------------------------------------
#define QSTR 136
#define VSTR 72
#define SM_Q   0
#define SM_ST  34816                 // stage base (K tile then V tile)
#define STG_B  35840                 // 17408 (K) + 18432 (V)
#define SM_MK  (SM_ST + 2 * STG_B)   // 106496
#define ATTN_SMEM (SM_MK + 512)      // 107008

__global__ void __launch_bounds__(256)
attn_hmma(const __half* __restrict__ Qs, const __half* __restrict__ Kh,
          const __half* __restrict__ VTh, const int* __restrict__ mask,
          __half* __restrict__ OH)
{
    extern __shared__ __align__(128) char sm[];
    const uint32_t base = smem_to_u32(sm);
    const int tid = threadIdx.x;
    const int w    = tid >> 5;
    const int lane = tid & 31;
    const int h  = blockIdx.x;
    const int qb = (int)gridDim.y - 1 - (int)blockIdx.y;   // heavy-first (LPT)
    const int b  = blockIdx.z;
    const int q0 = qb * 128;
    const int kvh = h >> 2;
    const int T = 2 * qb + 2;

    auto load_kv = [&](int t) {
        const int k0 = t * 64;
        const int s  = t & 1;
        const uint32_t kdst = base + SM_ST + s * STG_B;
        #pragma unroll
        for (int i = 0; i < 4; ++i) {
            const int idx = i * 256 + tid;
            const int row = idx >> 4, c = idx & 15;
            CP_ASYNC16(kdst + row * 272 + c * 16,
                       Kh + (size_t)(b * SEQ + k0 + row) * KVW + kvh * DH + c * 8);
        }
        const uint32_t vdst = kdst + 17408;
        #pragma unroll
        for (int i = 0; i < 4; ++i) {
            const int idx = i * 256 + tid;
            const int row = idx >> 3, c = idx & 7;
            CP_ASYNC16(vdst + row * 144 + c * 16,
                       VTh + (size_t)(b * KVW + kvh * DH + row) * SEQ + k0 + c * 8);
        }
        if (tid < 64)
            CP_ASYNC4(base + SM_MK + s * 256 + tid * 4, mask + b * SEQ + k0 + tid);
    };

    // prologue: Q + KV(0)
    #pragma unroll
    for (int i = 0; i < 8; ++i) {
        const int idx = i * 256 + tid;
        const int row = idx >> 4, c = idx & 15;
        CP_ASYNC16(base + SM_Q + row * 272 + c * 16,
                   Qs + (size_t)(b * SEQ + q0 + row) * HID + h * DH + c * 8);
    }
    load_kv(0);
    CP_COMMIT();

    float s[8][4];
    float o[16][4];
    #pragma unroll
    for (int j = 0; j < 16; ++j)
        #pragma unroll
        for (int c = 0; c < 4; ++c) o[j][c] = 0.f;
    float m0 = -1e30f, m1 = -1e30f, l0 = 0.f, l1 = 0.f;

    const int r0g = q0 + w * 16 + (lane >> 2);
    const int r1g = r0g + 8;
    const int c0l = (lane & 3) * 2;

    for (int t = 0; t < T; ++t) {
        const int k0 = t * 64;
        const int st = t & 1;
        const bool active = (q0 + w * 16 + 15) >= k0;

        CP_WAIT(0);
        __syncthreads();
        if (t + 1 < T) {
            load_kv(t + 1);
            CP_COMMIT();
        }

        if (active) {
            const uint32_t pK = base + SM_ST + st * STG_B;
            const uint32_t pV = pK + 17408;
            const int* mk_s = (const int*)(sm + SM_MK + st * 256);

            #pragma unroll
            for (int j = 0; j < 8; ++j)
                #pragma unroll
                for (int c = 0; c < 4; ++c) s[j][c] = 0.f;

            // S = Q*K
            #pragma unroll
            for (int kc = 0; kc < 8; ++kc) {
                const uint32_t offa =
                    ((w * 16 + (lane & 15)) * QSTR + kc * 16 + ((lane >> 4) << 3)) * 2;
                uint32_t aq[4];
                ldsm_x4(aq, base + SM_Q + offa);
                #pragma unroll
                for (int g = 0; g < 4; ++g) {
                    const uint32_t offb =
                        ((g * 16 + (lane & 7) + ((lane >> 4) << 3)) * QSTR +
                         kc * 16 + (((lane >> 3) & 1) << 3)) * 2;
                    uint32_t bh[4];
                    ldsm_x4(bh, pK + offb);
                    mma_f16(s[2*g],   aq, &bh[0]);
                    mma_f16(s[2*g+1], aq, &bh[2]);
                }
            }

            // mask + online softmax (base-2 domain)
            float mx0 = -1e30f, mx1 = -1e30f;
            #pragma unroll
            for (int j = 0; j < 8; ++j) {
                const int cg = k0 + j * 8 + c0l;
                const int mk0 = mk_s[j * 8 + c0l];
                const int mk1 = mk_s[j * 8 + c0l + 1];
                s[j][0] = (cg     <= r0g && mk0) ? s[j][0] : -1e30f;
                s[j][1] = (cg + 1 <= r0g && mk1) ? s[j][1] : -1e30f;
                s[j][2] = (cg     <= r1g && mk0) ? s[j][2] : -1e30f;
                s[j][3] = (cg + 1 <= r1g && mk1) ? s[j][3] : -1e30f;
                mx0 = fmaxf(mx0, fmaxf(s[j][0], s[j][1]));
                mx1 = fmaxf(mx1, fmaxf(s[j][2], s[j][3]));
            }
            mx0 = fmaxf(mx0, __shfl_xor_sync(0xffffffff, mx0, 1));
            mx0 = fmaxf(mx0, __shfl_xor_sync(0xffffffff, mx0, 2));
            mx1 = fmaxf(mx1, __shfl_xor_sync(0xffffffff, mx1, 1));
            mx1 = fmaxf(mx1, __shfl_xor_sync(0xffffffff, mx1, 2));
            const float mn0 = fmaxf(m0, mx0), mn1 = fmaxf(m1, mx1);
            const float f0 = ex2(m0 - mn0), f1 = ex2(m1 - mn1);
            m0 = mn0; m1 = mn1;
            float sum0 = 0.f, sum1 = 0.f;
            #pragma unroll
            for (int j = 0; j < 8; ++j) {
                s[j][0] = ex2(s[j][0] - mn0);
                s[j][1] = ex2(s[j][1] - mn0);
                s[j][2] = ex2(s[j][2] - mn1);
                s[j][3] = ex2(s[j][3] - mn1);
                sum0 += s[j][0] + s[j][1];
                sum1 += s[j][2] + s[j][3];
            }
            sum0 += __shfl_xor_sync(0xffffffff, sum0, 1);
            sum0 += __shfl_xor_sync(0xffffffff, sum0, 2);
            sum1 += __shfl_xor_sync(0xffffffff, sum1, 1);
            sum1 += __shfl_xor_sync(0xffffffff, sum1, 2);
            l0 = l0 * f0 + sum0;
            l1 = l1 * f1 + sum1;
            #pragma unroll
            for (int j = 0; j < 16; ++j) {
                o[j][0] *= f0; o[j][1] *= f0;
                o[j][2] *= f1; o[j][3] *= f1;
            }

            // O += P*V
            #pragma unroll
            for (int kc = 0; kc < 4; ++kc) {
                uint32_t ap[4];
                ap[0] = packh2(s[2*kc][0],   s[2*kc][1]);
                ap[1] = packh2(s[2*kc][2],   s[2*kc][3]);
                ap[2] = packh2(s[2*kc+1][0], s[2*kc+1][1]);
                ap[3] = packh2(s[2*kc+1][2], s[2*kc+1][3]);
                #pragma unroll
                for (int g = 0; g < 8; ++g) {
                    const uint32_t offb =
                        ((g * 16 + (lane & 7) + ((lane >> 4) << 3)) * VSTR +
                         kc * 16 + (((lane >> 3) & 1) << 3)) * 2;
                    uint32_t bh[4];
                    ldsm_x4(bh, pV + offb);
                    mma_f16(o[2*g],   ap, &bh[0]);
                    mma_f16(o[2*g+1], ap, &bh[2]);
                }
            }
        }
    }

    // epilogue: normalize, store single fp16
    const float inv0 = 1.f / l0, inv1 = 1.f / l1;
    const size_t base0 = (size_t)(b * SEQ + r0g) * HID + h * DH;
    const size_t base1 = (size_t)(b * SEQ + r1g) * HID + h * DH;
    #pragma unroll
    for (int j = 0; j < 16; ++j) {
        const int col = j * 8 + c0l;
        *(uint32_t*)&OH[base0 + col] = packh2(o[j][0] * inv0, o[j][1] * inv0);
        *(uint32_t*)&OH[base1 + col] = packh2(o[j][2] * inv1, o[j][3] * inv1);
    }
}

// ---------------------------------------------------------------------------
// Launch
// ---------------------------------------------------------------------------
extern "C" void kernel_launch(void* const* d_in, const int* in_sizes, int n_in,
                              void* d_out, int out_size)
{
    const float* x    = (const float*)d_in[0];
    const int*   mask = (const int*)  d_in[1];
    const float* Wq   = (const float*)d_in[2];
    const float* bq   = (const float*)d_in[3];
    const float* Wk   = (const float*)d_in[4];
    const float* bk   = (const float*)d_in[5];
    const float* Wv   = (const float*)d_in[6];
    const float* bv   = (const float*)d_in[7];
    const float* Wo   = (const float*)d_in[8];
    const float* bo   = (const float*)d_in[9];
    float* out = (float*)d_out;

    void *pv, *pxh, *pqs, *pkh, *pvth, *pah, *pwh, *pwoh;
    cudaGetSymbolAddress(&pv,  g_v);
    cudaGetSymbolAddress(&pxh, g_xh);
    cudaGetSymbolAddress(&pqs, g_qs);
    cudaGetSymbolAddress(&pkh, g_kh);
    cudaGetSymbolAddress(&pvth, g_vth);
    cudaGetSymbolAddress(&pah, g_ah);
    cudaGetSymbolAddress(&pwh, g_wh);
    cudaGetSymbolAddress(&pwoh, g_woh);

    __half* wh = (__half*)pwh;

    // --- converters ---
    const int n4 = MTOT * HID / 4;
    xcvt_kernel<<<n4 / 256, 256>>>(x, (__half*)pxh, n4);
    dim3 tb(32, 8);
    wconvT_kernel<<<dim3(160, GEMM_K / 32), tb>>>(
        Wq, Wk, Wv, Wo, wh, (__half*)pwoh);

    // --- fused QKV projection (fp16 single-pass, 3-stage pipeline) ---
    const int gemm_smem = 3 * STAGE_B;   // 61440
    cudaFuncSetAttribute(gemm_qkv, cudaFuncAttributeMaxDynamicSharedMemorySize,
                         gemm_smem);
    cudaFuncSetAttribute(gemm_o, cudaFuncAttributeMaxDynamicSharedMemorySize,
                         gemm_smem);
    gemm_qkv<<<dim3(NQKV / 128, MTOT / 128), 256, gemm_smem>>>(
        (const __half*)pxh, wh, bq, bk, bv,
        (__half*)pqs, (__half*)pkh, (float*)pv);

    // --- V transpose (single fp16) ---
    vsplitT_kernel<<<dim3(KVW / 32, SEQ / 32, BATCH), tb>>>(
        (const float*)pv, (__half*)pvth);

    // --- fp16 flash attention ---
    cudaFuncSetAttribute(attn_hmma, cudaFuncAttributeMaxDynamicSharedMemorySize,
                         ATTN_SMEM);
    attn_hmma<<<dim3(NH, SEQ / 128, BATCH), 256, ATTN_SMEM>>>(
        (const __half*)pqs, (const __half*)pkh, (const __half*)pvth,
        mask, (__half*)pah);

    // --- output projection (fp16 single-pass) ---
    gemm_o<<<dim3(HID / 128, MTOT / 128), 256, gemm_smem>>>(
        (const __half*)pah, (__half*)pwoh, bo, out);
}

// round 12
// speedup vs baseline: 2.5981x; 1.0458x over previous
#include <cuda_runtime.h>
#include <cuda_bf16.h>
#include <cuda_fp16.h>
#include <cstdint>
#include <math.h>

// ---------------------------------------------------------------------------
// Problem constants
// ---------------------------------------------------------------------------
#define BATCH   2
#define SEQ     2048
#define HID     2048
#define NH      16
#define NKV     4
#define DH      128
#define KVW     (NKV * DH)          // 512
#define MTOT    (BATCH * SEQ)       // 4096
#define GROUPS  (NH / NKV)          // 4
#define GEMM_K  2048
#define NQKV    (HID + 2 * KVW)     // 3072

// ---------------------------------------------------------------------------
// PTX helpers — ONLY non-'a' features (mma.sync / ldmatrix / cp.async).
// ---------------------------------------------------------------------------
__device__ __forceinline__ uint32_t smem_to_u32(const void* p) {
    uint32_t a;
    asm("{ .reg .u64 t; cvta.to.shared.u64 t, %1; cvt.u32.u64 %0, t; }"
        : "=r"(a) : "l"(p));
    return a;
}
#define CP_ASYNC16(dst, src) \
    asm volatile("cp.async.cg.shared.global [%0], [%1], 16;" \
                 :: "r"(dst), "l"(src))
#define CP_ASYNC4(dst, src) \
    asm volatile("cp.async.ca.shared.global [%0], [%1], 4;" \
                 :: "r"(dst), "l"(src))
#define CP_COMMIT() asm volatile("cp.async.commit_group;")
#define CP_WAIT(n)  asm volatile("cp.async.wait_group %0;" :: "n"(n))

__device__ __forceinline__ void ldsm_x4(uint32_t* r, uint32_t addr) {
    asm volatile("ldmatrix.sync.aligned.m8n8.x4.shared.b16 {%0,%1,%2,%3}, [%4];"
                 : "=r"(r[0]), "=r"(r[1]), "=r"(r[2]), "=r"(r[3]) : "r"(addr));
}
__device__ __forceinline__ void mma_f16(float* d, const uint32_t* a,
                                        const uint32_t* b) {
    asm volatile(
        "mma.sync.aligned.m16n8k16.row.col.f32.f16.f16.f32 "
        "{%0,%1,%2,%3}, {%4,%5,%6,%7}, {%8,%9}, {%0,%1,%2,%3};"
        : "+f"(d[0]), "+f"(d[1]), "+f"(d[2]), "+f"(d[3])
        : "r"(a[0]), "r"(a[1]), "r"(a[2]), "r"(a[3]), "r"(b[0]), "r"(b[1]));
}
__device__ __forceinline__ uint32_t packh2(float x, float y) {
    __half2 h(__float2half(x), __float2half(y));
    return *reinterpret_cast<uint32_t*>(&h);
}
__device__ __forceinline__ float ex2(float x) {
    float r;
    asm("ex2.approx.f32 %0, %1;" : "=f"(r) : "f"(x));
    return r;
}

// ---------------------------------------------------------------------------
// Scratch buffers
// ---------------------------------------------------------------------------
__device__ float g_v[(size_t)MTOT * KVW];
__device__ __half g_xh[(size_t)MTOT * HID];           // x single fp16
__device__ __half g_qs[(size_t)MTOT * HID];           // q single fp16 (pre-scaled)
__device__ __half g_kh[(size_t)MTOT * KVW];           // k single fp16
__device__ __half g_vth[(size_t)MTOT * KVW];          // VT single fp16 [B*KVW, SEQ]
__device__ __half g_ah[(size_t)MTOT * HID];           // attn out fp16
__device__ __half g_wh[(size_t)NQKV * HID];           // [Wq;Wk;Wv] T, single fp16
__device__ __half g_woh[(size_t)HID * HID];           // Wo T, single fp16

// ---------------------------------------------------------------------------
// Converters
// ---------------------------------------------------------------------------
__global__ void xcvt_kernel(const float* __restrict__ in,
                            __half* __restrict__ hi, int n4)
{
    int i = blockIdx.x * blockDim.x + threadIdx.x;
    if (i >= n4) return;
    float4 v = ((const float4*)in)[i];
    __half2 a(__float2half(v.x), __float2half(v.y));
    __half2 b(__float2half(v.z), __float2half(v.w));
    ((__half2*)hi)[2*i]   = a;
    ((__half2*)hi)[2*i+1] = b;
}

// All four weight matrices transposed to single fp16 in ONE launch.
__global__ void wconvT_kernel(const float* __restrict__ Wq,
                              const float* __restrict__ Wk,
                              const float* __restrict__ Wv,
                              const float* __restrict__ Wo,
                              __half* __restrict__ wh,
                              __half* __restrict__ woh)
{
    const int bx = blockIdx.x;
    const float* W;
    __half* Th;
    int N, nblk;
    if (bx < 64)      { W = Wq; Th = wh;  N = HID; nblk = bx; }
    else if (bx < 80) { W = Wk; Th = wh + (size_t)HID * GEMM_K;  N = KVW; nblk = bx - 64; }
    else if (bx < 96) { W = Wv; Th = wh + (size_t)(HID + KVW) * GEMM_K; N = KVW; nblk = bx - 80; }
    else              { W = Wo; Th = woh; N = HID; nblk = bx - 96; }

    __shared__ float t[32][33];
    const int n  = nblk * 32 + threadIdx.x;
    const int kb = blockIdx.y * 32;
    #pragma unroll
    for (int j = 0; j < 32; j += 8)
        t[threadIdx.y + j][threadIdx.x] = W[(size_t)(kb + threadIdx.y + j) * N + n];
    __syncthreads();
    const int k  = kb + threadIdx.x;
    const int nb = nblk * 32;
    #pragma unroll
    for (int j = 0; j < 32; j += 8) {
        float v = t[threadIdx.x][threadIdx.y + j];
        Th[(size_t)(nb + threadIdx.y + j) * GEMM_K + k] = __float2half(v);
    }
}

// V [B*SEQ, KVW] fp32 -> VT [B*KVW, SEQ] single fp16
__global__ void vsplitT_kernel(const float* __restrict__ V,
                               __half* __restrict__ Th)
{
    __shared__ float t[32][33];
    const int n0 = blockIdx.x * 32;
    const int s0 = blockIdx.y * 32;
    const int b  = blockIdx.z;
    #pragma unroll
    for (int j = 0; j < 32; j += 8)
        t[threadIdx.y + j][threadIdx.x] =
            V[(size_t)(b * SEQ + s0 + threadIdx.y + j) * KVW + n0 + threadIdx.x];
    __syncthreads();
    #pragma unroll
    for (int j = 0; j < 32; j += 8) {
        float v = t[threadIdx.x][threadIdx.y + j];
        size_t o = (size_t)(b * KVW + n0 + threadIdx.y + j) * SEQ + s0 + threadIdx.x;
        Th[o] = __float2half(v);
    }
}

// ---------------------------------------------------------------------------
// fp16 HMMA GEMM mainloop: C = A[M,K] @ B^T[N,K]  (single-pass, 2 smem mats)
// 3-stage pipeline, ONE sync per chunk.
// ---------------------------------------------------------------------------
#define KC        32
#define AS_STRIDE 40
#define MAT_B     (128 * AS_STRIDE * 2)   // 10240 bytes
#define STAGE_B   (2 * MAT_B)             // 20480 bytes
#define NCHUNK    (GEMM_K / KC)

#define GEMM_MAINLOOP_F16(AhP, BhP)                                             \
    float acc[4][4][4];                                                         \
    _Pragma("unroll")                                                           \
    for (int a = 0; a < 4; ++a)                                                 \
        _Pragma("unroll")                                                       \
        for (int b2 = 0; b2 < 4; ++b2)                                          \
            _Pragma("unroll")                                                   \
            for (int c = 0; c < 4; ++c) acc[a][b2][c] = 0.f;                    \
    const __half* mats[2] = {AhP, BhP};                                         \
    auto load_stage = [&](int s, int k0) {                                      \
        const uint32_t st = smem_base + s * STAGE_B;                            \
        _Pragma("unroll")                                                       \
        for (int mat = 0; mat < 2; ++mat) {                                     \
            const __half* src = mats[mat];                                      \
            const int r0 = (mat < 1) ? m0 : n0;                                 \
            const uint32_t dstb = st + mat * MAT_B;                             \
            _Pragma("unroll")                                                   \
            for (int it = 0; it < 2; ++it) {                                    \
                const int idx = it * 256 + tid;                                 \
                const int row = idx >> 2;                                       \
                const int k4  = idx & 3;                                        \
                const void* sp = src + (size_t)(r0 + row) * GEMM_K + k0 + k4*8; \
                const uint32_t dp = dstb + row * (AS_STRIDE * 2) + k4 * 16;     \
                CP_ASYNC16(dp, sp);                                             \
            }                                                                   \
        }                                                                       \
    };                                                                          \
    load_stage(0, 0);                                                           \
    CP_COMMIT();                                                                \
    load_stage(1, KC);                                                          \
    CP_COMMIT();                                                                \
    for (int c = 0; c < NCHUNK; ++c) {                                          \
        if (c + 1 < NCHUNK) { CP_WAIT(1); } else { CP_WAIT(0); }                \
        __syncthreads();                                                        \
        if (c + 2 < NCHUNK) {                                                   \
            load_stage((c + 2) % 3, (c + 2) * KC);                              \
            CP_COMMIT();                                                        \
        }                                                                       \
        const uint32_t stg = smem_base + (c % 3) * STAGE_B;                     \
        const uint32_t pA  = stg;                                               \
        const uint32_t pB  = stg + MAT_B;                                       \
        _Pragma("unroll")                                                       \
        for (int ks = 0; ks < 2; ++ks) {                                        \
            const int kcol = ks * 16;                                           \
            uint32_t bh[8];                                                     \
            _Pragma("unroll")                                                   \
            for (int p = 0; p < 2; ++p) {                                       \
                const int nrow = wn * 32 + p * 16 + (lane & 7) + ((lane>>4)<<3);\
                const int kk   = kcol + (((lane >> 3) & 1) << 3);               \
                const uint32_t off = (nrow * AS_STRIDE + kk) * 2;               \
                ldsm_x4(&bh[p * 4], pB + off);                                  \
            }                                                                   \
            _Pragma("unroll")                                                   \
            for (int mt = 0; mt < 4; ++mt) {                                    \
                const int mrow = wm * 64 + mt * 16 + (lane & 15);               \
                const int kk2  = kcol + ((lane >> 4) << 3);                     \
                const uint32_t offa = (mrow * AS_STRIDE + kk2) * 2;             \
                uint32_t afr[4];                                                \
                ldsm_x4(afr, pA + offa);                                        \
                _Pragma("unroll")                                               \
                for (int nt = 0; nt < 4; ++nt) mma_f16(acc[mt][nt], afr, &bh[nt*2]); \
            }                                                                   \
        }                                                                       \
    }

// ---------------------------------------------------------------------------
// Fused QKV projection: q -> single fp16 (pre-scaled by scl*log2e),
// k -> single fp16, v -> fp32.
// ---------------------------------------------------------------------------
#define ATT_SCL (0.08838834764831845f * 1.4426950408889634f)

__global__ void __launch_bounds__(256)
gemm_qkv(const __half* __restrict__ Ah, const __half* __restrict__ Bh,
         const float* __restrict__ bq, const float* __restrict__ bk,
         const float* __restrict__ bv,
         __half* __restrict__ Qs, __half* __restrict__ Kh,
         float* __restrict__ Vo)
{
    extern __shared__ __align__(128) char smem[];
    const uint32_t smem_base = smem_to_u32(smem);
    const int tid  = threadIdx.x;
    const int warp = tid >> 5;
    const int lane = tid & 31;
    const int wm   = warp >> 2;
    const int wn   = warp & 3;
    const int m0   = blockIdx.y * 128;
    const int n0   = blockIdx.x * 128;

    GEMM_MAINLOOP_F16(Ah, Bh)

    #pragma unroll
    for (int mt = 0; mt < 4; ++mt)
        #pragma unroll
        for (int rh = 0; rh < 2; ++rh) {
            const int row = m0 + wm * 64 + mt * 16 + (lane >> 2) + rh * 8;
            #pragma unroll
            for (int nt = 0; nt < 4; ++nt) {
                const int col = n0 + wn * 32 + nt * 8 + (lane & 3) * 2;
                if (n0 < HID) {
                    const float v0 = (acc[mt][nt][rh*2+0] + bq[col])   * ATT_SCL;
                    const float v1 = (acc[mt][nt][rh*2+1] + bq[col+1]) * ATT_SCL;
                    *(uint32_t*)&Qs[(size_t)row * HID + col] = packh2(v0, v1);
                } else if (n0 < HID + KVW) {
                    const int c2 = col - HID;
                    const float v0 = acc[mt][nt][rh*2+0] + bk[c2];
                    const float v1 = acc[mt][nt][rh*2+1] + bk[c2+1];
                    *(uint32_t*)&Kh[(size_t)row * KVW + c2] = packh2(v0, v1);
                } else {
                    const int c2 = col - HID - KVW;
                    float2 v;
                    v.x = acc[mt][nt][rh*2+0] + bv[c2];
                    v.y = acc[mt][nt][rh*2+1] + bv[c2+1];
                    *(float2*)&Vo[(size_t)row * KVW + c2] = v;
                }
            }
        }
}

// ---------------------------------------------------------------------------
// O-projection GEMM (fp16 single-pass, fp32 out)
// ---------------------------------------------------------------------------
__global__ void __launch_bounds__(256)
gemm_o(const __half* __restrict__ Ah, const __half* __restrict__ Bh,
       const float* __restrict__ bias, float* __restrict__ C)
{
    extern __shared__ __align__(128) char smem[];
    const uint32_t smem_base = smem_to_u32(smem);
    const int tid  = threadIdx.x;
    const int warp = tid >> 5;
    const int lane = tid & 31;
    const int wm   = warp >> 2;
    const int wn   = warp & 3;
    const int m0   = blockIdx.y * 128;
    const int n0   = blockIdx.x * 128;

    GEMM_MAINLOOP_F16(Ah, Bh)

    #pragma unroll
    for (int mt = 0; mt < 4; ++mt)
        #pragma unroll
        for (int rh = 0; rh < 2; ++rh) {
            const int row = m0 + wm * 64 + mt * 16 + (lane >> 2) + rh * 8;
            #pragma unroll
            for (int nt = 0; nt < 4; ++nt) {
                const int col = n0 + wn * 32 + nt * 8 + (lane & 3) * 2;
                float2 v;
                v.x = acc[mt][nt][rh*2+0] + bias[col];
                v.y = acc[mt][nt][rh*2+1] + bias[col+1];
                *(float2*)&C[(size_t)row * HID + col] = v;
            }
        }
}

// ---------------------------------------------------------------------------
// fp16 FlashAttention: 128 q-rows x 64 kv tiles, 8 warps.
// Single-pass QK, single-pass PV. K+V+mask double-buffered; ONE sync per tile.
// __launch_bounds__(256, 2): cap regs at 128 -> 2 CTAs/SM (smem 2x107KB fits)
// so the serial softmax chain of one CTA overlaps the MMAs of the other.
// Grid (NH, SEQ/128, BATCH), qb reversed on slow axis => LPT.
// ---------------------------------------------------------------------------
#define QSTR 136
#define VSTR 72
#define SM_Q   0
#define SM_ST  34816                 // stage base (K tile then V tile)
#define STG_B  35840                 // 17408 (K) + 18432 (V)
#define SM_MK  (SM_ST + 2 * STG_B)   // 106496
#define ATTN_SMEM (SM_MK + 512)      // 107008

__global__ void __launch_bounds__(256, 2)
attn_hmma(const __half* __restrict__ Qs, const __half* __restrict__ Kh,
          const __half* __restrict__ VTh, const int* __restrict__ mask,
          __half* __restrict__ OH)
{
    extern __shared__ __align__(128) char sm[];
    const uint32_t base = smem_to_u32(sm);
    const int tid = threadIdx.x;
    const int w    = tid >> 5;
    const int lane = tid & 31;
    const int h  = blockIdx.x;
    const int qb = (int)gridDim.y - 1 - (int)blockIdx.y;   // heavy-first (LPT)
    const int b  = blockIdx.z;
    const int q0 = qb * 128;
    const int kvh = h >> 2;
    const int T = 2 * qb + 2;

    auto load_kv = [&](int t) {
        const int k0 = t * 64;
        const int s  = t & 1;
        const uint32_t kdst = base + SM_ST + s * STG_B;
        #pragma unroll
        for (int i = 0; i < 4; ++i) {
            const int idx = i * 256 + tid;
            const int row = idx >> 4, c = idx & 15;
            CP_ASYNC16(kdst + row * 272 + c * 16,
                       Kh + (size_t)(b * SEQ + k0 + row) * KVW + kvh * DH + c * 8);
        }
        const uint32_t vdst = kdst + 17408;
        #pragma unroll
        for (int i = 0; i < 4; ++i) {
            const int idx = i * 256 + tid;
            const int row = idx >> 3, c = idx & 7;
            CP_ASYNC16(vdst + row * 144 + c * 16,
                       VTh + (size_t)(b * KVW + kvh * DH + row) * SEQ + k0 + c * 8);
        }
        if (tid < 64)
            CP_ASYNC4(base + SM_MK + s * 256 + tid * 4, mask + b * SEQ + k0 + tid);
    };

    // prologue: Q + KV(0)
    #pragma unroll
    for (int i = 0; i < 8; ++i) {
        const int idx = i * 256 + tid;
        const int row = idx >> 4, c = idx & 15;
        CP_ASYNC16(base + SM_Q + row * 272 + c * 16,
                   Qs + (size_t)(b * SEQ + q0 + row) * HID + h * DH + c * 8);
    }
    load_kv(0);
    CP_COMMIT();

    float s[8][4];
    float o[16][4];
    #pragma unroll
    for (int j = 0; j < 16; ++j)
        #pragma unroll
        for (int c = 0; c < 4; ++c) o[j][c] = 0.f;
    float m0 = -1e30f, m1 = -1e30f, l0 = 0.f, l1 = 0.f;

    const int r0g = q0 + w * 16 + (lane >> 2);
    const int r1g = r0g + 8;
    const int c0l = (lane & 3) * 2;

    for (int t = 0; t < T; ++t) {
        const int k0 = t * 64;
        const int st = t & 1;
        const bool active = (q0 + w * 16 + 15) >= k0;

        CP_WAIT(0);
        __syncthreads();
        if (t + 1 < T) {
            load_kv(t + 1);
            CP_COMMIT();
        }

        if (active) {
            const uint32_t pK = base + SM_ST + st * STG_B;
            const uint32_t pV = pK + 17408;
            const int* mk_s = (const int*)(sm + SM_MK + st * 256);

            #pragma unroll
            for (int j = 0; j < 8; ++j)
                #pragma unroll
                for (int c = 0; c < 4; ++c) s[j][c] = 0.f;

            // S = Q*K
            #pragma unroll
            for (int kc = 0; kc < 8; ++kc) {
                const uint32_t offa =
                    ((w * 16 + (lane & 15)) * QSTR + kc * 16 + ((lane >> 4) << 3)) * 2;
                uint32_t aq[4];
                ldsm_x4(aq, base + SM_Q + offa);
                #pragma unroll
                for (int g = 0; g < 4; ++g) {
                    const uint32_t offb =
                        ((g * 16 + (lane & 7) + ((lane >> 4) << 3)) * QSTR +
                         kc * 16 + (((lane >> 3) & 1) << 3)) * 2;
                    uint32_t bh[4];
                    ldsm_x4(bh, pK + offb);
                    mma_f16(s[2*g],   aq, &bh[0]);
                    mma_f16(s[2*g+1], aq, &bh[2]);
                }
            }

            // mask + online softmax (base-2 domain)
            float mx0 = -1e30f, mx1 = -1e30f;
            #pragma unroll
            for (int j = 0; j < 8; ++j) {
                const int cg = k0 + j * 8 + c0l;
                const int mk0 = mk_s[j * 8 + c0l];
                const int mk1 = mk_s[j * 8 + c0l + 1];
                s[j][0] = (cg     <= r0g && mk0) ? s[j][0] : -1e30f;
                s[j][1] = (cg + 1 <= r0g && mk1) ? s[j][1] : -1e30f;
                s[j][2] = (cg     <= r1g && mk0) ? s[j][2] : -1e30f;
                s[j][3] = (cg + 1 <= r1g && mk1) ? s[j][3] : -1e30f;
                mx0 = fmaxf(mx0, fmaxf(s[j][0], s[j][1]));
                mx1 = fmaxf(mx1, fmaxf(s[j][2], s[j][3]));
            }
            mx0 = fmaxf(mx0, __shfl_xor_sync(0xffffffff, mx0, 1));
            mx0 = fmaxf(mx0, __shfl_xor_sync(0xffffffff, mx0, 2));
            mx1 = fmaxf(mx1, __shfl_xor_sync(0xffffffff, mx1, 1));
            mx1 = fmaxf(mx1, __shfl_xor_sync(0xffffffff, mx1, 2));
            const float mn0 = fmaxf(m0, mx0), mn1 = fmaxf(m1, mx1);
            const float f0 = ex2(m0 - mn0), f1 = ex2(m1 - mn1);
            m0 = mn0; m1 = mn1;
            float sum0 = 0.f, sum1 = 0.f;
            #pragma unroll
            for (int j = 0; j < 8; ++j) {
                s[j][0] = ex2(s[j][0] - mn0);
                s[j][1] = ex2(s[j][1] - mn0);
                s[j][2] = ex2(s[j][2] - mn1);
                s[j][3] = ex2(s[j][3] - mn1);
                sum0 += s[j][0] + s[j][1];
                sum1 += s[j][2] + s[j][3];
            }
            sum0 += __shfl_xor_sync(0xffffffff, sum0, 1);
            sum0 += __shfl_xor_sync(0xffffffff, sum0, 2);
            sum1 += __shfl_xor_sync(0xffffffff, sum1, 1);
            sum1 += __shfl_xor_sync(0xffffffff, sum1, 2);
            l0 = l0 * f0 + sum0;
            l1 = l1 * f1 + sum1;
            #pragma unroll
            for (int j = 0; j < 16; ++j) {
                o[j][0] *= f0; o[j][1] *= f0;
                o[j][2] *= f1; o[j][3] *= f1;
            }

            // O += P*V
            #pragma unroll
            for (int kc = 0; kc < 4; ++kc) {
                uint32_t ap[4];
                ap[0] = packh2(s[2*kc][0],   s[2*kc][1]);
                ap[1] = packh2(s[2*kc][2],   s[2*kc][3]);
                ap[2] = packh2(s[2*kc+1][0], s[2*kc+1][1]);
                ap[3] = packh2(s[2*kc+1][2], s[2*kc+1][3]);
                #pragma unroll
                for (int g = 0; g < 8; ++g) {
                    const uint32_t offb =
                        ((g * 16 + (lane & 7) + ((lane >> 4) << 3)) * VSTR +
                         kc * 16 + (((lane >> 3) & 1) << 3)) * 2;
                    uint32_t bh[4];
                    ldsm_x4(bh, pV + offb);
                    mma_f16(o[2*g],   ap, &bh[0]);
                    mma_f16(o[2*g+1], ap, &bh[2]);
                }
            }
        }
    }

    // epilogue: normalize, store single fp16
    const float inv0 = 1.f / l0, inv1 = 1.f / l1;
    const size_t base0 = (size_t)(b * SEQ + r0g) * HID + h * DH;
    const size_t base1 = (size_t)(b * SEQ + r1g) * HID + h * DH;
    #pragma unroll
    for (int j = 0; j < 16; ++j) {
        const int col = j * 8 + c0l;
        *(uint32_t*)&OH[base0 + col] = packh2(o[j][0] * inv0, o[j][1] * inv0);
        *(uint32_t*)&OH[base1 + col] = packh2(o[j][2] * inv1, o[j][3] * inv1);
    }
}

// ---------------------------------------------------------------------------
// Launch
// ---------------------------------------------------------------------------
extern "C" void kernel_launch(void* const* d_in, const int* in_sizes, int n_in,
                              void* d_out, int out_size)
{
    const float* x    = (const float*)d_in[0];
    const int*   mask = (const int*)  d_in[1];
    const float* Wq   = (const float*)d_in[2];
    const float* bq   = (const float*)d_in[3];
    const float* Wk   = (const float*)d_in[4];
    const float* bk   = (const float*)d_in[5];
    const float* Wv   = (const float*)d_in[6];
    const float* bv   = (const float*)d_in[7];
    const float* Wo   = (const float*)d_in[8];
    const float* bo   = (const float*)d_in[9];
    float* out = (float*)d_out;

    void *pv, *pxh, *pqs, *pkh, *pvth, *pah, *pwh, *pwoh;
    cudaGetSymbolAddress(&pv,  g_v);
    cudaGetSymbolAddress(&pxh, g_xh);
    cudaGetSymbolAddress(&pqs, g_qs);
    cudaGetSymbolAddress(&pkh, g_kh);
    cudaGetSymbolAddress(&pvth, g_vth);
    cudaGetSymbolAddress(&pah, g_ah);
    cudaGetSymbolAddress(&pwh, g_wh);
    cudaGetSymbolAddress(&pwoh, g_woh);

    __half* wh = (__half*)pwh;

    // --- converters ---
    const int n4 = MTOT * HID / 4;
    xcvt_kernel<<<n4 / 256, 256>>>(x, (__half*)pxh, n4);
    dim3 tb(32, 8);
    wconvT_kernel<<<dim3(160, GEMM_K / 32), tb>>>(
        Wq, Wk, Wv, Wo, wh, (__half*)pwoh);

    // --- fused QKV projection (fp16 single-pass, 3-stage pipeline) ---
    const int gemm_smem = 3 * STAGE_B;   // 61440
    cudaFuncSetAttribute(gemm_qkv, cudaFuncAttributeMaxDynamicSharedMemorySize,
                         gemm_smem);
    cudaFuncSetAttribute(gemm_o, cudaFuncAttributeMaxDynamicSharedMemorySize,
                         gemm_smem);
    gemm_qkv<<<dim3(NQKV / 128, MTOT / 128), 256, gemm_smem>>>(
        (const __half*)pxh, wh, bq, bk, bv,
        (__half*)pqs, (__half*)pkh, (float*)pv);

    // --- V transpose (single fp16) ---
    vsplitT_kernel<<<dim3(KVW / 32, SEQ / 32, BATCH), tb>>>(
        (const float*)pv, (__half*)pvth);

    // --- fp16 flash attention (2 CTAs/SM target) ---
    cudaFuncSetAttribute(attn_hmma, cudaFuncAttributeMaxDynamicSharedMemorySize,
                         ATTN_SMEM);
    attn_hmma<<<dim3(NH, SEQ / 128, BATCH), 256, ATTN_SMEM>>>(
        (const __half*)pqs, (const __half*)pkh, (const __half*)pvth,
        mask, (__half*)pah);

    // --- output projection (fp16 single-pass) ---
    gemm_o<<<dim3(HID / 128, MTOT / 128), 256, gemm_smem>>>(
        (const __half*)pah, (__half*)pwoh, bo, out);
}

// round 13
// speedup vs baseline: 2.9042x; 1.1178x over previous
#include <cuda_runtime.h>
#include <cuda_bf16.h>
#include <cuda_fp16.h>
#include <cstdint>
#include <math.h>

// ---------------------------------------------------------------------------
// Problem constants
// ---------------------------------------------------------------------------
#define BATCH   2
#define SEQ     2048
#define HID     2048
#define NH      16
#define NKV     4
#define DH      128
#define KVW     (NKV * DH)          // 512
#define MTOT    (BATCH * SEQ)       // 4096
#define GROUPS  (NH / NKV)          // 4
#define GEMM_K  2048
#define NQKV    (HID + 2 * KVW)     // 3072

// ---------------------------------------------------------------------------
// PTX helpers — ONLY non-'a' features (mma.sync / ldmatrix / cp.async).
// ---------------------------------------------------------------------------
__device__ __forceinline__ uint32_t smem_to_u32(const void* p) {
    uint32_t a;
    asm("{ .reg .u64 t; cvta.to.shared.u64 t, %1; cvt.u32.u64 %0, t; }"
        : "=r"(a) : "l"(p));
    return a;
}
#define CP_ASYNC16(dst, src) \
    asm volatile("cp.async.cg.shared.global [%0], [%1], 16;" \
                 :: "r"(dst), "l"(src))
#define CP_ASYNC4(dst, src) \
    asm volatile("cp.async.ca.shared.global [%0], [%1], 4;" \
                 :: "r"(dst), "l"(src))
#define CP_COMMIT() asm volatile("cp.async.commit_group;")
#define CP_WAIT(n)  asm volatile("cp.async.wait_group %0;" :: "n"(n))

__device__ __forceinline__ void ldsm_x4(uint32_t* r, uint32_t addr) {
    asm volatile("ldmatrix.sync.aligned.m8n8.x4.shared.b16 {%0,%1,%2,%3}, [%4];"
                 : "=r"(r[0]), "=r"(r[1]), "=r"(r[2]), "=r"(r[3]) : "r"(addr));
}
__device__ __forceinline__ void mma_f16(float* d, const uint32_t* a,
                                        const uint32_t* b) {
    asm volatile(
        "mma.sync.aligned.m16n8k16.row.col.f32.f16.f16.f32 "
        "{%0,%1,%2,%3}, {%4,%5,%6,%7}, {%8,%9}, {%0,%1,%2,%3};"
        : "+f"(d[0]), "+f"(d[1]), "+f"(d[2]), "+f"(d[3])
        : "r"(a[0]), "r"(a[1]), "r"(a[2]), "r"(a[3]), "r"(b[0]), "r"(b[1]));
}
__device__ __forceinline__ uint32_t packh2(float x, float y) {
    __half2 h(__float2half(x), __float2half(y));
    return *reinterpret_cast<uint32_t*>(&h);
}
__device__ __forceinline__ float ex2(float x) {
    float r;
    asm("ex2.approx.f32 %0, %1;" : "=f"(r) : "f"(x));
    return r;
}

// ---------------------------------------------------------------------------
// Scratch buffers
// ---------------------------------------------------------------------------
__device__ float g_v[(size_t)MTOT * KVW];
__device__ __half g_xh[(size_t)MTOT * HID];           // x single fp16
__device__ __half g_qs[(size_t)MTOT * HID];           // q single fp16 (pre-scaled)
__device__ __half g_kh[(size_t)MTOT * KVW];           // k single fp16
__device__ __half g_vth[(size_t)MTOT * KVW];          // VT single fp16 [B*KVW, SEQ]
__device__ __half g_ah[(size_t)MTOT * HID];           // attn out fp16
__device__ __half g_wh[(size_t)NQKV * HID];           // [Wq;Wk;Wv] T, single fp16
__device__ __half g_woh[(size_t)HID * HID];           // Wo T, single fp16

// ---------------------------------------------------------------------------
// Converters
// ---------------------------------------------------------------------------
__global__ void xcvt_kernel(const float* __restrict__ in,
                            __half* __restrict__ hi, int n4)
{
    int i = blockIdx.x * blockDim.x + threadIdx.x;
    if (i >= n4) return;
    float4 v = ((const float4*)in)[i];
    __half2 a(__float2half(v.x), __float2half(v.y));
    __half2 b(__float2half(v.z), __float2half(v.w));
    ((__half2*)hi)[2*i]   = a;
    ((__half2*)hi)[2*i+1] = b;
}

// All four weight matrices transposed to single fp16 in ONE launch.
__global__ void wconvT_kernel(const float* __restrict__ Wq,
                              const float* __restrict__ Wk,
                              const float* __restrict__ Wv,
                              const float* __restrict__ Wo,
                              __half* __restrict__ wh,
                              __half* __restrict__ woh)
{
    const int bx = blockIdx.x;
    const float* W;
    __half* Th;
    int N, nblk;
    if (bx < 64)      { W = Wq; Th = wh;  N = HID; nblk = bx; }
    else if (bx < 80) { W = Wk; Th = wh + (size_t)HID * GEMM_K;  N = KVW; nblk = bx - 64; }
    else if (bx < 96) { W = Wv; Th = wh + (size_t)(HID + KVW) * GEMM_K; N = KVW; nblk = bx - 80; }
    else              { W = Wo; Th = woh; N = HID; nblk = bx - 96; }

    __shared__ float t[32][33];
    const int n  = nblk * 32 + threadIdx.x;
    const int kb = blockIdx.y * 32;
    #pragma unroll
    for (int j = 0; j < 32; j += 8)
        t[threadIdx.y + j][threadIdx.x] = W[(size_t)(kb + threadIdx.y + j) * N + n];
    __syncthreads();
    const int k  = kb + threadIdx.x;
    const int nb = nblk * 32;
    #pragma unroll
    for (int j = 0; j < 32; j += 8) {
        float v = t[threadIdx.x][threadIdx.y + j];
        Th[(size_t)(nb + threadIdx.y + j) * GEMM_K + k] = __float2half(v);
    }
}

// V [B*SEQ, KVW] fp32 -> VT [B*KVW, SEQ] single fp16
__global__ void vsplitT_kernel(const float* __restrict__ V,
                               __half* __restrict__ Th)
{
    __shared__ float t[32][33];
    const int n0 = blockIdx.x * 32;
    const int s0 = blockIdx.y * 32;
    const int b  = blockIdx.z;
    #pragma unroll
    for (int j = 0; j < 32; j += 8)
        t[threadIdx.y + j][threadIdx.x] =
            V[(size_t)(b * SEQ + s0 + threadIdx.y + j) * KVW + n0 + threadIdx.x];
    __syncthreads();
    #pragma unroll
    for (int j = 0; j < 32; j += 8) {
        float v = t[threadIdx.x][threadIdx.y + j];
        size_t o = (size_t)(b * KVW + n0 + threadIdx.y + j) * SEQ + s0 + threadIdx.x;
        Th[o] = __float2half(v);
    }
}

// ---------------------------------------------------------------------------
// fp16 HMMA GEMM mainloop: C = A[M,K] @ B^T[N,K]  (single-pass, 2 smem mats)
// KC=64 chunks (overhead amortized 2x), 3-stage pipeline, ONE sync per chunk.
// Row stride 72 halfs (144B): ldsm rows hit distinct banks, 16B aligned.
// ---------------------------------------------------------------------------
#define KC        64
#define AS_STRIDE 72
#define MAT_B     (128 * AS_STRIDE * 2)   // 18432 bytes
#define STAGE_B   (2 * MAT_B)             // 36864 bytes
#define NCHUNK    (GEMM_K / KC)           // 32

#define GEMM_MAINLOOP_F16(AhP, BhP)                                             \
    float acc[4][4][4];                                                         \
    _Pragma("unroll")                                                           \
    for (int a = 0; a < 4; ++a)                                                 \
        _Pragma("unroll")                                                       \
        for (int b2 = 0; b2 < 4; ++b2)                                          \
            _Pragma("unroll")                                                   \
            for (int c = 0; c < 4; ++c) acc[a][b2][c] = 0.f;                    \
    const __half* mats[2] = {AhP, BhP};                                         \
    auto load_stage = [&](int s, int k0) {                                      \
        const uint32_t st = smem_base + s * STAGE_B;                            \
        _Pragma("unroll")                                                       \
        for (int mat = 0; mat < 2; ++mat) {                                     \
            const __half* src = mats[mat];                                      \
            const int r0 = (mat < 1) ? m0 : n0;                                 \
            const uint32_t dstb = st + mat * MAT_B;                             \
            _Pragma("unroll")                                                   \
            for (int it = 0; it < 4; ++it) {                                    \
                const int idx = it * 256 + tid;                                 \
                const int row = idx >> 3;                                       \
                const int k8  = idx & 7;                                        \
                const void* sp = src + (size_t)(r0 + row) * GEMM_K + k0 + k8*8; \
                const uint32_t dp = dstb + row * (AS_STRIDE * 2) + k8 * 16;     \
                CP_ASYNC16(dp, sp);                                             \
            }                                                                   \
        }                                                                       \
    };                                                                          \
    load_stage(0, 0);                                                           \
    CP_COMMIT();                                                                \
    load_stage(1, KC);                                                          \
    CP_COMMIT();                                                                \
    for (int c = 0; c < NCHUNK; ++c) {                                          \
        if (c + 1 < NCHUNK) { CP_WAIT(1); } else { CP_WAIT(0); }                \
        __syncthreads();                                                        \
        if (c + 2 < NCHUNK) {                                                   \
            load_stage((c + 2) % 3, (c + 2) * KC);                              \
            CP_COMMIT();                                                        \
        }                                                                       \
        const uint32_t stg = smem_base + (c % 3) * STAGE_B;                     \
        const uint32_t pA  = stg;                                               \
        const uint32_t pB  = stg + MAT_B;                                       \
        _Pragma("unroll")                                                       \
        for (int ks = 0; ks < 4; ++ks) {                                        \
            const int kcol = ks * 16;                                           \
            uint32_t bh[8];                                                     \
            _Pragma("unroll")                                                   \
            for (int p = 0; p < 2; ++p) {                                       \
                const int nrow = wn * 32 + p * 16 + (lane & 7) + ((lane>>4)<<3);\
                const int kk   = kcol + (((lane >> 3) & 1) << 3);               \
                const uint32_t off = (nrow * AS_STRIDE + kk) * 2;               \
                ldsm_x4(&bh[p * 4], pB + off);                                  \
            }                                                                   \
            _Pragma("unroll")                                                   \
            for (int mt = 0; mt < 4; ++mt) {                                    \
                const int mrow = wm * 64 + mt * 16 + (lane & 15);               \
                const int kk2  = kcol + ((lane >> 4) << 3);                     \
                const uint32_t offa = (mrow * AS_STRIDE + kk2) * 2;             \
                uint32_t afr[4];                                                \
                ldsm_x4(afr, pA + offa);                                        \
                _Pragma("unroll")                                               \
                for (int nt = 0; nt < 4; ++nt) mma_f16(acc[mt][nt], afr, &bh[nt*2]); \
            }                                                                   \
        }                                                                       \
    }

// ---------------------------------------------------------------------------
// Fused QKV projection: q -> single fp16 (pre-scaled by scl*log2e),
// k -> single fp16, v -> fp32.
// ---------------------------------------------------------------------------
#define ATT_SCL (0.08838834764831845f * 1.4426950408889634f)

__global__ void __launch_bounds__(256, 2)
gemm_qkv(const __half* __restrict__ Ah, const __half* __restrict__ Bh,
         const float* __restrict__ bq, const float* __restrict__ bk,
         const float* __restrict__ bv,
         __half* __restrict__ Qs, __half* __restrict__ Kh,
         float* __restrict__ Vo)
{
    extern __shared__ __align__(128) char smem[];
    const uint32_t smem_base = smem_to_u32(smem);
    const int tid  = threadIdx.x;
    const int warp = tid >> 5;
    const int lane = tid & 31;
    const int wm   = warp >> 2;
    const int wn   = warp & 3;
    const int m0   = blockIdx.y * 128;
    const int n0   = blockIdx.x * 128;

    GEMM_MAINLOOP_F16(Ah, Bh)

    #pragma unroll
    for (int mt = 0; mt < 4; ++mt)
        #pragma unroll
        for (int rh = 0; rh < 2; ++rh) {
            const int row = m0 + wm * 64 + mt * 16 + (lane >> 2) + rh * 8;
            #pragma unroll
            for (int nt = 0; nt < 4; ++nt) {
                const int col = n0 + wn * 32 + nt * 8 + (lane & 3) * 2;
                if (n0 < HID) {
                    const float v0 = (acc[mt][nt][rh*2+0] + bq[col])   * ATT_SCL;
                    const float v1 = (acc[mt][nt][rh*2+1] + bq[col+1]) * ATT_SCL;
                    *(uint32_t*)&Qs[(size_t)row * HID + col] = packh2(v0, v1);
                } else if (n0 < HID + KVW) {
                    const int c2 = col - HID;
                    const float v0 = acc[mt][nt][rh*2+0] + bk[c2];
                    const float v1 = acc[mt][nt][rh*2+1] + bk[c2+1];
                    *(uint32_t*)&Kh[(size_t)row * KVW + c2] = packh2(v0, v1);
                } else {
                    const int c2 = col - HID - KVW;
                    float2 v;
                    v.x = acc[mt][nt][rh*2+0] + bv[c2];
                    v.y = acc[mt][nt][rh*2+1] + bv[c2+1];
                    *(float2*)&Vo[(size_t)row * KVW + c2] = v;
                }
            }
        }
}

// ---------------------------------------------------------------------------
// O-projection GEMM (fp16 single-pass, fp32 out)
// ---------------------------------------------------------------------------
__global__ void __launch_bounds__(256, 2)
gemm_o(const __half* __restrict__ Ah, const __half* __restrict__ Bh,
       const float* __restrict__ bias, float* __restrict__ C)
{
    extern __shared__ __align__(128) char smem[];
    const uint32_t smem_base = smem_to_u32(smem);
    const int tid  = threadIdx.x;
    const int warp = tid >> 5;
    const int lane = tid & 31;
    const int wm   = warp >> 2;
    const int wn   = warp & 3;
    const int m0   = blockIdx.y * 128;
    const int n0   = blockIdx.x * 128;

    GEMM_MAINLOOP_F16(Ah, Bh)

    #pragma unroll
    for (int mt = 0; mt < 4; ++mt)
        #pragma unroll
        for (int rh = 0; rh < 2; ++rh) {
            const int row = m0 + wm * 64 + mt * 16 + (lane >> 2) + rh * 8;
            #pragma unroll
            for (int nt = 0; nt < 4; ++nt) {
                const int col = n0 + wn * 32 + nt * 8 + (lane & 3) * 2;
                float2 v;
                v.x = acc[mt][nt][rh*2+0] + bias[col];
                v.y = acc[mt][nt][rh*2+1] + bias[col+1];
                *(float2*)&C[(size_t)row * HID + col] = v;
            }
        }
}

// ---------------------------------------------------------------------------
// fp16 FlashAttention: 128 q-rows x 64 kv tiles, 8 warps.
// Single-pass QK, single-pass PV. K+V+mask double-buffered; ONE sync per tile.
// __launch_bounds__(256, 2): 2 CTAs/SM. Grid (NH, SEQ/128, BATCH), qb reversed
// on slow axis => LPT scheduling.
// ---------------------------------------------------------------------------
#define QSTR 136
#define VSTR 72
#define SM_Q   0
#define SM_ST  34816                 // stage base (K tile then V tile)
#define STG_B  35840                 // 17408 (K) + 18432 (V)
#define SM_MK  (SM_ST + 2 * STG_B)   // 106496
#define ATTN_SMEM (SM_MK + 512)      // 107008

__global__ void __launch_bounds__(256, 2)
attn_hmma(const __half* __restrict__ Qs, const __half* __restrict__ Kh,
          const __half* __restrict__ VTh, const int* __restrict__ mask,
          __half* __restrict__ OH)
{
    extern __shared__ __align__(128) char sm[];
    const uint32_t base = smem_to_u32(sm);
    const int tid = threadIdx.x;
    const int w    = tid >> 5;
    const int lane = tid & 31;
    const int h  = blockIdx.x;
    const int qb = (int)gridDim.y - 1 - (int)blockIdx.y;   // heavy-first (LPT)
    const int b  = blockIdx.z;
    const int q0 = qb * 128;
    const int kvh = h >> 2;
    const int T = 2 * qb + 2;

    auto load_kv = [&](int t) {
        const int k0 = t * 64;
        const int s  = t & 1;
        const uint32_t kdst = base + SM_ST + s * STG_B;
        #pragma unroll
        for (int i = 0; i < 4; ++i) {
            const int idx = i * 256 + tid;
            const int row = idx >> 4, c = idx & 15;
            CP_ASYNC16(kdst + row * 272 + c * 16,
                       Kh + (size_t)(b * SEQ + k0 + row) * KVW + kvh * DH + c * 8);
        }
        const uint32_t vdst = kdst + 17408;
        #pragma unroll
        for (int i = 0; i < 4; ++i) {
            const int idx = i * 256 + tid;
            const int row = idx >> 3, c = idx & 7;
            CP_ASYNC16(vdst + row * 144 + c * 16,
                       VTh + (size_t)(b * KVW + kvh * DH + row) * SEQ + k0 + c * 8);
        }
        if (tid < 64)
            CP_ASYNC4(base + SM_MK + s * 256 + tid * 4, mask + b * SEQ + k0 + tid);
    };

    // prologue: Q + KV(0)
    #pragma unroll
    for (int i = 0; i < 8; ++i) {
        const int idx = i * 256 + tid;
        const int row = idx >> 4, c = idx & 15;
        CP_ASYNC16(base + SM_Q + row * 272 + c * 16,
                   Qs + (size_t)(b * SEQ + q0 + row) * HID + h * DH + c * 8);
    }
    load_kv(0);
    CP_COMMIT();

    float s[8][4];
    float o[16][4];
    #pragma unroll
    for (int j = 0; j < 16; ++j)
        #pragma unroll
        for (int c = 0; c < 4; ++c) o[j][c] = 0.f;
    float m0 = -1e30f, m1 = -1e30f, l0 = 0.f, l1 = 0.f;

    const int r0g = q0 + w * 16 + (lane >> 2);
    const int r1g = r0g + 8;
    const int c0l = (lane & 3) * 2;

    for (int t = 0; t < T; ++t) {
        const int k0 = t * 64;
        const int st = t & 1;
        const bool active = (q0 + w * 16 + 15) >= k0;

        CP_WAIT(0);
        __syncthreads();
        if (t + 1 < T) {
            load_kv(t + 1);
            CP_COMMIT();
        }

        if (active) {
            const uint32_t pK = base + SM_ST + st * STG_B;
            const uint32_t pV = pK + 17408;
            const int* mk_s = (const int*)(sm + SM_MK + st * 256);

            #pragma unroll
            for (int j = 0; j < 8; ++j)
                #pragma unroll
                for (int c = 0; c < 4; ++c) s[j][c] = 0.f;

            // S = Q*K
            #pragma unroll
            for (int kc = 0; kc < 8; ++kc) {
                const uint32_t offa =
                    ((w * 16 + (lane & 15)) * QSTR + kc * 16 + ((lane >> 4) << 3)) * 2;
                uint32_t aq[4];
                ldsm_x4(aq, base + SM_Q + offa);
                #pragma unroll
                for (int g = 0; g < 4; ++g) {
                    const uint32_t offb =
                        ((g * 16 + (lane & 7) + ((lane >> 4) << 3)) * QSTR +
                         kc * 16 + (((lane >> 3) & 1) << 3)) * 2;
                    uint32_t bh[4];
                    ldsm_x4(bh, pK + offb);
                    mma_f16(s[2*g],   aq, &bh[0]);
                    mma_f16(s[2*g+1], aq, &bh[2]);
                }
            }

            // mask + online softmax (base-2 domain)
            float mx0 = -1e30f, mx1 = -1e30f;
            #pragma unroll
            for (int j = 0; j < 8; ++j) {
                const int cg = k0 + j * 8 + c0l;
                const int mk0 = mk_s[j * 8 + c0l];
                const int mk1 = mk_s[j * 8 + c0l + 1];
                s[j][0] = (cg     <= r0g && mk0) ? s[j][0] : -1e30f;
                s[j][1] = (cg + 1 <= r0g && mk1) ? s[j][1] : -1e30f;
                s[j][2] = (cg     <= r1g && mk0) ? s[j][2] : -1e30f;
                s[j][3] = (cg + 1 <= r1g && mk1) ? s[j][3] : -1e30f;
                mx0 = fmaxf(mx0, fmaxf(s[j][0], s[j][1]));
                mx1 = fmaxf(mx1, fmaxf(s[j][2], s[j][3]));
            }
            mx0 = fmaxf(mx0, __shfl_xor_sync(0xffffffff, mx0, 1));
            mx0 = fmaxf(mx0, __shfl_xor_sync(0xffffffff, mx0, 2));
            mx1 = fmaxf(mx1, __shfl_xor_sync(0xffffffff, mx1, 1));
            mx1 = fmaxf(mx1, __shfl_xor_sync(0xffffffff, mx1, 2));
            const float mn0 = fmaxf(m0, mx0), mn1 = fmaxf(m1, mx1);
            const float f0 = ex2(m0 - mn0), f1 = ex2(m1 - mn1);
            m0 = mn0; m1 = mn1;
            float sum0 = 0.f, sum1 = 0.f;
            #pragma unroll
            for (int j = 0; j < 8; ++j) {
                s[j][0] = ex2(s[j][0] - mn0);
                s[j][1] = ex2(s[j][1] - mn0);
                s[j][2] = ex2(s[j][2] - mn1);
                s[j][3] = ex2(s[j][3] - mn1);
                sum0 += s[j][0] + s[j][1];
                sum1 += s[j][2] + s[j][3];
            }
            sum0 += __shfl_xor_sync(0xffffffff, sum0, 1);
            sum0 += __shfl_xor_sync(0xffffffff, sum0, 2);
            sum1 += __shfl_xor_sync(0xffffffff, sum1, 1);
            sum1 += __shfl_xor_sync(0xffffffff, sum1, 2);
            l0 = l0 * f0 + sum0;
            l1 = l1 * f1 + sum1;
            #pragma unroll
            for (int j = 0; j < 16; ++j) {
                o[j][0] *= f0; o[j][1] *= f0;
                o[j][2] *= f1; o[j][3] *= f1;
            }

            // O += P*V
            #pragma unroll
            for (int kc = 0; kc < 4; ++kc) {
                uint32_t ap[4];
                ap[0] = packh2(s[2*kc][0],   s[2*kc][1]);
                ap[1] = packh2(s[2*kc][2],   s[2*kc][3]);
                ap[2] = packh2(s[2*kc+1][0], s[2*kc+1][1]);
                ap[3] = packh2(s[2*kc+1][2], s[2*kc+1][3]);
                #pragma unroll
                for (int g = 0; g < 8; ++g) {
                    const uint32_t offb =
                        ((g * 16 + (lane & 7) + ((lane >> 4) << 3)) * VSTR +
                         kc * 16 + (((lane >> 3) & 1) << 3)) * 2;
                    uint32_t bh[4];
                    ldsm_x4(bh, pV + offb);
                    mma_f16(o[2*g],   ap, &bh[0]);
                    mma_f16(o[2*g+1], ap, &bh[2]);
                }
            }
        }
    }

    // epilogue: normalize, store single fp16
    const float inv0 = 1.f / l0, inv1 = 1.f / l1;
    const size_t base0 = (size_t)(b * SEQ + r0g) * HID + h * DH;
    const size_t base1 = (size_t)(b * SEQ + r1g) * HID + h * DH;
    #pragma unroll
    for (int j = 0; j < 16; ++j) {
        const int col = j * 8 + c0l;
        *(uint32_t*)&OH[base0 + col] = packh2(o[j][0] * inv0, o[j][1] * inv0);
        *(uint32_t*)&OH[base1 + col] = packh2(o[j][2] * inv1, o[j][3] * inv1);
    }
}

// ---------------------------------------------------------------------------
// Launch
// ---------------------------------------------------------------------------
extern "C" void kernel_launch(void* const* d_in, const int* in_sizes, int n_in,
                              void* d_out, int out_size)
{
    const float* x    = (const float*)d_in[0];
    const int*   mask = (const int*)  d_in[1];
    const float* Wq   = (const float*)d_in[2];
    const float* bq   = (const float*)d_in[3];
    const float* Wk   = (const float*)d_in[4];
    const float* bk   = (const float*)d_in[5];
    const float* Wv   = (const float*)d_in[6];
    const float* bv   = (const float*)d_in[7];
    const float* Wo   = (const float*)d_in[8];
    const float* bo   = (const float*)d_in[9];
    float* out = (float*)d_out;

    void *pv, *pxh, *pqs, *pkh, *pvth, *pah, *pwh, *pwoh;
    cudaGetSymbolAddress(&pv,  g_v);
    cudaGetSymbolAddress(&pxh, g_xh);
    cudaGetSymbolAddress(&pqs, g_qs);
    cudaGetSymbolAddress(&pkh, g_kh);
    cudaGetSymbolAddress(&pvth, g_vth);
    cudaGetSymbolAddress(&pah, g_ah);
    cudaGetSymbolAddress(&pwh, g_wh);
    cudaGetSymbolAddress(&pwoh, g_woh);

    __half* wh = (__half*)pwh;

    // --- converters ---
    const int n4 = MTOT * HID / 4;
    xcvt_kernel<<<n4 / 256, 256>>>(x, (__half*)pxh, n4);
    dim3 tb(32, 8);
    wconvT_kernel<<<dim3(160, GEMM_K / 32), tb>>>(
        Wq, Wk, Wv, Wo, wh, (__half*)pwoh);

    // --- fused QKV projection (fp16 single-pass, KC=64, 3-stage) ---
    const int gemm_smem = 3 * STAGE_B;   // 110592
    cudaFuncSetAttribute(gemm_qkv, cudaFuncAttributeMaxDynamicSharedMemorySize,
                         gemm_smem);
    cudaFuncSetAttribute(gemm_o, cudaFuncAttributeMaxDynamicSharedMemorySize,
                         gemm_smem);
    gemm_qkv<<<dim3(NQKV / 128, MTOT / 128), 256, gemm_smem>>>(
        (const __half*)pxh, wh, bq, bk, bv,
        (__half*)pqs, (__half*)pkh, (float*)pv);

    // --- V transpose (single fp16) ---
    vsplitT_kernel<<<dim3(KVW / 32, SEQ / 32, BATCH), tb>>>(
        (const float*)pv, (__half*)pvth);

    // --- fp16 flash attention (2 CTAs/SM) ---
    cudaFuncSetAttribute(attn_hmma, cudaFuncAttributeMaxDynamicSharedMemorySize,
                         ATTN_SMEM);
    attn_hmma<<<dim3(NH, SEQ / 128, BATCH), 256, ATTN_SMEM>>>(
        (const __half*)pqs, (const __half*)pkh, (const __half*)pvth,
        mask, (__half*)pah);

    // --- output projection (fp16 single-pass, KC=64, 3-stage) ---
    gemm_o<<<dim3(HID / 128, MTOT / 128), 256, gemm_smem>>>(
        (const __half*)pah, (__half*)pwoh, bo, out);
}

// round 14
// speedup vs baseline: 2.9697x; 1.0226x over previous
#include <cuda_runtime.h>
#include <cuda_bf16.h>
#include <cuda_fp16.h>
#include <cstdint>
#include <math.h>

// ---------------------------------------------------------------------------
// Problem constants
// ---------------------------------------------------------------------------
#define BATCH   2
#define SEQ     2048
#define HID     2048
#define NH      16
#define NKV     4
#define DH      128
#define KVW     (NKV * DH)          // 512
#define MTOT    (BATCH * SEQ)       // 4096
#define GROUPS  (NH / NKV)          // 4
#define GEMM_K  2048
#define NQKV    (HID + 2 * KVW)     // 3072

// ---------------------------------------------------------------------------
// PTX helpers — ONLY non-'a' features (mma.sync / ldmatrix / cp.async).
// ---------------------------------------------------------------------------
__device__ __forceinline__ uint32_t smem_to_u32(const void* p) {
    uint32_t a;
    asm("{ .reg .u64 t; cvta.to.shared.u64 t, %1; cvt.u32.u64 %0, t; }"
        : "=r"(a) : "l"(p));
    return a;
}
#define CP_ASYNC16(dst, src) \
    asm volatile("cp.async.cg.shared.global [%0], [%1], 16;" \
                 :: "r"(dst), "l"(src))
#define CP_ASYNC4(dst, src) \
    asm volatile("cp.async.ca.shared.global [%0], [%1], 4;" \
                 :: "r"(dst), "l"(src))
#define CP_COMMIT() asm volatile("cp.async.commit_group;")
#define CP_WAIT(n)  asm volatile("cp.async.wait_group %0;" :: "n"(n))

__device__ __forceinline__ void ldsm_x4(uint32_t* r, uint32_t addr) {
    asm volatile("ldmatrix.sync.aligned.m8n8.x4.shared.b16 {%0,%1,%2,%3}, [%4];"
                 : "=r"(r[0]), "=r"(r[1]), "=r"(r[2]), "=r"(r[3]) : "r"(addr));
}
__device__ __forceinline__ void mma_f16(float* d, const uint32_t* a,
                                        const uint32_t* b) {
    asm volatile(
        "mma.sync.aligned.m16n8k16.row.col.f32.f16.f16.f32 "
        "{%0,%1,%2,%3}, {%4,%5,%6,%7}, {%8,%9}, {%0,%1,%2,%3};"
        : "+f"(d[0]), "+f"(d[1]), "+f"(d[2]), "+f"(d[3])
        : "r"(a[0]), "r"(a[1]), "r"(a[2]), "r"(a[3]), "r"(b[0]), "r"(b[1]));
}
__device__ __forceinline__ uint32_t packh2(float x, float y) {
    __half2 h(__float2half(x), __float2half(y));
    return *reinterpret_cast<uint32_t*>(&h);
}
__device__ __forceinline__ float ex2(float x) {
    float r;
    asm("ex2.approx.f32 %0, %1;" : "=f"(r) : "f"(x));
    return r;
}

// ---------------------------------------------------------------------------
// Scratch buffers
// ---------------------------------------------------------------------------
__device__ __half g_xh[(size_t)MTOT * HID];           // x single fp16
__device__ __half g_qs[(size_t)MTOT * HID];           // q single fp16 (pre-scaled)
__device__ __half g_kh[(size_t)MTOT * KVW];           // k single fp16
__device__ __half g_vth[(size_t)MTOT * KVW];          // VT single fp16 [B*KVW, SEQ]
__device__ __half g_ah[(size_t)MTOT * HID];           // attn out fp16
__device__ __half g_wh[(size_t)NQKV * HID];           // [Wq;Wk;Wv] T, single fp16
__device__ __half g_woh[(size_t)HID * HID];           // Wo T, single fp16

// ---------------------------------------------------------------------------
// Single merged converter: x -> fp16 AND all 4 weights transposed -> fp16.
// blocks [0, 10240): weight transpose (wmat = bx/64 in [0,160), by = bx%64)
// blocks [10240, 18432): x elementwise (float4 per thread)
// ---------------------------------------------------------------------------
#define WCONV_BLOCKS (160 * 64)
#define XCONV_BLOCKS (MTOT * HID / 4 / 256)   // 8192

__global__ void conv_kernel(const float* __restrict__ x,
                            const float* __restrict__ Wq,
                            const float* __restrict__ Wk,
                            const float* __restrict__ Wv,
                            const float* __restrict__ Wo,
                            __half* __restrict__ xh,
                            __half* __restrict__ wh,
                            __half* __restrict__ woh)
{
    const int bx  = blockIdx.x;
    const int tid = threadIdx.x;

    if (bx >= WCONV_BLOCKS) {
        // x conversion
        const int i = (bx - WCONV_BLOCKS) * 256 + tid;
        float4 v = ((const float4*)x)[i];
        ((uint32_t*)xh)[2*i]   = packh2(v.x, v.y);
        ((uint32_t*)xh)[2*i+1] = packh2(v.z, v.w);
        return;
    }

    // weight transpose
    const int wmat = bx >> 6;          // 0..159
    const int by   = bx & 63;
    const float* W;
    __half* Th;
    int N, nblk;
    if (wmat < 64)      { W = Wq; Th = wh;  N = HID; nblk = wmat; }
    else if (wmat < 80) { W = Wk; Th = wh + (size_t)HID * GEMM_K;  N = KVW; nblk = wmat - 64; }
    else if (wmat < 96) { W = Wv; Th = wh + (size_t)(HID + KVW) * GEMM_K; N = KVW; nblk = wmat - 80; }
    else                { W = Wo; Th = woh; N = HID; nblk = wmat - 96; }

    __shared__ float t[32][33];
    const int tx = tid & 31, ty = tid >> 5;
    const int n  = nblk * 32 + tx;
    const int kb = by * 32;
    #pragma unroll
    for (int j = 0; j < 32; j += 8)
        t[ty + j][tx] = W[(size_t)(kb + ty + j) * N + n];
    __syncthreads();
    const int k  = kb + tx;
    const int nb = nblk * 32;
    #pragma unroll
    for (int j = 0; j < 32; j += 8) {
        float v = t[tx][ty + j];
        Th[(size_t)(nb + ty + j) * GEMM_K + k] = __float2half(v);
    }
}

// ---------------------------------------------------------------------------
// fp16 HMMA GEMM mainloop: C = A[M,K] @ B^T[N,K]  (single-pass, 2 smem mats)
// KC=64 chunks, 3-stage pipeline, ONE sync per chunk, bias prefetched to smem.
// ---------------------------------------------------------------------------
#define KC        64
#define AS_STRIDE 72
#define MAT_B     (128 * AS_STRIDE * 2)   // 18432 bytes
#define STAGE_B   (2 * MAT_B)             // 36864 bytes
#define NCHUNK    (GEMM_K / KC)           // 32
#define SM_BIAS   (3 * STAGE_B)           // 110592
#define GEMM_SMEM (SM_BIAS + 512)         // 111104

#define GEMM_MAINLOOP_F16(AhP, BhP, BIAS_SRC)                                   \
    float acc[4][4][4];                                                         \
    _Pragma("unroll")                                                           \
    for (int a = 0; a < 4; ++a)                                                 \
        _Pragma("unroll")                                                       \
        for (int b2 = 0; b2 < 4; ++b2)                                          \
            _Pragma("unroll")                                                   \
            for (int c = 0; c < 4; ++c) acc[a][b2][c] = 0.f;                    \
    const __half* mats[2] = {AhP, BhP};                                         \
    auto load_stage = [&](int s, int k0) {                                      \
        const uint32_t st = smem_base + s * STAGE_B;                            \
        _Pragma("unroll")                                                       \
        for (int mat = 0; mat < 2; ++mat) {                                     \
            const __half* src = mats[mat];                                      \
            const int r0 = (mat < 1) ? m0 : n0;                                 \
            const uint32_t dstb = st + mat * MAT_B;                             \
            _Pragma("unroll")                                                   \
            for (int it = 0; it < 4; ++it) {                                    \
                const int idx = it * 256 + tid;                                 \
                const int row = idx >> 3;                                       \
                const int k8  = idx & 7;                                        \
                const void* sp = src + (size_t)(r0 + row) * GEMM_K + k0 + k8*8; \
                const uint32_t dp = dstb + row * (AS_STRIDE * 2) + k8 * 16;     \
                CP_ASYNC16(dp, sp);                                             \
            }                                                                   \
        }                                                                       \
    };                                                                          \
    if (tid < 32) CP_ASYNC16(smem_base + SM_BIAS + tid * 16, (BIAS_SRC) + tid * 4); \
    load_stage(0, 0);                                                           \
    CP_COMMIT();                                                                \
    load_stage(1, KC);                                                          \
    CP_COMMIT();                                                                \
    for (int c = 0; c < NCHUNK; ++c) {                                          \
        if (c + 1 < NCHUNK) { CP_WAIT(1); } else { CP_WAIT(0); }                \
        __syncthreads();                                                        \
        if (c + 2 < NCHUNK) {                                                   \
            load_stage((c + 2) % 3, (c + 2) * KC);                              \
            CP_COMMIT();                                                        \
        }                                                                       \
        const uint32_t stg = smem_base + (c % 3) * STAGE_B;                     \
        const uint32_t pA  = stg;                                               \
        const uint32_t pB  = stg + MAT_B;                                       \
        _Pragma("unroll")                                                       \
        for (int ks = 0; ks < 4; ++ks) {                                        \
            const int kcol = ks * 16;                                           \
            uint32_t bh[8];                                                     \
            _Pragma("unroll")                                                   \
            for (int p = 0; p < 2; ++p) {                                       \
                const int nrow = wn * 32 + p * 16 + (lane & 7) + ((lane>>4)<<3);\
                const int kk   = kcol + (((lane >> 3) & 1) << 3);               \
                const uint32_t off = (nrow * AS_STRIDE + kk) * 2;               \
                ldsm_x4(&bh[p * 4], pB + off);                                  \
            }                                                                   \
            _Pragma("unroll")                                                   \
            for (int mt = 0; mt < 4; ++mt) {                                    \
                const int mrow = wm * 64 + mt * 16 + (lane & 15);               \
                const int kk2  = kcol + ((lane >> 4) << 3);                     \
                const uint32_t offa = (mrow * AS_STRIDE + kk2) * 2;             \
                uint32_t afr[4];                                                \
                ldsm_x4(afr, pA + offa);                                        \
                _Pragma("unroll")                                               \
                for (int nt = 0; nt < 4; ++nt) mma_f16(acc[mt][nt], afr, &bh[nt*2]); \
            }                                                                   \
        }                                                                       \
    }

// ---------------------------------------------------------------------------
// Fused QKV projection: q -> single fp16 (pre-scaled by scl*log2e),
// k -> single fp16, v -> fp16 stored DIRECTLY TRANSPOSED into VT[B*KVW, SEQ].
// ---------------------------------------------------------------------------
#define ATT_SCL (0.08838834764831845f * 1.4426950408889634f)

__global__ void __launch_bounds__(256, 2)
gemm_qkv(const __half* __restrict__ Ah, const __half* __restrict__ Bh,
         const float* __restrict__ bq, const float* __restrict__ bk,
         const float* __restrict__ bv,
         __half* __restrict__ Qs, __half* __restrict__ Kh,
         __half* __restrict__ VT)
{
    extern __shared__ __align__(128) char smem[];
    const uint32_t smem_base = smem_to_u32(smem);
    const int tid  = threadIdx.x;
    const int warp = tid >> 5;
    const int lane = tid & 31;
    const int wm   = warp >> 2;
    const int wn   = warp & 3;
    const int m0   = blockIdx.y * 128;
    const int n0   = blockIdx.x * 128;

    const float* bsrc = (n0 < HID) ? (bq + n0)
                       : (n0 < HID + KVW) ? (bk + n0 - HID)
                       : (bv + n0 - HID - KVW);

    GEMM_MAINLOOP_F16(Ah, Bh, bsrc)

    const float* bias_s = (const float*)(smem + SM_BIAS);

    #pragma unroll
    for (int mt = 0; mt < 4; ++mt)
        #pragma unroll
        for (int rh = 0; rh < 2; ++rh) {
            const int row = m0 + wm * 64 + mt * 16 + (lane >> 2) + rh * 8;
            #pragma unroll
            for (int nt = 0; nt < 4; ++nt) {
                const int cl  = wn * 32 + nt * 8 + (lane & 3) * 2;  // 0..127
                const int col = n0 + cl;
                const float b0 = bias_s[cl], b1 = bias_s[cl + 1];
                if (n0 < HID) {
                    const float v0 = (acc[mt][nt][rh*2+0] + b0) * ATT_SCL;
                    const float v1 = (acc[mt][nt][rh*2+1] + b1) * ATT_SCL;
                    *(uint32_t*)&Qs[(size_t)row * HID + col] = packh2(v0, v1);
                } else if (n0 < HID + KVW) {
                    const int c2 = col - HID;
                    const float v0 = acc[mt][nt][rh*2+0] + b0;
                    const float v1 = acc[mt][nt][rh*2+1] + b1;
                    *(uint32_t*)&Kh[(size_t)row * KVW + c2] = packh2(v0, v1);
                } else {
                    const int c2 = col - HID - KVW;
                    const int bb = row >> 11;          // / SEQ
                    const int ss = row & (SEQ - 1);
                    const float v0 = acc[mt][nt][rh*2+0] + b0;
                    const float v1 = acc[mt][nt][rh*2+1] + b1;
                    VT[((size_t)bb * KVW + c2)     * SEQ + ss] = __float2half(v0);
                    VT[((size_t)bb * KVW + c2 + 1) * SEQ + ss] = __float2half(v1);
                }
            }
        }
}

// ---------------------------------------------------------------------------
// O-projection GEMM (fp16 single-pass, fp32 out)
// ---------------------------------------------------------------------------
__global__ void __launch_bounds__(256, 2)
gemm_o(const __half* __restrict__ Ah, const __half* __restrict__ Bh,
       const float* __restrict__ bias, float* __restrict__ C)
{
    extern __shared__ __align__(128) char smem[];
    const uint32_t smem_base = smem_to_u32(smem);
    const int tid  = threadIdx.x;
    const int warp = tid >> 5;
    const int lane = tid & 31;
    const int wm   = warp >> 2;
    const int wn   = warp & 3;
    const int m0   = blockIdx.y * 128;
    const int n0   = blockIdx.x * 128;

    GEMM_MAINLOOP_F16(Ah, Bh, bias + n0)

    const float* bias_s = (const float*)(smem + SM_BIAS);

    #pragma unroll
    for (int mt = 0; mt < 4; ++mt)
        #pragma unroll
        for (int rh = 0; rh < 2; ++rh) {
            const int row = m0 + wm * 64 + mt * 16 + (lane >> 2) + rh * 8;
            #pragma unroll
            for (int nt = 0; nt < 4; ++nt) {
                const int cl  = wn * 32 + nt * 8 + (lane & 3) * 2;
                const int col = n0 + cl;
                float2 v;
                v.x = acc[mt][nt][rh*2+0] + bias_s[cl];
                v.y = acc[mt][nt][rh*2+1] + bias_s[cl + 1];
                *(float2*)&C[(size_t)row * HID + col] = v;
            }
        }
}

// ---------------------------------------------------------------------------
// fp16 FlashAttention: 128 q-rows x 64 kv tiles, 8 warps.
// Single-pass QK, single-pass PV. K+V+mask double-buffered; ONE sync per tile.
// __launch_bounds__(256, 2): 2 CTAs/SM. Grid (NH, SEQ/128, BATCH), qb reversed
// on slow axis => LPT scheduling.
// ---------------------------------------------------------------------------
#define QSTR 136
#define VSTR 72
#define SM_Q   0
#define SM_ST  34816                 // stage base (K tile then V tile)
#define STG_B  35840                 // 17408 (K) + 18432 (V)
#define SM_MK  (SM_ST + 2 * STG_B)   // 106496
#define ATTN_SMEM (SM_MK + 512)      // 107008

__global__ void __launch_bounds__(256, 2)
attn_hmma(const __half* __restrict__ Qs, const __half* __restrict__ Kh,
          const __half* __restrict__ VTh, const int* __restrict__ mask,
          __half* __restrict__ OH)
{
    extern __shared__ __align__(128) char sm[];
    const uint32_t base = smem_to_u32(sm);
    const int tid = threadIdx.x;
    const int w    = tid >> 5;
    const int lane = tid & 31;
    const int h  = blockIdx.x;
    const int qb = (int)gridDim.y - 1 - (int)blockIdx.y;   // heavy-first (LPT)
    const int b  = blockIdx.z;
    const int q0 = qb * 128;
    const int kvh = h >> 2;
    const int T = 2 * qb + 2;

    auto load_kv = [&](int t) {
        const int k0 = t * 64;
        const int s  = t & 1;
        const uint32_t kdst = base + SM_ST + s * STG_B;
        #pragma unroll
        for (int i = 0; i < 4; ++i) {
            const int idx = i * 256 + tid;
            const int row = idx >> 4, c = idx & 15;
            CP_ASYNC16(kdst + row * 272 + c * 16,
                       Kh + (size_t)(b * SEQ + k0 + row) * KVW + kvh * DH + c * 8);
        }
        const uint32_t vdst = kdst + 17408;
        #pragma unroll
        for (int i = 0; i < 4; ++i) {
            const int idx = i * 256 + tid;
            const int row = idx >> 3, c = idx & 7;
            CP_ASYNC16(vdst + row * 144 + c * 16,
                       VTh + (size_t)(b * KVW + kvh * DH + row) * SEQ + k0 + c * 8);
        }
        if (tid < 64)
            CP_ASYNC4(base + SM_MK + s * 256 + tid * 4, mask + b * SEQ + k0 + tid);
    };

    // prologue: Q + KV(0)
    #pragma unroll
    for (int i = 0; i < 8; ++i) {
        const int idx = i * 256 + tid;
        const int row = idx >> 4, c = idx & 15;
        CP_ASYNC16(base + SM_Q + row * 272 + c * 16,
                   Qs + (size_t)(b * SEQ + q0 + row) * HID + h * DH + c * 8);
    }
    load_kv(0);
    CP_COMMIT();

    float s[8][4];
    float o[16][4];
    #pragma unroll
    for (int j = 0; j < 16; ++j)
        #pragma unroll
        for (int c = 0; c < 4; ++c) o[j][c] = 0.f;
    float m0 = -1e30f, m1 = -1e30f, l0 = 0.f, l1 = 0.f;

    const int r0g = q0 + w * 16 + (lane >> 2);
    const int r1g = r0g + 8;
    const int c0l = (lane & 3) * 2;

    for (int t = 0; t < T; ++t) {
        const int k0 = t * 64;
        const int st = t & 1;
        const bool active = (q0 + w * 16 + 15) >= k0;

        CP_WAIT(0);
        __syncthreads();
        if (t + 1 < T) {
            load_kv(t + 1);
            CP_COMMIT();
        }

        if (active) {
            const uint32_t pK = base + SM_ST + st * STG_B;
            const uint32_t pV = pK + 17408;
            const int* mk_s = (const int*)(sm + SM_MK + st * 256);

            #pragma unroll
            for (int j = 0; j < 8; ++j)
                #pragma unroll
                for (int c = 0; c < 4; ++c) s[j][c] = 0.f;

            // S = Q*K
            #pragma unroll
            for (int kc = 0; kc < 8; ++kc) {
                const uint32_t offa =
                    ((w * 16 + (lane & 15)) * QSTR + kc * 16 + ((lane >> 4) << 3)) * 2;
                uint32_t aq[4];
                ldsm_x4(aq, base + SM_Q + offa);
                #pragma unroll
                for (int g = 0; g < 4; ++g) {
                    const uint32_t offb =
                        ((g * 16 + (lane & 7) + ((lane >> 4) << 3)) * QSTR +
                         kc * 16 + (((lane >> 3) & 1) << 3)) * 2;
                    uint32_t bh[4];
                    ldsm_x4(bh, pK + offb);
                    mma_f16(s[2*g],   aq, &bh[0]);
                    mma_f16(s[2*g+1], aq, &bh[2]);
                }
            }

            // mask + online softmax (base-2 domain)
            float mx0 = -1e30f, mx1 = -1e30f;
            #pragma unroll
            for (int j = 0; j < 8; ++j) {
                const int cg = k0 + j * 8 + c0l;
                const int mk0 = mk_s[j * 8 + c0l];
                const int mk1 = mk_s[j * 8 + c0l + 1];
                s[j][0] = (cg     <= r0g && mk0) ? s[j][0] : -1e30f;
                s[j][1] = (cg + 1 <= r0g && mk1) ? s[j][1] : -1e30f;
                s[j][2] = (cg     <= r1g && mk0) ? s[j][2] : -1e30f;
                s[j][3] = (cg + 1 <= r1g && mk1) ? s[j][3] : -1e30f;
                mx0 = fmaxf(mx0, fmaxf(s[j][0], s[j][1]));
                mx1 = fmaxf(mx1, fmaxf(s[j][2], s[j][3]));
            }
            mx0 = fmaxf(mx0, __shfl_xor_sync(0xffffffff, mx0, 1));
            mx0 = fmaxf(mx0, __shfl_xor_sync(0xffffffff, mx0, 2));
            mx1 = fmaxf(mx1, __shfl_xor_sync(0xffffffff, mx1, 1));
            mx1 = fmaxf(mx1, __shfl_xor_sync(0xffffffff, mx1, 2));
            const float mn0 = fmaxf(m0, mx0), mn1 = fmaxf(m1, mx1);
            const float f0 = ex2(m0 - mn0), f1 = ex2(m1 - mn1);
            m0 = mn0; m1 = mn1;
            float sum0 = 0.f, sum1 = 0.f;
            #pragma unroll
            for (int j = 0; j < 8; ++j) {
                s[j][0] = ex2(s[j][0] - mn0);
                s[j][1] = ex2(s[j][1] - mn0);
                s[j][2] = ex2(s[j][2] - mn1);
                s[j][3] = ex2(s[j][3] - mn1);
                sum0 += s[j][0] + s[j][1];
                sum1 += s[j][2] + s[j][3];
            }
            sum0 += __shfl_xor_sync(0xffffffff, sum0, 1);
            sum0 += __shfl_xor_sync(0xffffffff, sum0, 2);
            sum1 += __shfl_xor_sync(0xffffffff, sum1, 1);
            sum1 += __shfl_xor_sync(0xffffffff, sum1, 2);
            l0 = l0 * f0 + sum0;
            l1 = l1 * f1 + sum1;
            #pragma unroll
            for (int j = 0; j < 16; ++j) {
                o[j][0] *= f0; o[j][1] *= f0;
                o[j][2] *= f1; o[j][3] *= f1;
            }

            // O += P*V
            #pragma unroll
            for (int kc = 0; kc < 4; ++kc) {
                uint32_t ap[4];
                ap[0] = packh2(s[2*kc][0],   s[2*kc][1]);
                ap[1] = packh2(s[2*kc][2],   s[2*kc][3]);
                ap[2] = packh2(s[2*kc+1][0], s[2*kc+1][1]);
                ap[3] = packh2(s[2*kc+1][2], s[2*kc+1][3]);
                #pragma unroll
                for (int g = 0; g < 8; ++g) {
                    const uint32_t offb =
                        ((g * 16 + (lane & 7) + ((lane >> 4) << 3)) * VSTR +
                         kc * 16 + (((lane >> 3) & 1) << 3)) * 2;
                    uint32_t bh[4];
                    ldsm_x4(bh, pV + offb);
                    mma_f16(o[2*g],   ap, &bh[0]);
                    mma_f16(o[2*g+1], ap, &bh[2]);
                }
            }
        }
    }

    // epilogue: normalize, store single fp16
    const float inv0 = 1.f / l0, inv1 = 1.f / l1;
    const size_t base0 = (size_t)(b * SEQ + r0g) * HID + h * DH;
    const size_t base1 = (size_t)(b * SEQ + r1g) * HID + h * DH;
    #pragma unroll
    for (int j = 0; j < 16; ++j) {
        const int col = j * 8 + c0l;
        *(uint32_t*)&OH[base0 + col] = packh2(o[j][0] * inv0, o[j][1] * inv0);
        *(uint32_t*)&OH[base1 + col] = packh2(o[j][2] * inv1, o[j][3] * inv1);
    }
}

// ---------------------------------------------------------------------------
// Launch
// ---------------------------------------------------------------------------
extern "C" void kernel_launch(void* const* d_in, const int* in_sizes, int n_in,
                              void* d_out, int out_size)
{
    const float* x    = (const float*)d_in[0];
    const int*   mask = (const int*)  d_in[1];
    const float* Wq   = (const float*)d_in[2];
    const float* bq   = (const float*)d_in[3];
    const float* Wk   = (const float*)d_in[4];
    const float* bk   = (const float*)d_in[5];
    const float* Wv   = (const float*)d_in[6];
    const float* bv   = (const float*)d_in[7];
    const float* Wo   = (const float*)d_in[8];
    const float* bo   = (const float*)d_in[9];
    float* out = (float*)d_out;

    void *pxh, *pqs, *pkh, *pvth, *pah, *pwh, *pwoh;
    cudaGetSymbolAddress(&pxh, g_xh);
    cudaGetSymbolAddress(&pqs, g_qs);
    cudaGetSymbolAddress(&pkh, g_kh);
    cudaGetSymbolAddress(&pvth, g_vth);
    cudaGetSymbolAddress(&pah, g_ah);
    cudaGetSymbolAddress(&pwh, g_wh);
    cudaGetSymbolAddress(&pwoh, g_woh);

    // --- single merged converter ---
    conv_kernel<<<WCONV_BLOCKS + XCONV_BLOCKS, 256>>>(
        x, Wq, Wk, Wv, Wo,
        (__half*)pxh, (__half*)pwh, (__half*)pwoh);

    // --- fused QKV projection (fp16 single-pass, KC=64, 3-stage, VT direct) ---
    cudaFuncSetAttribute(gemm_qkv, cudaFuncAttributeMaxDynamicSharedMemorySize,
                         GEMM_SMEM);
    cudaFuncSetAttribute(gemm_o, cudaFuncAttributeMaxDynamicSharedMemorySize,
                         GEMM_SMEM);
    gemm_qkv<<<dim3(NQKV / 128, MTOT / 128), 256, GEMM_SMEM>>>(
        (const __half*)pxh, (const __half*)pwh, bq, bk, bv,
        (__half*)pqs, (__half*)pkh, (__half*)pvth);

    // --- fp16 flash attention (2 CTAs/SM, LPT) ---
    cudaFuncSetAttribute(attn_hmma, cudaFuncAttributeMaxDynamicSharedMemorySize,
                         ATTN_SMEM);
    attn_hmma<<<dim3(NH, SEQ / 128, BATCH), 256, ATTN_SMEM>>>(
        (const __half*)pqs, (const __half*)pkh, (const __half*)pvth,
        mask, (__half*)pah);

    // --- output projection (fp16 single-pass, KC=64, 3-stage) ---
    gemm_o<<<dim3(HID / 128, MTOT / 128), 256, GEMM_SMEM>>>(
        (const __half*)pah, (const __half*)pwoh, bo, out);
}